// round 6
// baseline (speedup 1.0000x reference)
#include <cuda_runtime.h>
#include <math.h>
#include <stdint.h>

#define BDIM 4
#define SEQ 1024
#define DMODEL 1024
#define NH 16
#define DH 64
#define SPAN 256
#define TWOSPAN 512
#define NBATCH (BDIM*NH)   /* 64 */
#define NEGF (-3.402823466e38f)

// ---------------- scratch (device globals; no allocation allowed) ----------
__device__ float g_q   [(size_t)NBATCH * SEQ * DH];        // [z][s][d]
__device__ float g_k   [(size_t)NBATCH * SEQ * DH];        // [z][s][d]
__device__ float g_vt  [(size_t)NBATCH * DH * SEQ];        // [z][d][s]  (transposed V)
__device__ float g_posk[(size_t)NH * TWOSPAN * DH];        // [h][p][d]
__device__ float g_posq[(size_t)NH * TWOSPAN * DH];
__device__ float g_c2p [(size_t)NBATCH * SEQ * TWOSPAN];   // [z][q][p] (pre-scaled)
__device__ float g_p2c [(size_t)NBATCH * SEQ * TWOSPAN];   // [z][k][p] (pre-scaled)
__device__ float g_ctx [(size_t)BDIM * SEQ * DMODEL];
__device__ int   g_lut [2047];                              // clipped bucket idx per delta

// ================= small helpers ============================================
#define MMA_TF32(d, a, b) \
    asm volatile("mma.sync.aligned.m16n8k8.row.col.f32.tf32.tf32.f32 " \
        "{%0,%1,%2,%3}, {%4,%5,%6,%7}, {%8,%9}, {%0,%1,%2,%3};" \
        : "+f"((d)[0]), "+f"((d)[1]), "+f"((d)[2]), "+f"((d)[3]) \
        : "r"((a)[0]), "r"((a)[1]), "r"((a)[2]), "r"((a)[3]), \
          "r"((b)[0]), "r"((b)[1]))

__device__ __forceinline__ void cp16(uint32_t dst, const void* src) {
    asm volatile("cp.async.cg.shared.global [%0], [%1], 16;" :: "r"(dst), "l"(src));
}
#define CP_COMMIT() asm volatile("cp.async.commit_group;" ::: "memory")
#define CP_WAIT(n)  asm volatile("cp.async.wait_group %0;" :: "n"(n) : "memory")

// ================= rel-position bucket LUT ==================================
__device__ __forceinline__ int rel_bucket(int rel) {
    float abs_pos = (rel < 128 && rel > -128) ? 127.0f : fabsf((float)rel);
    if (abs_pos <= 128.0f) return rel;
    float sgn = (rel > 0) ? 1.0f : -1.0f;
    float log_pos = ceilf(logf(abs_pos * (1.0f/128.0f)) / logf(511.0f/128.0f) * 127.0f) + 128.0f;
    return (int)(log_pos * sgn);
}
__global__ void lut_k() {
    int t = blockIdx.x * blockDim.x + threadIdx.x;
    if (t >= 2047) return;
    int b = rel_bucket(t - 1023);
    g_lut[t] = min(max(b + SPAN, 0), TWOSPAN - 1);
}

// ================= unified tf32 mma.sync GEMM (C = A @ B^T + epilogues) =====
#define EPI_HEADS   0
#define EPI_HEADS_T 1
#define EPI_POS     2
#define EPI_SCALE   3
#define EPI_OUT     6

template<int EPI, int BN, int CH>
__global__ void __launch_bounds__(256, 2)
tc_gemm(const float* __restrict__ A, const float* __restrict__ Bm,
        const float* __restrict__ bias, const float* __restrict__ ex1,
        float* __restrict__ C,
        int Ka, size_t sA, size_t sB, int nbMod, float alpha)
{
    constexpr int NS    = 3;
    constexpr int WN    = BN / 4;
    constexpr int NF    = WN / 8;
    constexpr int BNW   = BN / 32;
    constexpr int AELEM = 128 * 32;
    constexpr int BELEM = BN * 32;

    extern __shared__ uint32_t smem_u[];
    const uint32_t smemU = (uint32_t)__cvta_generic_to_shared(smem_u);

    const int tid  = threadIdx.x;
    const int lane = tid & 31, wid = tid >> 5;
    const int wr = wid & 1, wc = wid >> 1;
    const int rq = lane >> 2, cc = lane & 3;
    const int z  = blockIdx.z;
    const int m0 = blockIdx.y * 128;
    const int n0 = blockIdx.x * BN;

    A  += (size_t)z * sA + (size_t)m0 * Ka;
    Bm += (size_t)(nbMod ? (z % nbMod) : 0) * sB + (size_t)n0 * Ka;

    float acc[4][NF][4];
    #pragma unroll
    for (int a = 0; a < 4; a++)
        #pragma unroll
        for (int b = 0; b < NF; b++)
            #pragma unroll
            for (int c = 0; c < 4; c++) acc[a][b][c] = 0.0f;

    int aBase[4][2];
    #pragma unroll
    for (int mi = 0; mi < 4; mi++) {
        int r = wr * 64 + mi * 16 + rq;
        aBase[mi][0] = r * 32 + cc;
        aBase[mi][1] = (r + 8) * 32 + cc;
    }
    int bBase[NF];
    #pragma unroll
    for (int ni = 0; ni < NF; ni++)
        bBase[ni] = (wc * WN + ni * 8 + rq) * 32 + cc;

    const int crow = tid >> 3;
    const int ckg  = tid & 7;

    auto issue = [&](int chunk) {
        const int s  = chunk % NS;
        const int k0 = chunk * 32;
        #pragma unroll
        for (int j = 0; j < 4; j++) {
            int row = j * 32 + crow;
            uint32_t dst = smemU + (uint32_t)(s * AELEM + row * 32 + ((ckg ^ (row & 7)) << 2)) * 4u;
            cp16(dst, A + (size_t)row * Ka + k0 + ckg * 4);
        }
        #pragma unroll
        for (int j = 0; j < BNW; j++) {
            int row = j * 32 + crow;
            uint32_t dst = smemU + (uint32_t)(NS * AELEM + s * BELEM + row * 32 + ((ckg ^ (row & 7)) << 2)) * 4u;
            cp16(dst, Bm + (size_t)row * Ka + k0 + ckg * 4);
        }
    };

    #pragma unroll
    for (int c = 0; c < NS - 1; c++) {
        if (c < CH) issue(c);
        CP_COMMIT();
    }

    #pragma unroll 1
    for (int i = 0; i < CH; i++) {
        CP_WAIT(NS - 2);
        __syncthreads();
        if (i + NS - 1 < CH) issue(i + NS - 1);
        CP_COMMIT();

        const uint32_t* as = smem_u + (i % NS) * AELEM;
        const uint32_t* bs = smem_u + NS * AELEM + (i % NS) * BELEM;
        #pragma unroll
        for (int ks = 0; ks < 4; ks++) {
            const int o0 = ((2 * ks) ^ rq) << 2;
            const int o1 = ((2 * ks + 1) ^ rq) << 2;
            uint32_t af[4][4];
            #pragma unroll
            for (int mi = 0; mi < 4; mi++) {
                af[mi][0] = as[aBase[mi][0] + o0];
                af[mi][1] = as[aBase[mi][1] + o0];
                af[mi][2] = as[aBase[mi][0] + o1];
                af[mi][3] = as[aBase[mi][1] + o1];
            }
            uint32_t bf[NF][2];
            #pragma unroll
            for (int ni = 0; ni < NF; ni++) {
                bf[ni][0] = bs[bBase[ni] + o0];
                bf[ni][1] = bs[bBase[ni] + o1];
            }
            #pragma unroll
            for (int mi = 0; mi < 4; mi++)
                #pragma unroll
                for (int ni = 0; ni < NF; ni++)
                    MMA_TF32(acc[mi][ni], af[mi], bf[ni]);
        }
    }
    CP_WAIT(0);
    __syncthreads();

    // ---------------- epilogue: frags -> smem stage -> global ----------------
    float* stage = (float*)smem_u;

    #pragma unroll 1
    for (int cb = 0; cb < BN / 32; cb++) {
        const int n0c = n0 + cb * 32;
        #pragma unroll
        for (int mi = 0; mi < 4; mi++)
            #pragma unroll
            for (int ni = 0; ni < NF; ni++) {
                int gc = wc * WN + ni * 8 + 2 * cc;
                if ((gc >> 5) == cb) {
                    int sc2 = gc & 31;
                    int r0 = wr * 64 + mi * 16 + rq;
                    stage[r0 * 33 + sc2]           = acc[mi][ni][0];
                    stage[r0 * 33 + sc2 + 1]       = acc[mi][ni][1];
                    stage[(r0 + 8) * 33 + sc2]     = acc[mi][ni][2];
                    stage[(r0 + 8) * 33 + sc2 + 1] = acc[mi][ni][3];
                }
            }
        __syncthreads();

        if (EPI == EPI_HEADS_T) {
            #pragma unroll 1
            for (int j = 0; j < 16; j++) {
                int e = j * 256 + tid;
                int row = e & 127, c = e >> 7;
                int m = m0 + row, n = n0c + c;
                float val = stage[row * 33 + c] + bias[n];
                int b = m >> 10, sq = m & 1023;
                int zz = b * NH + (n >> 6), dd = n & 63;
                C[((size_t)zz * DH + dd) * SEQ + sq] = val;
            }
        } else {
            #pragma unroll 1
            for (int j = 0; j < 16; j++) {
                int e = j * 256 + tid;
                int row = e >> 5, c = e & 31;
                int m = m0 + row, n = n0c + c;
                float val = stage[row * 33 + c];
                if (EPI == EPI_HEADS) {
                    val += bias[n];
                    int b = m >> 10, sq = m & 1023, h = n >> 6, dd = n & 63;
                    C[(((size_t)(b * NH + h)) * SEQ + sq) * DH + dd] = val;
                } else if (EPI == EPI_POS) {
                    val += bias[n];
                    int h = n >> 6, dd = n & 63;
                    C[((size_t)h * TWOSPAN + m) * DH + dd] = val;
                } else if (EPI == EPI_SCALE) {
                    C[(size_t)z * SEQ * TWOSPAN + (size_t)m * TWOSPAN + n] = val * alpha;
                } else { // EPI_OUT
                    val += bias[n] + ex1[(size_t)m * DMODEL + n];
                    C[(size_t)m * DMODEL + n] = val;
                }
            }
        }
        __syncthreads();
    }
}

// ================= flash attention: scores+softmax+PV fused =================
// grid (8 q-tiles, 64 z), 256 threads = 8 warps; warp w owns q rows 16w..16w+15.
// smem (floats): Q 8192 | K 2x4096 | V 2x4096 | lut 2047 ints  => 104KB, 2 CTA/SM
__global__ void __launch_bounds__(256, 2)
flash_k(const float* __restrict__ Qg, const float* __restrict__ Kg,
        const float* __restrict__ Vg, const float* __restrict__ c2p,
        const float* __restrict__ p2c, const int* __restrict__ mask,
        float* __restrict__ ctx, float alpha)
{
    constexpr int QS = 0, KS = 8192, VS = 16384;
    extern __shared__ float fsm[];
    int* lut_s = (int*)&fsm[24576];
    const uint32_t smemU = (uint32_t)__cvta_generic_to_shared(fsm);

    const int tid = threadIdx.x, lane = tid & 31, w = tid >> 5;
    const int rq = lane >> 2, cc = lane & 3;
    const int z = blockIdx.y, m0 = blockIdx.x * 128;
    const int b = z >> 4;

    const float* Qz = Qg + (size_t)z * SEQ * DH;
    const float* Kz = Kg + (size_t)z * SEQ * DH;
    const float* Vz = Vg + (size_t)z * DH * SEQ;
    const float* c2pz = c2p + (size_t)z * SEQ * TWOSPAN;
    const float* p2cz = p2c + (size_t)z * SEQ * TWOSPAN;
    const int* mz = mask + (size_t)b * SEQ * SEQ;

    for (int t = tid; t < 2047; t += 256) lut_s[t] = g_lut[t];

    // Q tile: 128 x 64, split in 2 panels of 32 cols, xor-swizzled
    #pragma unroll
    for (int it = 0; it < 8; it++) {
        int idx = it * 256 + tid;
        int row = idx >> 4, kg = idx & 15;
        int panel = kg >> 3, kg8 = kg & 7;
        uint32_t dst = smemU + (uint32_t)(QS + panel * 4096 + row * 32 + ((kg8 ^ (row & 7)) << 2)) * 4u;
        cp16(dst, Qz + (size_t)(m0 + row) * DH + kg * 4);
    }
    auto issueKV = [&](int t) {
        int s = t & 1, n0 = t * 64;
        #pragma unroll
        for (int it = 0; it < 4; it++) {
            int idx = it * 256 + tid;
            int row = idx >> 4, kg = idx & 15;
            int panel = kg >> 3, kg8 = kg & 7;
            uint32_t sw = (uint32_t)(((kg8 ^ (row & 7)) << 2) + row * 32 + panel * 2048);
            cp16(smemU + (uint32_t)(KS + s * 4096 + sw) * 4u, Kz + (size_t)(n0 + row) * DH + kg * 4);
            cp16(smemU + (uint32_t)(VS + s * 4096 + sw) * 4u, Vz + (size_t)row * SEQ + n0 + kg * 4);
        }
    };
    issueKV(0);
    CP_COMMIT();

    float oacc[8][4];
    #pragma unroll
    for (int f = 0; f < 8; f++)
        #pragma unroll
        for (int e = 0; e < 4; e++) oacc[f][e] = 0.0f;
    float mrow[2] = {NEGF, NEGF};
    float lrow[2] = {0.0f, 0.0f};

    const int iA = m0 + 16 * w + rq, iB = iA + 8;
    const float* c2pA = c2pz + (size_t)iA * TWOSPAN;
    const float* c2pB = c2pz + (size_t)iB * TWOSPAN;
    const int* mA = mz + (size_t)iA * SEQ;
    const int* mB = mz + (size_t)iB * SEQ;
    const int srcL = (lane & ~3) | (cc >> 1);
    const bool odd = cc & 1;

    #pragma unroll 1
    for (int t = 0; t < 16; t++) {
        const int s = t & 1, n0 = t * 64;
        CP_WAIT(0);
        __syncthreads();
        if (t + 1 < 16) issueKV(t + 1);
        CP_COMMIT();

        // ---- S = Q @ K^T ----
        float sacc[8][4];
        #pragma unroll
        for (int f = 0; f < 8; f++)
            #pragma unroll
            for (int e = 0; e < 4; e++) sacc[f][e] = 0.0f;
        #pragma unroll
        for (int ks = 0; ks < 8; ks++) {
            int panel = ks >> 2, kk = ks & 3;
            int o0 = ((2 * kk) ^ rq) << 2, o1 = ((2 * kk + 1) ^ rq) << 2;
            const float* qp = fsm + QS + panel * 4096;
            const float* kp = fsm + KS + s * 4096 + panel * 2048;
            uint32_t af[4];
            af[0] = __float_as_uint(qp[(16 * w + rq) * 32 + cc + o0]);
            af[1] = __float_as_uint(qp[(16 * w + rq + 8) * 32 + cc + o0]);
            af[2] = __float_as_uint(qp[(16 * w + rq) * 32 + cc + o1]);
            af[3] = __float_as_uint(qp[(16 * w + rq + 8) * 32 + cc + o1]);
            #pragma unroll
            for (int f = 0; f < 8; f++) {
                uint32_t bf[2];
                bf[0] = __float_as_uint(kp[(8 * f + rq) * 32 + cc + o0]);
                bf[1] = __float_as_uint(kp[(8 * f + rq) * 32 + cc + o1]);
                MMA_TF32(sacc[f], af, bf);
            }
        }

        // ---- scale + c2p + p2c + mask, row max ----
        float mx0 = NEGF, mx1 = NEGF;
        #pragma unroll
        for (int f = 0; f < 8; f++) {
            int j0 = n0 + 8 * f + 2 * cc;
            int2 mm0 = *(const int2*)&mA[j0];
            int2 mm1 = *(const int2*)&mB[j0];
            float v0 = mm0.x ? sacc[f][0] * alpha + c2pA[lut_s[iA - j0 + 1023]]
                               + p2cz[(size_t)j0 * TWOSPAN + lut_s[j0 - iA + 1023]] : NEGF;
            float v1 = mm0.y ? sacc[f][1] * alpha + c2pA[lut_s[iA - j0 + 1022]]
                               + p2cz[(size_t)(j0 + 1) * TWOSPAN + lut_s[j0 + 1 - iA + 1023]] : NEGF;
            float v2 = mm1.x ? sacc[f][2] * alpha + c2pB[lut_s[iB - j0 + 1023]]
                               + p2cz[(size_t)j0 * TWOSPAN + lut_s[j0 - iB + 1023]] : NEGF;
            float v3 = mm1.y ? sacc[f][3] * alpha + c2pB[lut_s[iB - j0 + 1022]]
                               + p2cz[(size_t)(j0 + 1) * TWOSPAN + lut_s[j0 + 1 - iB + 1023]] : NEGF;
            sacc[f][0] = v0; sacc[f][1] = v1; sacc[f][2] = v2; sacc[f][3] = v3;
            mx0 = fmaxf(mx0, fmaxf(v0, v1));
            mx1 = fmaxf(mx1, fmaxf(v2, v3));
        }
        mx0 = fmaxf(mx0, __shfl_xor_sync(0xffffffffu, mx0, 1));
        mx0 = fmaxf(mx0, __shfl_xor_sync(0xffffffffu, mx0, 2));
        mx1 = fmaxf(mx1, __shfl_xor_sync(0xffffffffu, mx1, 1));
        mx1 = fmaxf(mx1, __shfl_xor_sync(0xffffffffu, mx1, 2));
        float mn0 = fmaxf(mrow[0], mx0), mn1 = fmaxf(mrow[1], mx1);
        float sc0 = __expf(mrow[0] - mn0), sc1 = __expf(mrow[1] - mn1);
        mrow[0] = mn0; mrow[1] = mn1;
        #pragma unroll
        for (int f = 0; f < 8; f++) {
            oacc[f][0] *= sc0; oacc[f][1] *= sc0;
            oacc[f][2] *= sc1; oacc[f][3] *= sc1;
        }
        lrow[0] *= sc0; lrow[1] *= sc1;

        // ---- per k-block: exp, fragment transpose via shuffles, PV MMA ----
        float rs0 = 0.0f, rs1 = 0.0f;
        #pragma unroll
        for (int f = 0; f < 8; f++) {
            float e0 = __expf(sacc[f][0] - mn0);
            float e1 = __expf(sacc[f][1] - mn0);
            float e2 = __expf(sacc[f][2] - mn1);
            float e3 = __expf(sacc[f][3] - mn1);
            rs0 += e0 + e1; rs1 += e2 + e3;
            // masked entries must contribute 0 to PV (and re-zero, per reference)
            float p0 = (sacc[f][0] == NEGF) ? 0.0f : e0;
            float p1 = (sacc[f][1] == NEGF) ? 0.0f : e1;
            float p2 = (sacc[f][2] == NEGF) ? 0.0f : e2;
            float p3 = (sacc[f][3] == NEGF) ? 0.0f : e3;
            // acc-layout (rq, 2cc/2cc+1) -> A-operand layout (rq, cc & cc+4)
            float ev0 = __shfl_sync(0xffffffffu, p0, srcL);
            float od0 = __shfl_sync(0xffffffffu, p1, srcL);
            float ev4 = __shfl_sync(0xffffffffu, p0, srcL + 2);
            float od4 = __shfl_sync(0xffffffffu, p1, srcL + 2);
            float ev1 = __shfl_sync(0xffffffffu, p2, srcL);
            float od1 = __shfl_sync(0xffffffffu, p3, srcL);
            float ev5 = __shfl_sync(0xffffffffu, p2, srcL + 2);
            float od5 = __shfl_sync(0xffffffffu, p3, srcL + 2);
            uint32_t pf[4];
            pf[0] = __float_as_uint(odd ? od0 : ev0);
            pf[1] = __float_as_uint(odd ? od1 : ev1);
            pf[2] = __float_as_uint(odd ? od4 : ev4);
            pf[3] = __float_as_uint(odd ? od5 : ev5);
            int panel = f >> 2, kk = f & 3;
            int o0 = ((2 * kk) ^ rq) << 2, o1 = ((2 * kk + 1) ^ rq) << 2;
            const float* vp = fsm + VS + s * 4096 + panel * 2048;
            #pragma unroll
            for (int n = 0; n < 8; n++) {
                uint32_t bf[2];
                bf[0] = __float_as_uint(vp[(8 * n + rq) * 32 + cc + o0]);
                bf[1] = __float_as_uint(vp[(8 * n + rq) * 32 + cc + o1]);
                MMA_TF32(oacc[n], pf, bf);
            }
        }
        rs0 += __shfl_xor_sync(0xffffffffu, rs0, 1);
        rs0 += __shfl_xor_sync(0xffffffffu, rs0, 2);
        rs1 += __shfl_xor_sync(0xffffffffu, rs1, 1);
        rs1 += __shfl_xor_sync(0xffffffffu, rs1, 2);
        lrow[0] += rs0;
        lrow[1] += rs1;
    }

    // ---- write ctx: [b][s][h*64+d] ----
    float inv0 = 1.0f / lrow[0], inv1 = 1.0f / lrow[1];
    int h = z & 15;
    float* crow0 = ctx + ((size_t)b * SEQ + (size_t)(m0 + 16 * w + rq)) * DMODEL + h * DH;
    float* crow1 = crow0 + (size_t)8 * DMODEL;
    #pragma unroll
    for (int f = 0; f < 8; f++) {
        int d0 = 8 * f + 2 * cc;
        float2 a = make_float2(oacc[f][0] * inv0, oacc[f][1] * inv0);
        float2 c = make_float2(oacc[f][2] * inv1, oacc[f][3] * inv1);
        *(float2*)&crow0[d0] = a;
        *(float2*)&crow1[d0] = c;
    }
}

// ================= layernorm ================================================
__device__ __forceinline__ float block_sum(float v, float* sh) {
    #pragma unroll
    for (int o = 16; o; o >>= 1) v += __shfl_xor_sync(0xffffffffu, v, o);
    int lane = threadIdx.x & 31, w = threadIdx.x >> 5;
    __syncthreads();
    if (lane == 0) sh[w] = v;
    __syncthreads();
    if (w == 0) {
        float x = (lane < (blockDim.x >> 5)) ? sh[lane] : 0.0f;
        #pragma unroll
        for (int o = 16; o; o >>= 1) x += __shfl_xor_sync(0xffffffffu, x, o);
        if (lane == 0) sh[0] = x;
    }
    __syncthreads();
    return sh[0];
}
__global__ void ln_k(float* __restrict__ out, const float* __restrict__ gamma,
                     const float* __restrict__ beta) {
    __shared__ float sh[32];
    int row = blockIdx.x, t = threadIdx.x;
    float* p = out + (size_t)row * DMODEL;
    float4 v = *(const float4*)(p + t * 4);
    float mean = block_sum(v.x + v.y + v.z + v.w, sh) * (1.0f / DMODEL);
    float dx = v.x - mean, dy = v.y - mean, dz = v.z - mean, dw = v.w - mean;
    float var = block_sum(dx*dx + dy*dy + dz*dz + dw*dw, sh) * (1.0f / DMODEL);
    float inv = rsqrtf(var + 1e-7f);
    float4 g = *(const float4*)(gamma + t * 4);
    float4 bb = *(const float4*)(beta + t * 4);
    float4 o;
    o.x = dx*inv*g.x + bb.x; o.y = dy*inv*g.y + bb.y;
    o.z = dz*inv*g.z + bb.z; o.w = dw*inv*g.w + bb.w;
    *(float4*)(p + t * 4) = o;
}

// ================= launch ====================================================
extern "C" void kernel_launch(void* const* d_in, const int* in_sizes, int n_in,
                              void* d_out, int out_size) {
    const float* hidden = (const float*)d_in[0];
    const int*   mask   = (const int*)  d_in[1];
    const float* rel    = (const float*)d_in[2];
    const float* Wq     = (const float*)d_in[3];
    const float* bq     = (const float*)d_in[4];
    const float* Wk     = (const float*)d_in[5];
    const float* bk     = (const float*)d_in[6];
    const float* Wv     = (const float*)d_in[7];
    const float* bv     = (const float*)d_in[8];
    const float* Wo     = (const float*)d_in[9];
    const float* bo     = (const float*)d_in[10];
    const float* gamma  = (const float*)d_in[11];
    const float* beta   = (const float*)d_in[12];
    float* out = (float*)d_out;

    float *q, *k, *vt, *pk, *pq, *c2p, *p2c, *ctx;
    cudaGetSymbolAddress((void**)&q,   g_q);
    cudaGetSymbolAddress((void**)&k,   g_k);
    cudaGetSymbolAddress((void**)&vt,  g_vt);
    cudaGetSymbolAddress((void**)&pk,  g_posk);
    cudaGetSymbolAddress((void**)&pq,  g_posq);
    cudaGetSymbolAddress((void**)&c2p, g_c2p);
    cudaGetSymbolAddress((void**)&p2c, g_p2c);
    cudaGetSymbolAddress((void**)&ctx, g_ctx);

    const float alpha = 1.0f / sqrtf((float)(DH * 3));
    const size_t SM128 = (size_t)3 * (128 * 32 + 128 * 32) * 4;   // 98304
    const size_t SMF   = (size_t)24576 * 4 + 2048 * 4;            // 106496 (104KB)

    cudaFuncSetAttribute((const void*)tc_gemm<EPI_HEADS,  128, 32>, cudaFuncAttributeMaxDynamicSharedMemorySize, (int)SM128);
    cudaFuncSetAttribute((const void*)tc_gemm<EPI_HEADS_T,128, 32>, cudaFuncAttributeMaxDynamicSharedMemorySize, (int)SM128);
    cudaFuncSetAttribute((const void*)tc_gemm<EPI_POS,    128, 32>, cudaFuncAttributeMaxDynamicSharedMemorySize, (int)SM128);
    cudaFuncSetAttribute((const void*)tc_gemm<EPI_SCALE,  128,  2>, cudaFuncAttributeMaxDynamicSharedMemorySize, (int)SM128);
    cudaFuncSetAttribute((const void*)tc_gemm<EPI_OUT,    128, 32>, cudaFuncAttributeMaxDynamicSharedMemorySize, (int)SM128);
    cudaFuncSetAttribute((const void*)flash_k, cudaFuncAttributeMaxDynamicSharedMemorySize, (int)SMF);

    lut_k<<<2, 1024>>>();

    // Q, K, V projections (M=4096, N=1024, K=1024)
    tc_gemm<EPI_HEADS,  128, 32><<<dim3(8, 32, 1), 256, SM128>>>(hidden, Wq, bq, 0, q,  1024, 0, 0, 0, 1.f);
    tc_gemm<EPI_HEADS,  128, 32><<<dim3(8, 32, 1), 256, SM128>>>(hidden, Wk, bk, 0, k,  1024, 0, 0, 0, 1.f);
    tc_gemm<EPI_HEADS_T,128, 32><<<dim3(8, 32, 1), 256, SM128>>>(hidden, Wv, bv, 0, vt, 1024, 0, 0, 0, 1.f);
    // position projections (M=512)
    tc_gemm<EPI_POS, 128, 32><<<dim3(8, 4, 1), 256, SM128>>>(rel, Wk, bk, 0, pk, 1024, 0, 0, 0, 1.f);
    tc_gemm<EPI_POS, 128, 32><<<dim3(8, 4, 1), 256, SM128>>>(rel, Wq, bq, 0, pq, 1024, 0, 0, 0, 1.f);
    // c2p / p2c attention tables (pre-scaled by alpha), per-z batched, K=64
    tc_gemm<EPI_SCALE, 128, 2><<<dim3(4, 8, NBATCH), 256, SM128>>>(q, pk, 0, 0, c2p, 64, (size_t)SEQ*DH, (size_t)TWOSPAN*DH, NH, alpha);
    tc_gemm<EPI_SCALE, 128, 2><<<dim3(4, 8, NBATCH), 256, SM128>>>(k, pq, 0, 0, p2c, 64, (size_t)SEQ*DH, (size_t)TWOSPAN*DH, NH, alpha);

    // fused attention: scores + masked softmax + P@V
    flash_k<<<dim3(8, NBATCH), 256, SMF>>>(q, k, vt, c2p, p2c, mask, ctx, alpha);

    // output projection + residual
    tc_gemm<EPI_OUT, 128, 32><<<dim3(8, 32, 1), 256, SM128>>>(ctx, Wo, bo, hidden, out, 1024, 0, 0, 0, 1.f);

    ln_k<<<BDIM * SEQ, 256>>>(out, gamma, beta);
}

// round 7
// speedup vs baseline: 1.0837x; 1.0837x over previous
#include <cuda_runtime.h>
#include <math.h>
#include <stdint.h>

#define BDIM 4
#define SEQ 1024
#define DMODEL 1024
#define NH 16
#define DH 64
#define SPAN 256
#define TWOSPAN 512
#define NBATCH (BDIM*NH)   /* 64 */
#define NEGF (-3.402823466e38f)

// ---------------- scratch (device globals; no allocation allowed) ----------
__device__ float g_q   [(size_t)NBATCH * SEQ * DH];        // [z][s][d]
__device__ float g_k   [(size_t)NBATCH * SEQ * DH];        // [z][s][d]
__device__ float g_vt  [(size_t)NBATCH * DH * SEQ];        // [z][d][s]  (transposed V)
__device__ float g_posk[(size_t)NH * TWOSPAN * DH];        // [h][p][d]
__device__ float g_posq[(size_t)NH * TWOSPAN * DH];
__device__ float g_c2p [(size_t)NBATCH * SEQ * TWOSPAN];   // [z][q][p]   (pre-scaled)
__device__ float g_p2cT[(size_t)NBATCH * TWOSPAN * SEQ];   // [z][p][k]   (TRANSPOSED, pre-scaled)
__device__ float g_ctx [(size_t)BDIM * SEQ * DMODEL];
__device__ int   g_lut [2047];                              // clipped bucket idx per delta

// ================= small helpers ============================================
#define MMA_TF32(d, a, b) \
    asm volatile("mma.sync.aligned.m16n8k8.row.col.f32.tf32.tf32.f32 " \
        "{%0,%1,%2,%3}, {%4,%5,%6,%7}, {%8,%9}, {%0,%1,%2,%3};" \
        : "+f"((d)[0]), "+f"((d)[1]), "+f"((d)[2]), "+f"((d)[3]) \
        : "r"((a)[0]), "r"((a)[1]), "r"((a)[2]), "r"((a)[3]), \
          "r"((b)[0]), "r"((b)[1]))

__device__ __forceinline__ void cp16(uint32_t dst, const void* src) {
    asm volatile("cp.async.cg.shared.global [%0], [%1], 16;" :: "r"(dst), "l"(src));
}
#define CP_COMMIT() asm volatile("cp.async.commit_group;" ::: "memory")
#define CP_WAIT(n)  asm volatile("cp.async.wait_group %0;" :: "n"(n) : "memory")

// ================= rel-position bucket LUT ==================================
__device__ __forceinline__ int rel_bucket(int rel) {
    float abs_pos = (rel < 128 && rel > -128) ? 127.0f : fabsf((float)rel);
    if (abs_pos <= 128.0f) return rel;
    float sgn = (rel > 0) ? 1.0f : -1.0f;
    float log_pos = ceilf(logf(abs_pos * (1.0f/128.0f)) / logf(511.0f/128.0f) * 127.0f) + 128.0f;
    return (int)(log_pos * sgn);
}
__global__ void lut_k() {
    int t = blockIdx.x * blockDim.x + threadIdx.x;
    if (t >= 2047) return;
    int b = rel_bucket(t - 1023);
    g_lut[t] = min(max(b + SPAN, 0), TWOSPAN - 1);
}

// ================= unified tf32 mma.sync GEMM (C = A @ B^T + epilogues) =====
#define EPI_HEADS   0
#define EPI_HEADS_T 1
#define EPI_POS     2
#define EPI_SCALE   3
#define EPI_OUT     6

template<int EPI, int BN, int CH>
__global__ void __launch_bounds__(256, 2)
tc_gemm(const float* __restrict__ A, const float* __restrict__ Bm,
        const float* __restrict__ bias, const float* __restrict__ ex1,
        float* __restrict__ C,
        int Ka, size_t sA, size_t sB, int nbModA, int nbModB,
        size_t sC, int ldC, float alpha)
{
    constexpr int NS    = 3;
    constexpr int WN    = BN / 4;
    constexpr int NF    = WN / 8;
    constexpr int BNW   = BN / 32;
    constexpr int AELEM = 128 * 32;
    constexpr int BELEM = BN * 32;

    extern __shared__ uint32_t smem_u[];
    const uint32_t smemU = (uint32_t)__cvta_generic_to_shared(smem_u);

    const int tid  = threadIdx.x;
    const int lane = tid & 31, wid = tid >> 5;
    const int wr = wid & 1, wc = wid >> 1;
    const int rq = lane >> 2, cc = lane & 3;
    const int z  = blockIdx.z;
    const int m0 = blockIdx.y * 128;
    const int n0 = blockIdx.x * BN;

    A  += (size_t)(nbModA ? (z % nbModA) : z) * sA + (size_t)m0 * Ka;
    Bm += (size_t)(nbModB ? (z % nbModB) : z) * sB + (size_t)n0 * Ka;

    float acc[4][NF][4];
    #pragma unroll
    for (int a = 0; a < 4; a++)
        #pragma unroll
        for (int b = 0; b < NF; b++)
            #pragma unroll
            for (int c = 0; c < 4; c++) acc[a][b][c] = 0.0f;

    int aBase[4][2];
    #pragma unroll
    for (int mi = 0; mi < 4; mi++) {
        int r = wr * 64 + mi * 16 + rq;
        aBase[mi][0] = r * 32 + cc;
        aBase[mi][1] = (r + 8) * 32 + cc;
    }
    int bBase[NF];
    #pragma unroll
    for (int ni = 0; ni < NF; ni++)
        bBase[ni] = (wc * WN + ni * 8 + rq) * 32 + cc;

    const int crow = tid >> 3;
    const int ckg  = tid & 7;

    auto issue = [&](int chunk) {
        const int s  = chunk % NS;
        const int k0 = chunk * 32;
        #pragma unroll
        for (int j = 0; j < 4; j++) {
            int row = j * 32 + crow;
            uint32_t dst = smemU + (uint32_t)(s * AELEM + row * 32 + ((ckg ^ (row & 7)) << 2)) * 4u;
            cp16(dst, A + (size_t)row * Ka + k0 + ckg * 4);
        }
        #pragma unroll
        for (int j = 0; j < BNW; j++) {
            int row = j * 32 + crow;
            uint32_t dst = smemU + (uint32_t)(NS * AELEM + s * BELEM + row * 32 + ((ckg ^ (row & 7)) << 2)) * 4u;
            cp16(dst, Bm + (size_t)row * Ka + k0 + ckg * 4);
        }
    };

    #pragma unroll
    for (int c = 0; c < NS - 1; c++) {
        if (c < CH) issue(c);
        CP_COMMIT();
    }

    #pragma unroll 1
    for (int i = 0; i < CH; i++) {
        CP_WAIT(NS - 2);
        __syncthreads();
        if (i + NS - 1 < CH) issue(i + NS - 1);
        CP_COMMIT();

        const uint32_t* as = smem_u + (i % NS) * AELEM;
        const uint32_t* bs = smem_u + NS * AELEM + (i % NS) * BELEM;
        #pragma unroll
        for (int ks = 0; ks < 4; ks++) {
            const int o0 = ((2 * ks) ^ rq) << 2;
            const int o1 = ((2 * ks + 1) ^ rq) << 2;
            uint32_t af[4][4];
            #pragma unroll
            for (int mi = 0; mi < 4; mi++) {
                af[mi][0] = as[aBase[mi][0] + o0];
                af[mi][1] = as[aBase[mi][1] + o0];
                af[mi][2] = as[aBase[mi][0] + o1];
                af[mi][3] = as[aBase[mi][1] + o1];
            }
            uint32_t bf[NF][2];
            #pragma unroll
            for (int ni = 0; ni < NF; ni++) {
                bf[ni][0] = bs[bBase[ni] + o0];
                bf[ni][1] = bs[bBase[ni] + o1];
            }
            #pragma unroll
            for (int mi = 0; mi < 4; mi++)
                #pragma unroll
                for (int ni = 0; ni < NF; ni++)
                    MMA_TF32(acc[mi][ni], af[mi], bf[ni]);
        }
    }
    CP_WAIT(0);
    __syncthreads();

    // ---------------- epilogue: frags -> smem stage -> global ----------------
    float* stage = (float*)smem_u;

    #pragma unroll 1
    for (int cb = 0; cb < BN / 32; cb++) {
        const int n0c = n0 + cb * 32;
        #pragma unroll
        for (int mi = 0; mi < 4; mi++)
            #pragma unroll
            for (int ni = 0; ni < NF; ni++) {
                int gc = wc * WN + ni * 8 + 2 * cc;
                if ((gc >> 5) == cb) {
                    int sc2 = gc & 31;
                    int r0 = wr * 64 + mi * 16 + rq;
                    stage[r0 * 33 + sc2]           = acc[mi][ni][0];
                    stage[r0 * 33 + sc2 + 1]       = acc[mi][ni][1];
                    stage[(r0 + 8) * 33 + sc2]     = acc[mi][ni][2];
                    stage[(r0 + 8) * 33 + sc2 + 1] = acc[mi][ni][3];
                }
            }
        __syncthreads();

        if (EPI == EPI_HEADS_T) {
            #pragma unroll 1
            for (int j = 0; j < 16; j++) {
                int e = j * 256 + tid;
                int row = e & 127, c = e >> 7;
                int m = m0 + row, n = n0c + c;
                float val = stage[row * 33 + c] + bias[n];
                int b = m >> 10, sq = m & 1023;
                int zz = b * NH + (n >> 6), dd = n & 63;
                C[((size_t)zz * DH + dd) * SEQ + sq] = val;
            }
        } else {
            #pragma unroll 1
            for (int j = 0; j < 16; j++) {
                int e = j * 256 + tid;
                int row = e >> 5, c = e & 31;
                int m = m0 + row, n = n0c + c;
                float val = stage[row * 33 + c];
                if (EPI == EPI_HEADS) {
                    val += bias[n];
                    int b = m >> 10, sq = m & 1023, h = n >> 6, dd = n & 63;
                    C[(((size_t)(b * NH + h)) * SEQ + sq) * DH + dd] = val;
                } else if (EPI == EPI_POS) {
                    val += bias[n];
                    int h = n >> 6, dd = n & 63;
                    C[((size_t)h * TWOSPAN + m) * DH + dd] = val;
                } else if (EPI == EPI_SCALE) {
                    C[(size_t)z * sC + (size_t)m * ldC + n] = val * alpha;
                } else { // EPI_OUT
                    val += bias[n] + ex1[(size_t)m * DMODEL + n];
                    C[(size_t)m * DMODEL + n] = val;
                }
            }
        }
        __syncthreads();
    }
}

// ================= flash attention: scores+softmax+PV fused =================
// grid (8 q-tiles, 64 z), 256 threads = 8 warps; warp w owns q rows 16w..16w+15.
// smem (floats): Q 8192 | K 2x4096 | V 2x4096 | P 8192 | lut 2047 ints
__global__ void __launch_bounds__(256, 1)
flash_k(const float* __restrict__ Qg, const float* __restrict__ Kg,
        const float* __restrict__ Vg, const float* __restrict__ c2p,
        const float* __restrict__ p2cT, const int* __restrict__ mask,
        float* __restrict__ ctx, float alpha)
{
    constexpr int QS = 0, KS = 8192, VS = 16384, PS = 24576;
    extern __shared__ float fsm[];
    int* lut_s = (int*)&fsm[32768];
    const uint32_t smemU = (uint32_t)__cvta_generic_to_shared(fsm);

    const int tid = threadIdx.x, lane = tid & 31, w = tid >> 5;
    const int rq = lane >> 2, cc = lane & 3;
    const int z = blockIdx.y, m0 = blockIdx.x * 128;
    const int b = z >> 4;

    const float* Qz = Qg + (size_t)z * SEQ * DH;
    const float* Kz = Kg + (size_t)z * SEQ * DH;
    const float* Vz = Vg + (size_t)z * DH * SEQ;
    const float* c2pz = c2p + (size_t)z * SEQ * TWOSPAN;
    const float* p2cz = p2cT + (size_t)z * TWOSPAN * SEQ;   // [pos][k]
    const int* mz = mask + (size_t)b * SEQ * SEQ;

    for (int t = tid; t < 2047; t += 256) lut_s[t] = g_lut[t];

    // Q tile: 128 x 64, split in 2 panels of 32 cols, xor-swizzled
    #pragma unroll
    for (int it = 0; it < 8; it++) {
        int idx = it * 256 + tid;
        int row = idx >> 4, kg = idx & 15;
        int panel = kg >> 3, kg8 = kg & 7;
        uint32_t dst = smemU + (uint32_t)(QS + panel * 4096 + row * 32 + ((kg8 ^ (row & 7)) << 2)) * 4u;
        cp16(dst, Qz + (size_t)(m0 + row) * DH + kg * 4);
    }
    auto issueKV = [&](int t) {
        int s = t & 1, n0 = t * 64;
        #pragma unroll
        for (int it = 0; it < 4; it++) {
            int idx = it * 256 + tid;
            int row = idx >> 4, kg = idx & 15;
            int panel = kg >> 3, kg8 = kg & 7;
            uint32_t sw = (uint32_t)(((kg8 ^ (row & 7)) << 2) + row * 32 + panel * 2048);
            cp16(smemU + (uint32_t)(KS + s * 4096 + sw) * 4u, Kz + (size_t)(n0 + row) * DH + kg * 4);
            cp16(smemU + (uint32_t)(VS + s * 4096 + sw) * 4u, Vz + (size_t)row * SEQ + n0 + kg * 4);
        }
    };
    issueKV(0);
    CP_COMMIT();

    float oacc[8][4];
    #pragma unroll
    for (int f = 0; f < 8; f++)
        #pragma unroll
        for (int e = 0; e < 4; e++) oacc[f][e] = 0.0f;
    float mrow[2] = {NEGF, NEGF};
    float lrow[2] = {0.0f, 0.0f};

    const int iA = m0 + 16 * w + rq, iB = iA + 8;
    const float* c2pA = c2pz + (size_t)iA * TWOSPAN;
    const float* c2pB = c2pz + (size_t)iB * TWOSPAN;
    const int* mA = mz + (size_t)iA * SEQ;
    const int* mB = mz + (size_t)iB * SEQ;

    #pragma unroll 1
    for (int t = 0; t < 16; t++) {
        const int s = t & 1, n0 = t * 64;
        CP_WAIT(0);
        __syncthreads();
        if (t + 1 < 16) issueKV(t + 1);
        CP_COMMIT();

        // ---- S = Q @ K^T ----
        float sacc[8][4];
        #pragma unroll
        for (int f = 0; f < 8; f++)
            #pragma unroll
            for (int e = 0; e < 4; e++) sacc[f][e] = 0.0f;
        #pragma unroll
        for (int ks = 0; ks < 8; ks++) {
            int panel = ks >> 2, kk = ks & 3;
            int o0 = ((2 * kk) ^ rq) << 2, o1 = ((2 * kk + 1) ^ rq) << 2;
            const float* qp = fsm + QS + panel * 4096;
            const float* kp = fsm + KS + s * 4096 + panel * 2048;
            uint32_t af[4];
            af[0] = __float_as_uint(qp[(16 * w + rq) * 32 + cc + o0]);
            af[1] = __float_as_uint(qp[(16 * w + rq + 8) * 32 + cc + o0]);
            af[2] = __float_as_uint(qp[(16 * w + rq) * 32 + cc + o1]);
            af[3] = __float_as_uint(qp[(16 * w + rq + 8) * 32 + cc + o1]);
            #pragma unroll
            for (int f = 0; f < 8; f++) {
                uint32_t bf[2];
                bf[0] = __float_as_uint(kp[(8 * f + rq) * 32 + cc + o0]);
                bf[1] = __float_as_uint(kp[(8 * f + rq) * 32 + cc + o1]);
                MMA_TF32(sacc[f], af, bf);
            }
        }

        // ---- epilogue: scale + c2p + p2c + mask, then online softmax ----
        float mx0 = NEGF, mx1 = NEGF;
        #pragma unroll
        for (int f = 0; f < 8; f++) {
            int j0 = n0 + 8 * f + 2 * cc;
            int2 mm0 = *(const int2*)&mA[j0];
            int2 mm1 = *(const int2*)&mB[j0];
            float v0 = mm0.x ? sacc[f][0] * alpha + c2pA[lut_s[iA - j0 + 1023]]
                               + p2cz[(size_t)lut_s[j0 - iA + 1023] * SEQ + j0] : NEGF;
            float v1 = mm0.y ? sacc[f][1] * alpha + c2pA[lut_s[iA - j0 + 1022]]
                               + p2cz[(size_t)lut_s[j0 + 1 - iA + 1023] * SEQ + j0 + 1] : NEGF;
            float v2 = mm1.x ? sacc[f][2] * alpha + c2pB[lut_s[iB - j0 + 1023]]
                               + p2cz[(size_t)lut_s[j0 - iB + 1023] * SEQ + j0] : NEGF;
            float v3 = mm1.y ? sacc[f][3] * alpha + c2pB[lut_s[iB - j0 + 1022]]
                               + p2cz[(size_t)lut_s[j0 + 1 - iB + 1023] * SEQ + j0 + 1] : NEGF;
            sacc[f][0] = v0; sacc[f][1] = v1; sacc[f][2] = v2; sacc[f][3] = v3;
            mx0 = fmaxf(mx0, fmaxf(v0, v1));
            mx1 = fmaxf(mx1, fmaxf(v2, v3));
        }
        mx0 = fmaxf(mx0, __shfl_xor_sync(0xffffffffu, mx0, 1));
        mx0 = fmaxf(mx0, __shfl_xor_sync(0xffffffffu, mx0, 2));
        mx1 = fmaxf(mx1, __shfl_xor_sync(0xffffffffu, mx1, 1));
        mx1 = fmaxf(mx1, __shfl_xor_sync(0xffffffffu, mx1, 2));
        float mn0 = fmaxf(mrow[0], mx0), mn1 = fmaxf(mrow[1], mx1);
        float sc0 = __expf(mrow[0] - mn0), sc1 = __expf(mrow[1] - mn1);
        mrow[0] = mn0; mrow[1] = mn1;

        float rs0 = 0.0f, rs1 = 0.0f;
        const int lrA = 16 * w + rq, lrB = lrA + 8;
        #pragma unroll
        for (int f = 0; f < 8; f++) {
            float e0 = __expf(sacc[f][0] - mn0);
            float e1 = __expf(sacc[f][1] - mn0);
            float e2 = __expf(sacc[f][2] - mn1);
            float e3 = __expf(sacc[f][3] - mn1);
            rs0 += e0 + e1; rs1 += e2 + e3;
            // masked entries contribute to denominator (matching reference) but 0 to PV
            float p0 = (sacc[f][0] == NEGF) ? 0.0f : e0;
            float p1 = (sacc[f][1] == NEGF) ? 0.0f : e1;
            float p2 = (sacc[f][2] == NEGF) ? 0.0f : e2;
            float p3 = (sacc[f][3] == NEGF) ? 0.0f : e3;
            int jl = 8 * f + 2 * cc;
            int panel = f >> 2, col32 = jl & 31;
            int base = PS + panel * 4096;
            int kgrp = col32 >> 2, rem = col32 & 3;
            fsm[base + lrA * 32 + ((kgrp ^ (lrA & 7)) << 2) + rem]     = p0;
            fsm[base + lrA * 32 + (((col32 + 1) >> 2 ^ (lrA & 7)) << 2) + ((col32 + 1) & 3)] = p1;
            fsm[base + lrB * 32 + ((kgrp ^ (lrB & 7)) << 2) + rem]     = p2;
            fsm[base + lrB * 32 + (((col32 + 1) >> 2 ^ (lrB & 7)) << 2) + ((col32 + 1) & 3)] = p3;
        }
        rs0 += __shfl_xor_sync(0xffffffffu, rs0, 1);
        rs0 += __shfl_xor_sync(0xffffffffu, rs0, 2);
        rs1 += __shfl_xor_sync(0xffffffffu, rs1, 1);
        rs1 += __shfl_xor_sync(0xffffffffu, rs1, 2);
        lrow[0] = lrow[0] * sc0 + rs0;
        lrow[1] = lrow[1] * sc1 + rs1;
        #pragma unroll
        for (int f = 0; f < 8; f++) {
            oacc[f][0] *= sc0; oacc[f][1] *= sc0;
            oacc[f][2] *= sc1; oacc[f][3] *= sc1;
        }
        __syncthreads();

        // ---- O += P @ V^T ----
        #pragma unroll
        for (int ks = 0; ks < 8; ks++) {
            int panel = ks >> 2, kk = ks & 3;
            int o0 = ((2 * kk) ^ rq) << 2, o1 = ((2 * kk + 1) ^ rq) << 2;
            const float* pp = fsm + PS + panel * 4096;
            const float* vp = fsm + VS + s * 4096 + panel * 2048;
            uint32_t af[4];
            af[0] = __float_as_uint(pp[(16 * w + rq) * 32 + cc + o0]);
            af[1] = __float_as_uint(pp[(16 * w + rq + 8) * 32 + cc + o0]);
            af[2] = __float_as_uint(pp[(16 * w + rq) * 32 + cc + o1]);
            af[3] = __float_as_uint(pp[(16 * w + rq + 8) * 32 + cc + o1]);
            #pragma unroll
            for (int f = 0; f < 8; f++) {
                uint32_t bf[2];
                bf[0] = __float_as_uint(vp[(8 * f + rq) * 32 + cc + o0]);
                bf[1] = __float_as_uint(vp[(8 * f + rq) * 32 + cc + o1]);
                MMA_TF32(oacc[f], af, bf);
            }
        }
    }

    // ---- write ctx: [b][s][h*64+d] ----
    float inv0 = 1.0f / lrow[0], inv1 = 1.0f / lrow[1];
    int h = z & 15;
    float* crow0 = ctx + ((size_t)b * SEQ + (size_t)(m0 + 16 * w + rq)) * DMODEL + h * DH;
    float* crow1 = crow0 + (size_t)8 * DMODEL;
    #pragma unroll
    for (int f = 0; f < 8; f++) {
        int d0 = 8 * f + 2 * cc;
        float2 a = make_float2(oacc[f][0] * inv0, oacc[f][1] * inv0);
        float2 c = make_float2(oacc[f][2] * inv1, oacc[f][3] * inv1);
        *(float2*)&crow0[d0] = a;
        *(float2*)&crow1[d0] = c;
    }
}

// ================= layernorm ================================================
__device__ __forceinline__ float block_sum(float v, float* sh) {
    #pragma unroll
    for (int o = 16; o; o >>= 1) v += __shfl_xor_sync(0xffffffffu, v, o);
    int lane = threadIdx.x & 31, w = threadIdx.x >> 5;
    __syncthreads();
    if (lane == 0) sh[w] = v;
    __syncthreads();
    if (w == 0) {
        float x = (lane < (blockDim.x >> 5)) ? sh[lane] : 0.0f;
        #pragma unroll
        for (int o = 16; o; o >>= 1) x += __shfl_xor_sync(0xffffffffu, x, o);
        if (lane == 0) sh[0] = x;
    }
    __syncthreads();
    return sh[0];
}
__global__ void ln_k(float* __restrict__ out, const float* __restrict__ gamma,
                     const float* __restrict__ beta) {
    __shared__ float sh[32];
    int row = blockIdx.x, t = threadIdx.x;
    float* p = out + (size_t)row * DMODEL;
    float4 v = *(const float4*)(p + t * 4);
    float mean = block_sum(v.x + v.y + v.z + v.w, sh) * (1.0f / DMODEL);
    float dx = v.x - mean, dy = v.y - mean, dz = v.z - mean, dw = v.w - mean;
    float var = block_sum(dx*dx + dy*dy + dz*dz + dw*dw, sh) * (1.0f / DMODEL);
    float inv = rsqrtf(var + 1e-7f);
    float4 g = *(const float4*)(gamma + t * 4);
    float4 bb = *(const float4*)(beta + t * 4);
    float4 o;
    o.x = dx*inv*g.x + bb.x; o.y = dy*inv*g.y + bb.y;
    o.z = dz*inv*g.z + bb.z; o.w = dw*inv*g.w + bb.w;
    *(float4*)(p + t * 4) = o;
}

// ================= launch ====================================================
extern "C" void kernel_launch(void* const* d_in, const int* in_sizes, int n_in,
                              void* d_out, int out_size) {
    const float* hidden = (const float*)d_in[0];
    const int*   mask   = (const int*)  d_in[1];
    const float* rel    = (const float*)d_in[2];
    const float* Wq     = (const float*)d_in[3];
    const float* bq     = (const float*)d_in[4];
    const float* Wk     = (const float*)d_in[5];
    const float* bk     = (const float*)d_in[6];
    const float* Wv     = (const float*)d_in[7];
    const float* bv     = (const float*)d_in[8];
    const float* Wo     = (const float*)d_in[9];
    const float* bo     = (const float*)d_in[10];
    const float* gamma  = (const float*)d_in[11];
    const float* beta   = (const float*)d_in[12];
    float* out = (float*)d_out;

    float *q, *k, *vt, *pk, *pq, *c2p, *p2cT, *ctx;
    cudaGetSymbolAddress((void**)&q,    g_q);
    cudaGetSymbolAddress((void**)&k,    g_k);
    cudaGetSymbolAddress((void**)&vt,   g_vt);
    cudaGetSymbolAddress((void**)&pk,   g_posk);
    cudaGetSymbolAddress((void**)&pq,   g_posq);
    cudaGetSymbolAddress((void**)&c2p,  g_c2p);
    cudaGetSymbolAddress((void**)&p2cT, g_p2cT);
    cudaGetSymbolAddress((void**)&ctx,  g_ctx);

    const float alpha = 1.0f / sqrtf((float)(DH * 3));
    const size_t SM128 = (size_t)3 * (128 * 32 + 128 * 32) * 4;   // 98304
    const size_t SMF   = (size_t)32768 * 4 + 2048 * 4;            // 139264

    cudaFuncSetAttribute((const void*)tc_gemm<EPI_HEADS,  128, 32>, cudaFuncAttributeMaxDynamicSharedMemorySize, (int)SM128);
    cudaFuncSetAttribute((const void*)tc_gemm<EPI_HEADS_T,128, 32>, cudaFuncAttributeMaxDynamicSharedMemorySize, (int)SM128);
    cudaFuncSetAttribute((const void*)tc_gemm<EPI_POS,    128, 32>, cudaFuncAttributeMaxDynamicSharedMemorySize, (int)SM128);
    cudaFuncSetAttribute((const void*)tc_gemm<EPI_SCALE,  128,  2>, cudaFuncAttributeMaxDynamicSharedMemorySize, (int)SM128);
    cudaFuncSetAttribute((const void*)tc_gemm<EPI_OUT,    128, 32>, cudaFuncAttributeMaxDynamicSharedMemorySize, (int)SM128);
    cudaFuncSetAttribute((const void*)flash_k, cudaFuncAttributeMaxDynamicSharedMemorySize, (int)SMF);

    lut_k<<<2, 1024>>>();

    // Q, K, V projections (M=4096, N=1024, K=1024)
    tc_gemm<EPI_HEADS,  128, 32><<<dim3(8, 32, 1), 256, SM128>>>(hidden, Wq, bq, 0, q,  1024, 0, 0, 0, 0, 0, 0, 1.f);
    tc_gemm<EPI_HEADS,  128, 32><<<dim3(8, 32, 1), 256, SM128>>>(hidden, Wk, bk, 0, k,  1024, 0, 0, 0, 0, 0, 0, 1.f);
    tc_gemm<EPI_HEADS_T,128, 32><<<dim3(8, 32, 1), 256, SM128>>>(hidden, Wv, bv, 0, vt, 1024, 0, 0, 0, 0, 0, 0, 1.f);
    // position projections (M=512)
    tc_gemm<EPI_POS, 128, 32><<<dim3(8, 4, 1), 256, SM128>>>(rel, Wk, bk, 0, pk, 1024, 0, 0, 0, 0, 0, 0, 1.f);
    tc_gemm<EPI_POS, 128, 32><<<dim3(8, 4, 1), 256, SM128>>>(rel, Wq, bq, 0, pq, 1024, 0, 0, 0, 0, 0, 0, 1.f);
    // c2p: [z][q][p] = alpha * q[z] @ posk[h]^T    (M=1024, N=512, K=64)
    tc_gemm<EPI_SCALE, 128, 2><<<dim3(4, 8, NBATCH), 256, SM128>>>(
        q, pk, 0, 0, c2p, 64, (size_t)SEQ*DH, (size_t)TWOSPAN*DH, 0, NH,
        (size_t)SEQ*TWOSPAN, TWOSPAN, alpha);
    // p2cT: [z][p][k] = alpha * posq[h] @ k[z]^T   (M=512, N=1024, K=64)  -- transposed table
    tc_gemm<EPI_SCALE, 128, 2><<<dim3(8, 4, NBATCH), 256, SM128>>>(
        pq, k, 0, 0, p2cT, 64, (size_t)TWOSPAN*DH, (size_t)SEQ*DH, NH, 0,
        (size_t)TWOSPAN*SEQ, SEQ, alpha);

    // fused attention: scores + masked softmax + P@V
    flash_k<<<dim3(8, NBATCH), 256, SMF>>>(q, k, vt, c2p, p2cT, mask, ctx, alpha);

    // output projection + residual
    tc_gemm<EPI_OUT, 128, 32><<<dim3(8, 32, 1), 256, SM128>>>(ctx, Wo, bo, hidden, out, 1024, 0, 0, 0, 0, 0, 0, 1.f);

    ln_k<<<BDIM * SEQ, 256>>>(out, gamma, beta);
}

// round 8
// speedup vs baseline: 1.2017x; 1.1090x over previous
#include <cuda_runtime.h>
#include <cuda_fp16.h>
#include <math.h>
#include <stdint.h>

#define BDIM 4
#define SEQ 1024
#define DMODEL 1024
#define NH 16
#define DH 64
#define SPAN 256
#define TWOSPAN 512
#define NBATCH (BDIM*NH)   /* 64 */
#define NEGF (-3.402823466e38f)

// ---------------- scratch (device globals; no allocation allowed) ----------
__device__ float  g_q   [(size_t)NBATCH * SEQ * DH];        // [z][s][d]
__device__ float  g_k   [(size_t)NBATCH * SEQ * DH];        // [z][s][d]
__device__ __half g_vt  [(size_t)NBATCH * DH * SEQ];        // [z][d][s] fp16 (transposed V)
__device__ float  g_posk[(size_t)NH * TWOSPAN * DH];        // [h][p][d]
__device__ float  g_posq[(size_t)NH * TWOSPAN * DH];
__device__ float  g_c2p [(size_t)NBATCH * SEQ * TWOSPAN];   // [z][q][p]   (pre-scaled)
__device__ float  g_p2cT[(size_t)NBATCH * TWOSPAN * SEQ];   // [z][p][k]   (transposed, pre-scaled)
__device__ float  g_ctx [(size_t)BDIM * SEQ * DMODEL];
__device__ int    g_lut [2047];                              // clipped bucket idx per delta

// ================= small helpers ============================================
#define MMA_TF32(d, a, b) \
    asm volatile("mma.sync.aligned.m16n8k8.row.col.f32.tf32.tf32.f32 " \
        "{%0,%1,%2,%3}, {%4,%5,%6,%7}, {%8,%9}, {%0,%1,%2,%3};" \
        : "+f"((d)[0]), "+f"((d)[1]), "+f"((d)[2]), "+f"((d)[3]) \
        : "r"((a)[0]), "r"((a)[1]), "r"((a)[2]), "r"((a)[3]), \
          "r"((b)[0]), "r"((b)[1]))

#define MMA_F16(d, a, b) \
    asm volatile("mma.sync.aligned.m16n8k16.row.col.f32.f16.f16.f32 " \
        "{%0,%1,%2,%3}, {%4,%5,%6,%7}, {%8,%9}, {%0,%1,%2,%3};" \
        : "+f"((d)[0]), "+f"((d)[1]), "+f"((d)[2]), "+f"((d)[3]) \
        : "r"((a)[0]), "r"((a)[1]), "r"((a)[2]), "r"((a)[3]), \
          "r"((b)[0]), "r"((b)[1]))

__device__ __forceinline__ uint32_t pack_h2(float lo, float hi) {
    uint32_t u;
    asm("cvt.rn.f16x2.f32 %0, %1, %2;" : "=r"(u) : "f"(hi), "f"(lo));
    return u;
}
__device__ __forceinline__ void cp16(uint32_t dst, const void* src) {
    asm volatile("cp.async.cg.shared.global [%0], [%1], 16;" :: "r"(dst), "l"(src));
}
#define CP_COMMIT() asm volatile("cp.async.commit_group;" ::: "memory")
#define CP_WAIT(n)  asm volatile("cp.async.wait_group %0;" :: "n"(n) : "memory")

// ================= rel-position bucket LUT ==================================
__device__ __forceinline__ int rel_bucket(int rel) {
    float abs_pos = (rel < 128 && rel > -128) ? 127.0f : fabsf((float)rel);
    if (abs_pos <= 128.0f) return rel;
    float sgn = (rel > 0) ? 1.0f : -1.0f;
    float log_pos = ceilf(logf(abs_pos * (1.0f/128.0f)) / logf(511.0f/128.0f) * 127.0f) + 128.0f;
    return (int)(log_pos * sgn);
}
__global__ void lut_k() {
    int t = blockIdx.x * blockDim.x + threadIdx.x;
    if (t >= 2047) return;
    int b = rel_bucket(t - 1023);
    g_lut[t] = min(max(b + SPAN, 0), TWOSPAN - 1);
}

// ================= unified tf32 mma.sync GEMM (C = A @ B^T + epilogues) =====
#define EPI_HEADS   0
#define EPI_HEADS_T 1
#define EPI_POS     2
#define EPI_SCALE   3
#define EPI_OUT     6

template<int EPI, int BN, int CH>
__global__ void __launch_bounds__(256, 2)
tc_gemm(const float* __restrict__ A, const float* __restrict__ Bm,
        const float* __restrict__ bias, const float* __restrict__ ex1,
        float* __restrict__ C,
        int Ka, size_t sA, size_t sB, int nbModA, int nbModB,
        size_t sC, int ldC, float alpha)
{
    constexpr int NS    = 3;
    constexpr int WN    = BN / 4;
    constexpr int NF    = WN / 8;
    constexpr int BNW   = BN / 32;
    constexpr int AELEM = 128 * 32;
    constexpr int BELEM = BN * 32;

    extern __shared__ uint32_t smem_u[];
    const uint32_t smemU = (uint32_t)__cvta_generic_to_shared(smem_u);

    const int tid  = threadIdx.x;
    const int lane = tid & 31, wid = tid >> 5;
    const int wr = wid & 1, wc = wid >> 1;
    const int rq = lane >> 2, cc = lane & 3;
    const int z  = blockIdx.z;
    const int m0 = blockIdx.y * 128;
    const int n0 = blockIdx.x * BN;

    A  += (size_t)(nbModA ? (z % nbModA) : z) * sA + (size_t)m0 * Ka;
    Bm += (size_t)(nbModB ? (z % nbModB) : z) * sB + (size_t)n0 * Ka;

    float acc[4][NF][4];
    #pragma unroll
    for (int a = 0; a < 4; a++)
        #pragma unroll
        for (int b = 0; b < NF; b++)
            #pragma unroll
            for (int c = 0; c < 4; c++) acc[a][b][c] = 0.0f;

    int aBase[4][2];
    #pragma unroll
    for (int mi = 0; mi < 4; mi++) {
        int r = wr * 64 + mi * 16 + rq;
        aBase[mi][0] = r * 32 + cc;
        aBase[mi][1] = (r + 8) * 32 + cc;
    }
    int bBase[NF];
    #pragma unroll
    for (int ni = 0; ni < NF; ni++)
        bBase[ni] = (wc * WN + ni * 8 + rq) * 32 + cc;

    const int crow = tid >> 3;
    const int ckg  = tid & 7;

    auto issue = [&](int chunk) {
        const int s  = chunk % NS;
        const int k0 = chunk * 32;
        #pragma unroll
        for (int j = 0; j < 4; j++) {
            int row = j * 32 + crow;
            uint32_t dst = smemU + (uint32_t)(s * AELEM + row * 32 + ((ckg ^ (row & 7)) << 2)) * 4u;
            cp16(dst, A + (size_t)row * Ka + k0 + ckg * 4);
        }
        #pragma unroll
        for (int j = 0; j < BNW; j++) {
            int row = j * 32 + crow;
            uint32_t dst = smemU + (uint32_t)(NS * AELEM + s * BELEM + row * 32 + ((ckg ^ (row & 7)) << 2)) * 4u;
            cp16(dst, Bm + (size_t)row * Ka + k0 + ckg * 4);
        }
    };

    #pragma unroll
    for (int c = 0; c < NS - 1; c++) {
        if (c < CH) issue(c);
        CP_COMMIT();
    }

    #pragma unroll 1
    for (int i = 0; i < CH; i++) {
        CP_WAIT(NS - 2);
        __syncthreads();
        if (i + NS - 1 < CH) issue(i + NS - 1);
        CP_COMMIT();

        const uint32_t* as = smem_u + (i % NS) * AELEM;
        const uint32_t* bs = smem_u + NS * AELEM + (i % NS) * BELEM;
        #pragma unroll
        for (int ks = 0; ks < 4; ks++) {
            const int o0 = ((2 * ks) ^ rq) << 2;
            const int o1 = ((2 * ks + 1) ^ rq) << 2;
            uint32_t af[4][4];
            #pragma unroll
            for (int mi = 0; mi < 4; mi++) {
                af[mi][0] = as[aBase[mi][0] + o0];
                af[mi][1] = as[aBase[mi][1] + o0];
                af[mi][2] = as[aBase[mi][0] + o1];
                af[mi][3] = as[aBase[mi][1] + o1];
            }
            uint32_t bf[NF][2];
            #pragma unroll
            for (int ni = 0; ni < NF; ni++) {
                bf[ni][0] = bs[bBase[ni] + o0];
                bf[ni][1] = bs[bBase[ni] + o1];
            }
            #pragma unroll
            for (int mi = 0; mi < 4; mi++)
                #pragma unroll
                for (int ni = 0; ni < NF; ni++)
                    MMA_TF32(acc[mi][ni], af[mi], bf[ni]);
        }
    }
    CP_WAIT(0);
    __syncthreads();

    // ---------------- epilogue: frags -> smem stage -> global ----------------
    float* stage = (float*)smem_u;

    #pragma unroll 1
    for (int cb = 0; cb < BN / 32; cb++) {
        const int n0c = n0 + cb * 32;
        #pragma unroll
        for (int mi = 0; mi < 4; mi++)
            #pragma unroll
            for (int ni = 0; ni < NF; ni++) {
                int gc = wc * WN + ni * 8 + 2 * cc;
                if ((gc >> 5) == cb) {
                    int sc2 = gc & 31;
                    int r0 = wr * 64 + mi * 16 + rq;
                    stage[r0 * 33 + sc2]           = acc[mi][ni][0];
                    stage[r0 * 33 + sc2 + 1]       = acc[mi][ni][1];
                    stage[(r0 + 8) * 33 + sc2]     = acc[mi][ni][2];
                    stage[(r0 + 8) * 33 + sc2 + 1] = acc[mi][ni][3];
                }
            }
        __syncthreads();

        if (EPI == EPI_HEADS_T) {
            // V projection: write fp16 transposed [z][d][s]
            #pragma unroll 1
            for (int j = 0; j < 16; j++) {
                int e = j * 256 + tid;
                int row = e & 127, c = e >> 7;
                int m = m0 + row, n = n0c + c;
                float val = stage[row * 33 + c] + bias[n];
                int b = m >> 10, sq = m & 1023;
                int zz = b * NH + (n >> 6), dd = n & 63;
                ((__half*)C)[((size_t)zz * DH + dd) * SEQ + sq] = __float2half(val);
            }
        } else {
            #pragma unroll 1
            for (int j = 0; j < 16; j++) {
                int e = j * 256 + tid;
                int row = e >> 5, c = e & 31;
                int m = m0 + row, n = n0c + c;
                float val = stage[row * 33 + c];
                if (EPI == EPI_HEADS) {
                    val += bias[n];
                    int b = m >> 10, sq = m & 1023, h = n >> 6, dd = n & 63;
                    C[(((size_t)(b * NH + h)) * SEQ + sq) * DH + dd] = val;
                } else if (EPI == EPI_POS) {
                    val += bias[n];
                    int h = n >> 6, dd = n & 63;
                    C[((size_t)h * TWOSPAN + m) * DH + dd] = val;
                } else if (EPI == EPI_SCALE) {
                    C[(size_t)z * sC + (size_t)m * ldC + n] = val * alpha;
                } else { // EPI_OUT
                    val += bias[n] + ex1[(size_t)m * DMODEL + n];
                    C[(size_t)m * DMODEL + n] = val;
                }
            }
        }
        __syncthreads();
    }
}

// ================= flash attention: scores+softmax+PV fused =================
// grid (8 q-tiles, 64 z), 256 threads = 8 warps; warp w owns q rows 16w..16w+15.
// smem bytes: Q 32768 | K 2x16384 | V(fp16) 2x8192 | lut 8188  => ~88KB, 2 CTA/SM
__global__ void __launch_bounds__(256, 2)
flash_k(const float* __restrict__ Qg, const float* __restrict__ Kg,
        const __half* __restrict__ Vg, const float* __restrict__ c2p,
        const float* __restrict__ p2cT, const int* __restrict__ mask,
        float* __restrict__ ctx, float alpha)
{
    constexpr int QS = 0, KS = 8192;          // float indices
    constexpr int VSB = 65536;                 // byte offset of V region
    extern __shared__ float fsm[];
    int* lut_s = (int*)&fsm[20480];
    char* smc = (char*)fsm;
    const uint32_t smemU = (uint32_t)__cvta_generic_to_shared(fsm);

    const int tid = threadIdx.x, lane = tid & 31, w = tid >> 5;
    const int rq = lane >> 2, cc = lane & 3;
    const int z = blockIdx.y, m0 = blockIdx.x * 128;
    const int b = z >> 4;

    const float*  Qz = Qg + (size_t)z * SEQ * DH;
    const float*  Kz = Kg + (size_t)z * SEQ * DH;
    const __half* Vz = Vg + (size_t)z * DH * SEQ;
    const float* c2pz = c2p + (size_t)z * SEQ * TWOSPAN;
    const float* p2cz = p2cT + (size_t)z * TWOSPAN * SEQ;   // [pos][k]
    const int* mz = mask + (size_t)b * SEQ * SEQ;

    for (int t = tid; t < 2047; t += 256) lut_s[t] = g_lut[t];

    // Q tile: 128 x 64 fp32, 2 panels of 32 cols, xor-swizzled
    #pragma unroll
    for (int it = 0; it < 8; it++) {
        int idx = it * 256 + tid;
        int row = idx >> 4, kg = idx & 15;
        int panel = kg >> 3, kg8 = kg & 7;
        uint32_t dst = smemU + (uint32_t)(QS + panel * 4096 + row * 32 + ((kg8 ^ (row & 7)) << 2)) * 4u;
        cp16(dst, Qz + (size_t)(m0 + row) * DH + kg * 4);
    }
    auto issueKV = [&](int t) {
        int s = t & 1, n0 = t * 64;
        #pragma unroll
        for (int it = 0; it < 4; it++) {        // K: 64 rows x 64 fp32
            int idx = it * 256 + tid;
            int row = idx >> 4, kg = idx & 15;
            int panel = kg >> 3, kg8 = kg & 7;
            uint32_t sw = (uint32_t)(((kg8 ^ (row & 7)) << 2) + row * 32 + panel * 2048);
            cp16(smemU + (uint32_t)(KS + s * 4096 + sw) * 4u, Kz + (size_t)(n0 + row) * DH + kg * 4);
        }
        #pragma unroll
        for (int it = 0; it < 2; it++) {        // V: 64 d-rows x 64 fp16
            int idx = it * 256 + tid;
            int row = idx >> 3, kg = idx & 7;
            uint32_t dst = smemU + (uint32_t)(VSB + s * 8192 + row * 128 + ((kg ^ (row & 7)) << 4));
            cp16(dst, Vz + (size_t)row * SEQ + n0 + kg * 8);
        }
    };
    issueKV(0);
    CP_COMMIT();

    float oacc[8][4];
    #pragma unroll
    for (int f = 0; f < 8; f++)
        #pragma unroll
        for (int e = 0; e < 4; e++) oacc[f][e] = 0.0f;
    float mrow[2] = {NEGF, NEGF};
    float lrow[2] = {0.0f, 0.0f};

    const int iA = m0 + 16 * w + rq, iB = iA + 8;
    const float* c2pA = c2pz + (size_t)iA * TWOSPAN;
    const float* c2pB = c2pz + (size_t)iB * TWOSPAN;
    const int* mA = mz + (size_t)iA * SEQ;
    const int* mB = mz + (size_t)iB * SEQ;

    #pragma unroll 1
    for (int t = 0; t < 16; t++) {
        const int s = t & 1, n0 = t * 64;
        CP_WAIT(0);
        __syncthreads();
        if (t + 1 < 16) issueKV(t + 1);
        CP_COMMIT();

        // ---- S = Q @ K^T (tf32) ----
        float sacc[8][4];
        #pragma unroll
        for (int f = 0; f < 8; f++)
            #pragma unroll
            for (int e = 0; e < 4; e++) sacc[f][e] = 0.0f;
        #pragma unroll
        for (int ks = 0; ks < 8; ks++) {
            int panel = ks >> 2, kk = ks & 3;
            int o0 = ((2 * kk) ^ rq) << 2, o1 = ((2 * kk + 1) ^ rq) << 2;
            const float* qp = fsm + QS + panel * 4096;
            const float* kp = fsm + KS + s * 4096 + panel * 2048;
            uint32_t af[4];
            af[0] = __float_as_uint(qp[(16 * w + rq) * 32 + cc + o0]);
            af[1] = __float_as_uint(qp[(16 * w + rq + 8) * 32 + cc + o0]);
            af[2] = __float_as_uint(qp[(16 * w + rq) * 32 + cc + o1]);
            af[3] = __float_as_uint(qp[(16 * w + rq + 8) * 32 + cc + o1]);
            #pragma unroll
            for (int f = 0; f < 8; f++) {
                uint32_t bf[2];
                bf[0] = __float_as_uint(kp[(8 * f + rq) * 32 + cc + o0]);
                bf[1] = __float_as_uint(kp[(8 * f + rq) * 32 + cc + o1]);
                MMA_TF32(sacc[f], af, bf);
            }
        }

        // ---- scale + c2p + p2c + mask, row max ----
        float mx0 = NEGF, mx1 = NEGF;
        #pragma unroll
        for (int f = 0; f < 8; f++) {
            int j0 = n0 + 8 * f + 2 * cc;
            int2 mm0 = *(const int2*)&mA[j0];
            int2 mm1 = *(const int2*)&mB[j0];
            float v0 = mm0.x ? sacc[f][0] * alpha + c2pA[lut_s[iA - j0 + 1023]]
                               + p2cz[(size_t)lut_s[j0 - iA + 1023] * SEQ + j0] : NEGF;
            float v1 = mm0.y ? sacc[f][1] * alpha + c2pA[lut_s[iA - j0 + 1022]]
                               + p2cz[(size_t)lut_s[j0 + 1 - iA + 1023] * SEQ + j0 + 1] : NEGF;
            float v2 = mm1.x ? sacc[f][2] * alpha + c2pB[lut_s[iB - j0 + 1023]]
                               + p2cz[(size_t)lut_s[j0 - iB + 1023] * SEQ + j0] : NEGF;
            float v3 = mm1.y ? sacc[f][3] * alpha + c2pB[lut_s[iB - j0 + 1022]]
                               + p2cz[(size_t)lut_s[j0 + 1 - iB + 1023] * SEQ + j0 + 1] : NEGF;
            sacc[f][0] = v0; sacc[f][1] = v1; sacc[f][2] = v2; sacc[f][3] = v3;
            mx0 = fmaxf(mx0, fmaxf(v0, v1));
            mx1 = fmaxf(mx1, fmaxf(v2, v3));
        }
        mx0 = fmaxf(mx0, __shfl_xor_sync(0xffffffffu, mx0, 1));
        mx0 = fmaxf(mx0, __shfl_xor_sync(0xffffffffu, mx0, 2));
        mx1 = fmaxf(mx1, __shfl_xor_sync(0xffffffffu, mx1, 1));
        mx1 = fmaxf(mx1, __shfl_xor_sync(0xffffffffu, mx1, 2));
        float mn0 = fmaxf(mrow[0], mx0), mn1 = fmaxf(mrow[1], mx1);
        float sc0 = __expf(mrow[0] - mn0), sc1 = __expf(mrow[1] - mn1);
        mrow[0] = mn0; mrow[1] = mn1;

        // ---- exp, pack P to fp16 A-fragments in-register ----
        float rs0 = 0.0f, rs1 = 0.0f;
        uint32_t ph[8][2];
        #pragma unroll
        for (int f = 0; f < 8; f++) {
            float e0 = __expf(sacc[f][0] - mn0);
            float e1 = __expf(sacc[f][1] - mn0);
            float e2 = __expf(sacc[f][2] - mn1);
            float e3 = __expf(sacc[f][3] - mn1);
            rs0 += e0 + e1; rs1 += e2 + e3;
            // masked entries contribute to denominator (reference) but 0 to PV
            float p0 = (sacc[f][0] == NEGF) ? 0.0f : e0;
            float p1 = (sacc[f][1] == NEGF) ? 0.0f : e1;
            float p2 = (sacc[f][2] == NEGF) ? 0.0f : e2;
            float p3 = (sacc[f][3] == NEGF) ? 0.0f : e3;
            ph[f][0] = pack_h2(p0, p1);   // row rq,   k = 2cc, 2cc+1
            ph[f][1] = pack_h2(p2, p3);   // row rq+8, k = 2cc, 2cc+1
        }
        rs0 += __shfl_xor_sync(0xffffffffu, rs0, 1);
        rs0 += __shfl_xor_sync(0xffffffffu, rs0, 2);
        rs1 += __shfl_xor_sync(0xffffffffu, rs1, 1);
        rs1 += __shfl_xor_sync(0xffffffffu, rs1, 2);
        lrow[0] = lrow[0] * sc0 + rs0;
        lrow[1] = lrow[1] * sc1 + rs1;
        #pragma unroll
        for (int f = 0; f < 8; f++) {
            oacc[f][0] *= sc0; oacc[f][1] *= sc0;
            oacc[f][2] *= sc1; oacc[f][3] *= sc1;
        }

        // ---- O += P @ V (fp16 m16n8k16, P in registers, V fp16 smem) ----
        const char* vp = smc + VSB + s * 8192;
        #pragma unroll
        for (int ks2 = 0; ks2 < 4; ks2++) {
            uint32_t a[4] = { ph[2*ks2][0], ph[2*ks2][1], ph[2*ks2+1][0], ph[2*ks2+1][1] };
            int g0 = (2 * ks2) ^ rq, g1 = (2 * ks2 + 1) ^ rq;
            #pragma unroll
            for (int n = 0; n < 8; n++) {
                int d = 8 * n + rq;
                uint32_t bf[2];
                bf[0] = *(const uint32_t*)(vp + d * 128 + (g0 << 4) + 4 * cc);
                bf[1] = *(const uint32_t*)(vp + d * 128 + (g1 << 4) + 4 * cc);
                MMA_F16(oacc[n], a, bf);
            }
        }
    }

    // ---- write ctx: [b][s][h*64+d] ----
    float inv0 = 1.0f / lrow[0], inv1 = 1.0f / lrow[1];
    int h = z & 15;
    float* crow0 = ctx + ((size_t)b * SEQ + (size_t)(m0 + 16 * w + rq)) * DMODEL + h * DH;
    float* crow1 = crow0 + (size_t)8 * DMODEL;
    #pragma unroll
    for (int f = 0; f < 8; f++) {
        int d0 = 8 * f + 2 * cc;
        float2 a = make_float2(oacc[f][0] * inv0, oacc[f][1] * inv0);
        float2 c = make_float2(oacc[f][2] * inv1, oacc[f][3] * inv1);
        *(float2*)&crow0[d0] = a;
        *(float2*)&crow1[d0] = c;
    }
}

// ================= layernorm ================================================
__device__ __forceinline__ float block_sum(float v, float* sh) {
    #pragma unroll
    for (int o = 16; o; o >>= 1) v += __shfl_xor_sync(0xffffffffu, v, o);
    int lane = threadIdx.x & 31, w = threadIdx.x >> 5;
    __syncthreads();
    if (lane == 0) sh[w] = v;
    __syncthreads();
    if (w == 0) {
        float x = (lane < (blockDim.x >> 5)) ? sh[lane] : 0.0f;
        #pragma unroll
        for (int o = 16; o; o >>= 1) x += __shfl_xor_sync(0xffffffffu, x, o);
        if (lane == 0) sh[0] = x;
    }
    __syncthreads();
    return sh[0];
}
__global__ void ln_k(float* __restrict__ out, const float* __restrict__ gamma,
                     const float* __restrict__ beta) {
    __shared__ float sh[32];
    int row = blockIdx.x, t = threadIdx.x;
    float* p = out + (size_t)row * DMODEL;
    float4 v = *(const float4*)(p + t * 4);
    float mean = block_sum(v.x + v.y + v.z + v.w, sh) * (1.0f / DMODEL);
    float dx = v.x - mean, dy = v.y - mean, dz = v.z - mean, dw = v.w - mean;
    float var = block_sum(dx*dx + dy*dy + dz*dz + dw*dw, sh) * (1.0f / DMODEL);
    float inv = rsqrtf(var + 1e-7f);
    float4 g = *(const float4*)(gamma + t * 4);
    float4 bb = *(const float4*)(beta + t * 4);
    float4 o;
    o.x = dx*inv*g.x + bb.x; o.y = dy*inv*g.y + bb.y;
    o.z = dz*inv*g.z + bb.z; o.w = dw*inv*g.w + bb.w;
    *(float4*)(p + t * 4) = o;
}

// ================= launch ====================================================
extern "C" void kernel_launch(void* const* d_in, const int* in_sizes, int n_in,
                              void* d_out, int out_size) {
    const float* hidden = (const float*)d_in[0];
    const int*   mask   = (const int*)  d_in[1];
    const float* rel    = (const float*)d_in[2];
    const float* Wq     = (const float*)d_in[3];
    const float* bq     = (const float*)d_in[4];
    const float* Wk     = (const float*)d_in[5];
    const float* bk     = (const float*)d_in[6];
    const float* Wv     = (const float*)d_in[7];
    const float* bv     = (const float*)d_in[8];
    const float* Wo     = (const float*)d_in[9];
    const float* bo     = (const float*)d_in[10];
    const float* gamma  = (const float*)d_in[11];
    const float* beta   = (const float*)d_in[12];
    float* out = (float*)d_out;

    float *q, *k, *pk, *pq, *c2p, *p2cT, *ctx;
    __half* vt;
    cudaGetSymbolAddress((void**)&q,    g_q);
    cudaGetSymbolAddress((void**)&k,    g_k);
    cudaGetSymbolAddress((void**)&vt,   g_vt);
    cudaGetSymbolAddress((void**)&pk,   g_posk);
    cudaGetSymbolAddress((void**)&pq,   g_posq);
    cudaGetSymbolAddress((void**)&c2p,  g_c2p);
    cudaGetSymbolAddress((void**)&p2cT, g_p2cT);
    cudaGetSymbolAddress((void**)&ctx,  g_ctx);

    const float alpha = 1.0f / sqrtf((float)(DH * 3));
    const size_t SM128 = (size_t)3 * (128 * 32 + 128 * 32) * 4;   // 98304
    const size_t SMF   = 90112;                                    // Q32K+K32K+V16K+lut

    cudaFuncSetAttribute((const void*)tc_gemm<EPI_HEADS,  128, 32>, cudaFuncAttributeMaxDynamicSharedMemorySize, (int)SM128);
    cudaFuncSetAttribute((const void*)tc_gemm<EPI_HEADS_T,128, 32>, cudaFuncAttributeMaxDynamicSharedMemorySize, (int)SM128);
    cudaFuncSetAttribute((const void*)tc_gemm<EPI_POS,    128, 32>, cudaFuncAttributeMaxDynamicSharedMemorySize, (int)SM128);
    cudaFuncSetAttribute((const void*)tc_gemm<EPI_SCALE,  128,  2>, cudaFuncAttributeMaxDynamicSharedMemorySize, (int)SM128);
    cudaFuncSetAttribute((const void*)tc_gemm<EPI_OUT,    128, 32>, cudaFuncAttributeMaxDynamicSharedMemorySize, (int)SM128);
    cudaFuncSetAttribute((const void*)flash_k, cudaFuncAttributeMaxDynamicSharedMemorySize, (int)SMF);

    lut_k<<<2, 1024>>>();

    // Q, K, V projections (M=4096, N=1024, K=1024)
    tc_gemm<EPI_HEADS,  128, 32><<<dim3(8, 32, 1), 256, SM128>>>(hidden, Wq, bq, 0, q,  1024, 0, 0, 0, 0, 0, 0, 1.f);
    tc_gemm<EPI_HEADS,  128, 32><<<dim3(8, 32, 1), 256, SM128>>>(hidden, Wk, bk, 0, k,  1024, 0, 0, 0, 0, 0, 0, 1.f);
    tc_gemm<EPI_HEADS_T,128, 32><<<dim3(8, 32, 1), 256, SM128>>>(hidden, Wv, bv, 0, (float*)vt, 1024, 0, 0, 0, 0, 0, 0, 1.f);
    // position projections (M=512)
    tc_gemm<EPI_POS, 128, 32><<<dim3(8, 4, 1), 256, SM128>>>(rel, Wk, bk, 0, pk, 1024, 0, 0, 0, 0, 0, 0, 1.f);
    tc_gemm<EPI_POS, 128, 32><<<dim3(8, 4, 1), 256, SM128>>>(rel, Wq, bq, 0, pq, 1024, 0, 0, 0, 0, 0, 0, 1.f);
    // c2p: [z][q][p] = alpha * q[z] @ posk[h]^T    (M=1024, N=512, K=64)
    tc_gemm<EPI_SCALE, 128, 2><<<dim3(4, 8, NBATCH), 256, SM128>>>(
        q, pk, 0, 0, c2p, 64, (size_t)SEQ*DH, (size_t)TWOSPAN*DH, 0, NH,
        (size_t)SEQ*TWOSPAN, TWOSPAN, alpha);
    // p2cT: [z][p][k] = alpha * posq[h] @ k[z]^T   (M=512, N=1024, K=64)
    tc_gemm<EPI_SCALE, 128, 2><<<dim3(8, 4, NBATCH), 256, SM128>>>(
        pq, k, 0, 0, p2cT, 64, (size_t)TWOSPAN*DH, (size_t)SEQ*DH, NH, 0,
        (size_t)TWOSPAN*SEQ, SEQ, alpha);

    // fused attention: scores + masked softmax + P@V
    flash_k<<<dim3(8, NBATCH), 256, SMF>>>(q, k, vt, c2p, p2cT, mask, ctx, alpha);

    // output projection + residual
    tc_gemm<EPI_OUT, 128, 32><<<dim3(8, 32, 1), 256, SM128>>>(ctx, Wo, bo, hidden, out, 1024, 0, 0, 0, 0, 0, 0, 1.f);

    ln_k<<<BDIM * SEQ, 256>>>(out, gamma, beta);
}

// round 9
// speedup vs baseline: 1.2268x; 1.0209x over previous
#include <cuda_runtime.h>
#include <cuda_fp16.h>
#include <math.h>
#include <stdint.h>

#define BDIM 4
#define SEQ 1024
#define DMODEL 1024
#define NH 16
#define DH 64
#define SPAN 256
#define TWOSPAN 512
#define NBATCH (BDIM*NH)   /* 64 */
#define NEGF (-3.402823466e38f)

// ---------------- scratch (device globals; no allocation allowed) ----------
__device__ float  g_q   [(size_t)NBATCH * SEQ * DH];        // [z][s][d]
__device__ float  g_k   [(size_t)NBATCH * SEQ * DH];        // [z][s][d]
__device__ __half g_vt  [(size_t)NBATCH * DH * SEQ];        // [z][d][s] fp16 (transposed V)
__device__ float  g_posk[(size_t)NH * TWOSPAN * DH];        // [h][p][d]
__device__ float  g_posq[(size_t)NH * TWOSPAN * DH];
__device__ __half g_c2p [(size_t)NBATCH * SEQ * TWOSPAN];   // [z][q][p]   fp16, pre-scaled
__device__ __half g_p2cT[(size_t)NBATCH * TWOSPAN * SEQ];   // [z][p][k]   fp16, transposed, pre-scaled
__device__ float  g_ctx [(size_t)BDIM * SEQ * DMODEL];
__device__ int    g_lut [2047];                              // clipped bucket idx per delta

// ================= small helpers ============================================
#define MMA_TF32(d, a, b) \
    asm volatile("mma.sync.aligned.m16n8k8.row.col.f32.tf32.tf32.f32 " \
        "{%0,%1,%2,%3}, {%4,%5,%6,%7}, {%8,%9}, {%0,%1,%2,%3};" \
        : "+f"((d)[0]), "+f"((d)[1]), "+f"((d)[2]), "+f"((d)[3]) \
        : "r"((a)[0]), "r"((a)[1]), "r"((a)[2]), "r"((a)[3]), \
          "r"((b)[0]), "r"((b)[1]))

#define MMA_F16(d, a, b) \
    asm volatile("mma.sync.aligned.m16n8k16.row.col.f32.f16.f16.f32 " \
        "{%0,%1,%2,%3}, {%4,%5,%6,%7}, {%8,%9}, {%0,%1,%2,%3};" \
        : "+f"((d)[0]), "+f"((d)[1]), "+f"((d)[2]), "+f"((d)[3]) \
        : "r"((a)[0]), "r"((a)[1]), "r"((a)[2]), "r"((a)[3]), \
          "r"((b)[0]), "r"((b)[1]))

__device__ __forceinline__ uint32_t pack_h2(float lo, float hi) {
    uint32_t u;
    asm("cvt.rn.f16x2.f32 %0, %1, %2;" : "=r"(u) : "f"(hi), "f"(lo));
    return u;
}
__device__ __forceinline__ void cp16(uint32_t dst, const void* src) {
    asm volatile("cp.async.cg.shared.global [%0], [%1], 16;" :: "r"(dst), "l"(src));
}
#define CP_COMMIT() asm volatile("cp.async.commit_group;" ::: "memory")
#define CP_WAIT(n)  asm volatile("cp.async.wait_group %0;" :: "n"(n) : "memory")

// ================= rel-position bucket LUT ==================================
__device__ __forceinline__ int rel_bucket(int rel) {
    float abs_pos = (rel < 128 && rel > -128) ? 127.0f : fabsf((float)rel);
    if (abs_pos <= 128.0f) return rel;
    float sgn = (rel > 0) ? 1.0f : -1.0f;
    float log_pos = ceilf(logf(abs_pos * (1.0f/128.0f)) / logf(511.0f/128.0f) * 127.0f) + 128.0f;
    return (int)(log_pos * sgn);
}
__global__ void lut_k() {
    int t = blockIdx.x * blockDim.x + threadIdx.x;
    if (t >= 2047) return;
    int b = rel_bucket(t - 1023);
    g_lut[t] = min(max(b + SPAN, 0), TWOSPAN - 1);
}

// ================= unified tf32 mma.sync GEMM (C = A @ B^T + epilogues) =====
#define EPI_HEADS   0
#define EPI_HEADS_T 1
#define EPI_POS     2
#define EPI_SCALE   3
#define EPI_OUT     6

template<int EPI, int BN, int CH>
__global__ void __launch_bounds__(256, 2)
tc_gemm(const float* __restrict__ A, const float* __restrict__ Bm,
        const float* __restrict__ bias, const float* __restrict__ ex1,
        float* __restrict__ C,
        int Ka, size_t sA, size_t sB, int nbModA, int nbModB,
        size_t sC, int ldC, float alpha)
{
    constexpr int NS    = 3;
    constexpr int WN    = BN / 4;
    constexpr int NF    = WN / 8;
    constexpr int BNW   = BN / 32;
    constexpr int AELEM = 128 * 32;
    constexpr int BELEM = BN * 32;

    extern __shared__ uint32_t smem_u[];
    const uint32_t smemU = (uint32_t)__cvta_generic_to_shared(smem_u);

    const int tid  = threadIdx.x;
    const int lane = tid & 31, wid = tid >> 5;
    const int wr = wid & 1, wc = wid >> 1;
    const int rq = lane >> 2, cc = lane & 3;
    const int z  = blockIdx.z;
    const int m0 = blockIdx.y * 128;
    const int n0 = blockIdx.x * BN;

    A  += (size_t)(nbModA ? (z % nbModA) : z) * sA + (size_t)m0 * Ka;
    Bm += (size_t)(nbModB ? (z % nbModB) : z) * sB + (size_t)n0 * Ka;

    float acc[4][NF][4];
    #pragma unroll
    for (int a = 0; a < 4; a++)
        #pragma unroll
        for (int b = 0; b < NF; b++)
            #pragma unroll
            for (int c = 0; c < 4; c++) acc[a][b][c] = 0.0f;

    int aBase[4][2];
    #pragma unroll
    for (int mi = 0; mi < 4; mi++) {
        int r = wr * 64 + mi * 16 + rq;
        aBase[mi][0] = r * 32 + cc;
        aBase[mi][1] = (r + 8) * 32 + cc;
    }
    int bBase[NF];
    #pragma unroll
    for (int ni = 0; ni < NF; ni++)
        bBase[ni] = (wc * WN + ni * 8 + rq) * 32 + cc;

    const int crow = tid >> 3;
    const int ckg  = tid & 7;

    auto issue = [&](int chunk) {
        const int s  = chunk % NS;
        const int k0 = chunk * 32;
        #pragma unroll
        for (int j = 0; j < 4; j++) {
            int row = j * 32 + crow;
            uint32_t dst = smemU + (uint32_t)(s * AELEM + row * 32 + ((ckg ^ (row & 7)) << 2)) * 4u;
            cp16(dst, A + (size_t)row * Ka + k0 + ckg * 4);
        }
        #pragma unroll
        for (int j = 0; j < BNW; j++) {
            int row = j * 32 + crow;
            uint32_t dst = smemU + (uint32_t)(NS * AELEM + s * BELEM + row * 32 + ((ckg ^ (row & 7)) << 2)) * 4u;
            cp16(dst, Bm + (size_t)row * Ka + k0 + ckg * 4);
        }
    };

    #pragma unroll
    for (int c = 0; c < NS - 1; c++) {
        if (c < CH) issue(c);
        CP_COMMIT();
    }

    #pragma unroll 1
    for (int i = 0; i < CH; i++) {
        CP_WAIT(NS - 2);
        __syncthreads();
        if (i + NS - 1 < CH) issue(i + NS - 1);
        CP_COMMIT();

        const uint32_t* as = smem_u + (i % NS) * AELEM;
        const uint32_t* bs = smem_u + NS * AELEM + (i % NS) * BELEM;
        #pragma unroll
        for (int ks = 0; ks < 4; ks++) {
            const int o0 = ((2 * ks) ^ rq) << 2;
            const int o1 = ((2 * ks + 1) ^ rq) << 2;
            uint32_t af[4][4];
            #pragma unroll
            for (int mi = 0; mi < 4; mi++) {
                af[mi][0] = as[aBase[mi][0] + o0];
                af[mi][1] = as[aBase[mi][1] + o0];
                af[mi][2] = as[aBase[mi][0] + o1];
                af[mi][3] = as[aBase[mi][1] + o1];
            }
            uint32_t bf[NF][2];
            #pragma unroll
            for (int ni = 0; ni < NF; ni++) {
                bf[ni][0] = bs[bBase[ni] + o0];
                bf[ni][1] = bs[bBase[ni] + o1];
            }
            #pragma unroll
            for (int mi = 0; mi < 4; mi++)
                #pragma unroll
                for (int ni = 0; ni < NF; ni++)
                    MMA_TF32(acc[mi][ni], af[mi], bf[ni]);
        }
    }
    CP_WAIT(0);
    __syncthreads();

    // ---------------- epilogue: frags -> smem stage -> global ----------------
    float* stage = (float*)smem_u;

    #pragma unroll 1
    for (int cb = 0; cb < BN / 32; cb++) {
        const int n0c = n0 + cb * 32;
        #pragma unroll
        for (int mi = 0; mi < 4; mi++)
            #pragma unroll
            for (int ni = 0; ni < NF; ni++) {
                int gc = wc * WN + ni * 8 + 2 * cc;
                if ((gc >> 5) == cb) {
                    int sc2 = gc & 31;
                    int r0 = wr * 64 + mi * 16 + rq;
                    stage[r0 * 33 + sc2]           = acc[mi][ni][0];
                    stage[r0 * 33 + sc2 + 1]       = acc[mi][ni][1];
                    stage[(r0 + 8) * 33 + sc2]     = acc[mi][ni][2];
                    stage[(r0 + 8) * 33 + sc2 + 1] = acc[mi][ni][3];
                }
            }
        __syncthreads();

        if (EPI == EPI_HEADS_T) {
            // V projection: write fp16 transposed [z][d][s]
            #pragma unroll 1
            for (int j = 0; j < 16; j++) {
                int e = j * 256 + tid;
                int row = e & 127, c = e >> 7;
                int m = m0 + row, n = n0c + c;
                float val = stage[row * 33 + c] + bias[n];
                int b = m >> 10, sq = m & 1023;
                int zz = b * NH + (n >> 6), dd = n & 63;
                ((__half*)C)[((size_t)zz * DH + dd) * SEQ + sq] = __float2half(val);
            }
        } else {
            #pragma unroll 1
            for (int j = 0; j < 16; j++) {
                int e = j * 256 + tid;
                int row = e >> 5, c = e & 31;
                int m = m0 + row, n = n0c + c;
                float val = stage[row * 33 + c];
                if (EPI == EPI_HEADS) {
                    val += bias[n];
                    int b = m >> 10, sq = m & 1023, h = n >> 6, dd = n & 63;
                    C[(((size_t)(b * NH + h)) * SEQ + sq) * DH + dd] = val;
                } else if (EPI == EPI_POS) {
                    val += bias[n];
                    int h = n >> 6, dd = n & 63;
                    C[((size_t)h * TWOSPAN + m) * DH + dd] = val;
                } else if (EPI == EPI_SCALE) {
                    // fp16 table output
                    ((__half*)C)[(size_t)z * sC + (size_t)m * ldC + n] = __float2half(val * alpha);
                } else { // EPI_OUT
                    val += bias[n] + ex1[(size_t)m * DMODEL + n];
                    C[(size_t)m * DMODEL + n] = val;
                }
            }
        }
        __syncthreads();
    }
}

// ================= flash attention: scores+softmax+PV fused =================
// grid (8 q-tiles, 64 z), 256 threads = 8 warps; warp w owns q rows 16w..16w+15.
// smem bytes: Q 32768 | K 2x16384 | V(fp16) 2x8192 | lut 8188  => ~88KB, 2 CTA/SM
__global__ void __launch_bounds__(256, 2)
flash_k(const float* __restrict__ Qg, const float* __restrict__ Kg,
        const __half* __restrict__ Vg, const __half* __restrict__ c2p,
        const __half* __restrict__ p2cT, const int* __restrict__ mask,
        float* __restrict__ ctx, float alpha)
{
    constexpr int QS = 0, KS = 8192;          // float indices
    constexpr int VSB = 65536;                 // byte offset of V region
    extern __shared__ float fsm[];
    int* lut_s = (int*)&fsm[20480];
    char* smc = (char*)fsm;
    const uint32_t smemU = (uint32_t)__cvta_generic_to_shared(fsm);

    const int tid = threadIdx.x, lane = tid & 31, w = tid >> 5;
    const int rq = lane >> 2, cc = lane & 3;
    const int z = blockIdx.y, m0 = blockIdx.x * 128;
    const int b = z >> 4;

    const float*  Qz = Qg + (size_t)z * SEQ * DH;
    const float*  Kz = Kg + (size_t)z * SEQ * DH;
    const __half* Vz = Vg + (size_t)z * DH * SEQ;
    const __half* c2pz = c2p + (size_t)z * SEQ * TWOSPAN;
    const __half* p2cz = p2cT + (size_t)z * TWOSPAN * SEQ;   // [pos][k]
    const int* mz = mask + (size_t)b * SEQ * SEQ;

    for (int t = tid; t < 2047; t += 256) lut_s[t] = g_lut[t];

    // Q tile: 128 x 64 fp32, 2 panels of 32 cols, xor-swizzled
    #pragma unroll
    for (int it = 0; it < 8; it++) {
        int idx = it * 256 + tid;
        int row = idx >> 4, kg = idx & 15;
        int panel = kg >> 3, kg8 = kg & 7;
        uint32_t dst = smemU + (uint32_t)(QS + panel * 4096 + row * 32 + ((kg8 ^ (row & 7)) << 2)) * 4u;
        cp16(dst, Qz + (size_t)(m0 + row) * DH + kg * 4);
    }
    auto issueKV = [&](int t) {
        int s = t & 1, n0 = t * 64;
        #pragma unroll
        for (int it = 0; it < 4; it++) {        // K: 64 rows x 64 fp32
            int idx = it * 256 + tid;
            int row = idx >> 4, kg = idx & 15;
            int panel = kg >> 3, kg8 = kg & 7;
            uint32_t sw = (uint32_t)(((kg8 ^ (row & 7)) << 2) + row * 32 + panel * 2048);
            cp16(smemU + (uint32_t)(KS + s * 4096 + sw) * 4u, Kz + (size_t)(n0 + row) * DH + kg * 4);
        }
        #pragma unroll
        for (int it = 0; it < 2; it++) {        // V: 64 d-rows x 64 fp16
            int idx = it * 256 + tid;
            int row = idx >> 3, kg = idx & 7;
            uint32_t dst = smemU + (uint32_t)(VSB + s * 8192 + row * 128 + ((kg ^ (row & 7)) << 4));
            cp16(dst, Vz + (size_t)row * SEQ + n0 + kg * 8);
        }
    };
    issueKV(0);
    CP_COMMIT();

    float oacc[8][4];
    #pragma unroll
    for (int f = 0; f < 8; f++)
        #pragma unroll
        for (int e = 0; e < 4; e++) oacc[f][e] = 0.0f;
    float mrow[2] = {NEGF, NEGF};
    float lrow[2] = {0.0f, 0.0f};

    const int iA = m0 + 16 * w + rq, iB = iA + 8;
    const __half* c2pA = c2pz + (size_t)iA * TWOSPAN;
    const __half* c2pB = c2pz + (size_t)iB * TWOSPAN;
    const int* mA = mz + (size_t)iA * SEQ;
    const int* mB = mz + (size_t)iB * SEQ;

    #pragma unroll 1
    for (int t = 0; t < 16; t++) {
        const int s = t & 1, n0 = t * 64;
        CP_WAIT(0);
        __syncthreads();
        if (t + 1 < 16) issueKV(t + 1);
        CP_COMMIT();

        // ---- S = Q @ K^T (tf32) ----
        float sacc[8][4];
        #pragma unroll
        for (int f = 0; f < 8; f++)
            #pragma unroll
            for (int e = 0; e < 4; e++) sacc[f][e] = 0.0f;
        #pragma unroll
        for (int ks = 0; ks < 8; ks++) {
            int panel = ks >> 2, kk = ks & 3;
            int o0 = ((2 * kk) ^ rq) << 2, o1 = ((2 * kk + 1) ^ rq) << 2;
            const float* qp = fsm + QS + panel * 4096;
            const float* kp = fsm + KS + s * 4096 + panel * 2048;
            uint32_t af[4];
            af[0] = __float_as_uint(qp[(16 * w + rq) * 32 + cc + o0]);
            af[1] = __float_as_uint(qp[(16 * w + rq + 8) * 32 + cc + o0]);
            af[2] = __float_as_uint(qp[(16 * w + rq) * 32 + cc + o1]);
            af[3] = __float_as_uint(qp[(16 * w + rq + 8) * 32 + cc + o1]);
            #pragma unroll
            for (int f = 0; f < 8; f++) {
                uint32_t bf[2];
                bf[0] = __float_as_uint(kp[(8 * f + rq) * 32 + cc + o0]);
                bf[1] = __float_as_uint(kp[(8 * f + rq) * 32 + cc + o1]);
                MMA_TF32(sacc[f], af, bf);
            }
        }

        // ---- scale + c2p + p2c + mask, row max ----
        float mx0 = NEGF, mx1 = NEGF;
        #pragma unroll
        for (int f = 0; f < 8; f++) {
            int j0 = n0 + 8 * f + 2 * cc;
            int2 mm0 = *(const int2*)&mA[j0];
            int2 mm1 = *(const int2*)&mB[j0];
            float v0 = mm0.x ? sacc[f][0] * alpha + __half2float(c2pA[lut_s[iA - j0 + 1023]])
                               + __half2float(p2cz[(size_t)lut_s[j0 - iA + 1023] * SEQ + j0]) : NEGF;
            float v1 = mm0.y ? sacc[f][1] * alpha + __half2float(c2pA[lut_s[iA - j0 + 1022]])
                               + __half2float(p2cz[(size_t)lut_s[j0 + 1 - iA + 1023] * SEQ + j0 + 1]) : NEGF;
            float v2 = mm1.x ? sacc[f][2] * alpha + __half2float(c2pB[lut_s[iB - j0 + 1023]])
                               + __half2float(p2cz[(size_t)lut_s[j0 - iB + 1023] * SEQ + j0]) : NEGF;
            float v3 = mm1.y ? sacc[f][3] * alpha + __half2float(c2pB[lut_s[iB - j0 + 1022]])
                               + __half2float(p2cz[(size_t)lut_s[j0 + 1 - iB + 1023] * SEQ + j0 + 1]) : NEGF;
            sacc[f][0] = v0; sacc[f][1] = v1; sacc[f][2] = v2; sacc[f][3] = v3;
            mx0 = fmaxf(mx0, fmaxf(v0, v1));
            mx1 = fmaxf(mx1, fmaxf(v2, v3));
        }
        mx0 = fmaxf(mx0, __shfl_xor_sync(0xffffffffu, mx0, 1));
        mx0 = fmaxf(mx0, __shfl_xor_sync(0xffffffffu, mx0, 2));
        mx1 = fmaxf(mx1, __shfl_xor_sync(0xffffffffu, mx1, 1));
        mx1 = fmaxf(mx1, __shfl_xor_sync(0xffffffffu, mx1, 2));
        float mn0 = fmaxf(mrow[0], mx0), mn1 = fmaxf(mrow[1], mx1);
        float sc0 = __expf(mrow[0] - mn0), sc1 = __expf(mrow[1] - mn1);
        mrow[0] = mn0; mrow[1] = mn1;

        // ---- exp, pack P to fp16 A-fragments in-register ----
        float rs0 = 0.0f, rs1 = 0.0f;
        uint32_t ph[8][2];
        #pragma unroll
        for (int f = 0; f < 8; f++) {
            float e0 = __expf(sacc[f][0] - mn0);
            float e1 = __expf(sacc[f][1] - mn0);
            float e2 = __expf(sacc[f][2] - mn1);
            float e3 = __expf(sacc[f][3] - mn1);
            rs0 += e0 + e1; rs1 += e2 + e3;
            // masked entries contribute to denominator (reference) but 0 to PV
            float p0 = (sacc[f][0] == NEGF) ? 0.0f : e0;
            float p1 = (sacc[f][1] == NEGF) ? 0.0f : e1;
            float p2 = (sacc[f][2] == NEGF) ? 0.0f : e2;
            float p3 = (sacc[f][3] == NEGF) ? 0.0f : e3;
            ph[f][0] = pack_h2(p0, p1);   // row rq,   k = 2cc, 2cc+1
            ph[f][1] = pack_h2(p2, p3);   // row rq+8, k = 2cc, 2cc+1
        }
        rs0 += __shfl_xor_sync(0xffffffffu, rs0, 1);
        rs0 += __shfl_xor_sync(0xffffffffu, rs0, 2);
        rs1 += __shfl_xor_sync(0xffffffffu, rs1, 1);
        rs1 += __shfl_xor_sync(0xffffffffu, rs1, 2);
        lrow[0] = lrow[0] * sc0 + rs0;
        lrow[1] = lrow[1] * sc1 + rs1;
        #pragma unroll
        for (int f = 0; f < 8; f++) {
            oacc[f][0] *= sc0; oacc[f][1] *= sc0;
            oacc[f][2] *= sc1; oacc[f][3] *= sc1;
        }

        // ---- O += P @ V (fp16 m16n8k16, P in registers, V fp16 smem) ----
        const char* vp = smc + VSB + s * 8192;
        #pragma unroll
        for (int ks2 = 0; ks2 < 4; ks2++) {
            uint32_t a[4] = { ph[2*ks2][0], ph[2*ks2][1], ph[2*ks2+1][0], ph[2*ks2+1][1] };
            int g0 = (2 * ks2) ^ rq, g1 = (2 * ks2 + 1) ^ rq;
            #pragma unroll
            for (int n = 0; n < 8; n++) {
                int d = 8 * n + rq;
                uint32_t bf[2];
                bf[0] = *(const uint32_t*)(vp + d * 128 + (g0 << 4) + 4 * cc);
                bf[1] = *(const uint32_t*)(vp + d * 128 + (g1 << 4) + 4 * cc);
                MMA_F16(oacc[n], a, bf);
            }
        }
    }

    // ---- write ctx: [b][s][h*64+d] ----
    float inv0 = 1.0f / lrow[0], inv1 = 1.0f / lrow[1];
    int h = z & 15;
    float* crow0 = ctx + ((size_t)b * SEQ + (size_t)(m0 + 16 * w + rq)) * DMODEL + h * DH;
    float* crow1 = crow0 + (size_t)8 * DMODEL;
    #pragma unroll
    for (int f = 0; f < 8; f++) {
        int d0 = 8 * f + 2 * cc;
        float2 a = make_float2(oacc[f][0] * inv0, oacc[f][1] * inv0);
        float2 c = make_float2(oacc[f][2] * inv1, oacc[f][3] * inv1);
        *(float2*)&crow0[d0] = a;
        *(float2*)&crow1[d0] = c;
    }
}

// ================= layernorm ================================================
__device__ __forceinline__ float block_sum(float v, float* sh) {
    #pragma unroll
    for (int o = 16; o; o >>= 1) v += __shfl_xor_sync(0xffffffffu, v, o);
    int lane = threadIdx.x & 31, w = threadIdx.x >> 5;
    __syncthreads();
    if (lane == 0) sh[w] = v;
    __syncthreads();
    if (w == 0) {
        float x = (lane < (blockDim.x >> 5)) ? sh[lane] : 0.0f;
        #pragma unroll
        for (int o = 16; o; o >>= 1) x += __shfl_xor_sync(0xffffffffu, x, o);
        if (lane == 0) sh[0] = x;
    }
    __syncthreads();
    return sh[0];
}
__global__ void ln_k(float* __restrict__ out, const float* __restrict__ gamma,
                     const float* __restrict__ beta) {
    __shared__ float sh[32];
    int row = blockIdx.x, t = threadIdx.x;
    float* p = out + (size_t)row * DMODEL;
    float4 v = *(const float4*)(p + t * 4);
    float mean = block_sum(v.x + v.y + v.z + v.w, sh) * (1.0f / DMODEL);
    float dx = v.x - mean, dy = v.y - mean, dz = v.z - mean, dw = v.w - mean;
    float var = block_sum(dx*dx + dy*dy + dz*dz + dw*dw, sh) * (1.0f / DMODEL);
    float inv = rsqrtf(var + 1e-7f);
    float4 g = *(const float4*)(gamma + t * 4);
    float4 bb = *(const float4*)(beta + t * 4);
    float4 o;
    o.x = dx*inv*g.x + bb.x; o.y = dy*inv*g.y + bb.y;
    o.z = dz*inv*g.z + bb.z; o.w = dw*inv*g.w + bb.w;
    *(float4*)(p + t * 4) = o;
}

// ================= launch ====================================================
extern "C" void kernel_launch(void* const* d_in, const int* in_sizes, int n_in,
                              void* d_out, int out_size) {
    const float* hidden = (const float*)d_in[0];
    const int*   mask   = (const int*)  d_in[1];
    const float* rel    = (const float*)d_in[2];
    const float* Wq     = (const float*)d_in[3];
    const float* bq     = (const float*)d_in[4];
    const float* Wk     = (const float*)d_in[5];
    const float* bk     = (const float*)d_in[6];
    const float* Wv     = (const float*)d_in[7];
    const float* bv     = (const float*)d_in[8];
    const float* Wo     = (const float*)d_in[9];
    const float* bo     = (const float*)d_in[10];
    const float* gamma  = (const float*)d_in[11];
    const float* beta   = (const float*)d_in[12];
    float* out = (float*)d_out;

    float *q, *k, *pk, *pq, *ctx;
    __half *vt, *c2p, *p2cT;
    cudaGetSymbolAddress((void**)&q,    g_q);
    cudaGetSymbolAddress((void**)&k,    g_k);
    cudaGetSymbolAddress((void**)&vt,   g_vt);
    cudaGetSymbolAddress((void**)&pk,   g_posk);
    cudaGetSymbolAddress((void**)&pq,   g_posq);
    cudaGetSymbolAddress((void**)&c2p,  g_c2p);
    cudaGetSymbolAddress((void**)&p2cT, g_p2cT);
    cudaGetSymbolAddress((void**)&ctx,  g_ctx);

    const float alpha = 1.0f / sqrtf((float)(DH * 3));
    const size_t SM128 = (size_t)3 * (128 * 32 + 128 * 32) * 4;   // 98304
    const size_t SMF   = 90112;                                    // Q32K+K32K+V16K+lut

    cudaFuncSetAttribute((const void*)tc_gemm<EPI_HEADS,  128, 32>, cudaFuncAttributeMaxDynamicSharedMemorySize, (int)SM128);
    cudaFuncSetAttribute((const void*)tc_gemm<EPI_HEADS_T,128, 32>, cudaFuncAttributeMaxDynamicSharedMemorySize, (int)SM128);
    cudaFuncSetAttribute((const void*)tc_gemm<EPI_POS,    128, 32>, cudaFuncAttributeMaxDynamicSharedMemorySize, (int)SM128);
    cudaFuncSetAttribute((const void*)tc_gemm<EPI_SCALE,  128,  2>, cudaFuncAttributeMaxDynamicSharedMemorySize, (int)SM128);
    cudaFuncSetAttribute((const void*)tc_gemm<EPI_OUT,    128, 32>, cudaFuncAttributeMaxDynamicSharedMemorySize, (int)SM128);
    cudaFuncSetAttribute((const void*)flash_k, cudaFuncAttributeMaxDynamicSharedMemorySize, (int)SMF);

    lut_k<<<2, 1024>>>();

    // Q, K, V projections (M=4096, N=1024, K=1024)
    tc_gemm<EPI_HEADS,  128, 32><<<dim3(8, 32, 1), 256, SM128>>>(hidden, Wq, bq, 0, q,  1024, 0, 0, 0, 0, 0, 0, 1.f);
    tc_gemm<EPI_HEADS,  128, 32><<<dim3(8, 32, 1), 256, SM128>>>(hidden, Wk, bk, 0, k,  1024, 0, 0, 0, 0, 0, 0, 1.f);
    tc_gemm<EPI_HEADS_T,128, 32><<<dim3(8, 32, 1), 256, SM128>>>(hidden, Wv, bv, 0, (float*)vt, 1024, 0, 0, 0, 0, 0, 0, 1.f);
    // position projections (M=512)
    tc_gemm<EPI_POS, 128, 32><<<dim3(8, 4, 1), 256, SM128>>>(rel, Wk, bk, 0, pk, 1024, 0, 0, 0, 0, 0, 0, 1.f);
    tc_gemm<EPI_POS, 128, 32><<<dim3(8, 4, 1), 256, SM128>>>(rel, Wq, bq, 0, pq, 1024, 0, 0, 0, 0, 0, 0, 1.f);
    // c2p: [z][q][p] = alpha * q[z] @ posk[h]^T    (M=1024, N=512, K=64), fp16 out
    tc_gemm<EPI_SCALE, 128, 2><<<dim3(4, 8, NBATCH), 256, SM128>>>(
        q, pk, 0, 0, (float*)c2p, 64, (size_t)SEQ*DH, (size_t)TWOSPAN*DH, 0, NH,
        (size_t)SEQ*TWOSPAN, TWOSPAN, alpha);
    // p2cT: [z][p][k] = alpha * posq[h] @ k[z]^T   (M=512, N=1024, K=64), fp16 out
    tc_gemm<EPI_SCALE, 128, 2><<<dim3(8, 4, NBATCH), 256, SM128>>>(
        pq, k, 0, 0, (float*)p2cT, 64, (size_t)TWOSPAN*DH, (size_t)SEQ*DH, NH, 0,
        (size_t)TWOSPAN*SEQ, SEQ, alpha);

    // fused attention: scores + masked softmax + P@V
    flash_k<<<dim3(8, NBATCH), 256, SMF>>>(q, k, vt, c2p, p2cT, mask, ctx, alpha);

    // output projection + residual
    tc_gemm<EPI_OUT, 128, 32><<<dim3(8, 32, 1), 256, SM128>>>(ctx, Wo, bo, hidden, out, 1024, 0, 0, 0, 0, 0, 0, 1.f);

    ln_k<<<BDIM * SEQ, 256>>>(out, gamma, beta);
}

// round 10
// speedup vs baseline: 1.2863x; 1.0485x over previous
#include <cuda_runtime.h>
#include <cuda_fp16.h>
#include <math.h>
#include <stdint.h>

#define BDIM 4
#define SEQ 1024
#define DMODEL 1024
#define NH 16
#define DH 64
#define SPAN 256
#define TWOSPAN 512
#define NBATCH (BDIM*NH)   /* 64 */
#define NEGF (-3.402823466e38f)

// ---------------- scratch (device globals; no allocation allowed) ----------
__device__ float  g_q   [(size_t)NBATCH * SEQ * DH];        // [z][s][d] fp32 (for SCALE)
__device__ float  g_k   [(size_t)NBATCH * SEQ * DH];        // [z][s][d] fp32 (for SCALE)
__device__ __half g_qh  [(size_t)NBATCH * SEQ * DH];        // [z][s][d] fp16 (for flash)
__device__ __half g_kh  [(size_t)NBATCH * SEQ * DH];        // [z][s][d] fp16 (for flash)
__device__ __half g_vt  [(size_t)NBATCH * DH * SEQ];        // [z][d][s] fp16 (transposed V)
__device__ float  g_posk[(size_t)NH * TWOSPAN * DH];        // [h][p][d]
__device__ float  g_posq[(size_t)NH * TWOSPAN * DH];
__device__ __half g_c2p [(size_t)NBATCH * SEQ * TWOSPAN];   // [z][q][p]   fp16, pre-scaled
__device__ __half g_p2cT[(size_t)NBATCH * TWOSPAN * SEQ];   // [z][p][k]   fp16, transposed, pre-scaled
__device__ float  g_ctx [(size_t)BDIM * SEQ * DMODEL];
__device__ int    g_lut [2047];                              // clipped bucket idx per delta

// ================= small helpers ============================================
#define MMA_TF32(d, a, b) \
    asm volatile("mma.sync.aligned.m16n8k8.row.col.f32.tf32.tf32.f32 " \
        "{%0,%1,%2,%3}, {%4,%5,%6,%7}, {%8,%9}, {%0,%1,%2,%3};" \
        : "+f"((d)[0]), "+f"((d)[1]), "+f"((d)[2]), "+f"((d)[3]) \
        : "r"((a)[0]), "r"((a)[1]), "r"((a)[2]), "r"((a)[3]), \
          "r"((b)[0]), "r"((b)[1]))

#define MMA_F16(d, a, b) \
    asm volatile("mma.sync.aligned.m16n8k16.row.col.f32.f16.f16.f32 " \
        "{%0,%1,%2,%3}, {%4,%5,%6,%7}, {%8,%9}, {%0,%1,%2,%3};" \
        : "+f"((d)[0]), "+f"((d)[1]), "+f"((d)[2]), "+f"((d)[3]) \
        : "r"((a)[0]), "r"((a)[1]), "r"((a)[2]), "r"((a)[3]), \
          "r"((b)[0]), "r"((b)[1]))

__device__ __forceinline__ uint32_t pack_h2(float lo, float hi) {
    uint32_t u;
    asm("cvt.rn.f16x2.f32 %0, %1, %2;" : "=r"(u) : "f"(hi), "f"(lo));
    return u;
}
__device__ __forceinline__ void cp16(uint32_t dst, const void* src) {
    asm volatile("cp.async.cg.shared.global [%0], [%1], 16;" :: "r"(dst), "l"(src));
}
#define CP_COMMIT() asm volatile("cp.async.commit_group;" ::: "memory")
#define CP_WAIT(n)  asm volatile("cp.async.wait_group %0;" :: "n"(n) : "memory")

// ================= rel-position bucket LUT ==================================
__device__ __forceinline__ int rel_bucket(int rel) {
    float abs_pos = (rel < 128 && rel > -128) ? 127.0f : fabsf((float)rel);
    if (abs_pos <= 128.0f) return rel;
    float sgn = (rel > 0) ? 1.0f : -1.0f;
    float log_pos = ceilf(logf(abs_pos * (1.0f/128.0f)) / logf(511.0f/128.0f) * 127.0f) + 128.0f;
    return (int)(log_pos * sgn);
}
__global__ void lut_k() {
    int t = blockIdx.x * blockDim.x + threadIdx.x;
    if (t >= 2047) return;
    int b = rel_bucket(t - 1023);
    g_lut[t] = min(max(b + SPAN, 0), TWOSPAN - 1);
}

// ================= unified tf32 mma.sync GEMM (C = A @ B^T + epilogues) =====
#define EPI_HEADS   0
#define EPI_HEADS_T 1
#define EPI_POS     2
#define EPI_SCALE   3
#define EPI_OUT     6

template<int EPI, int BN, int CH>
__global__ void __launch_bounds__(256, 2)
tc_gemm(const float* __restrict__ A, const float* __restrict__ Bm,
        const float* __restrict__ bias, const float* __restrict__ ex1,
        float* __restrict__ C, __half* __restrict__ Ch,
        int Ka, size_t sA, size_t sB, int nbModA, int nbModB,
        size_t sC, int ldC, float alpha)
{
    constexpr int NS    = 3;
    constexpr int WN    = BN / 4;
    constexpr int NF    = WN / 8;
    constexpr int BNW   = BN / 32;
    constexpr int AELEM = 128 * 32;
    constexpr int BELEM = BN * 32;

    extern __shared__ uint32_t smem_u[];
    const uint32_t smemU = (uint32_t)__cvta_generic_to_shared(smem_u);

    const int tid  = threadIdx.x;
    const int lane = tid & 31, wid = tid >> 5;
    const int wr = wid & 1, wc = wid >> 1;
    const int rq = lane >> 2, cc = lane & 3;
    const int z  = blockIdx.z;
    const int m0 = blockIdx.y * 128;
    const int n0 = blockIdx.x * BN;

    A  += (size_t)(nbModA ? (z % nbModA) : z) * sA + (size_t)m0 * Ka;
    Bm += (size_t)(nbModB ? (z % nbModB) : z) * sB + (size_t)n0 * Ka;

    float acc[4][NF][4];
    #pragma unroll
    for (int a = 0; a < 4; a++)
        #pragma unroll
        for (int b = 0; b < NF; b++)
            #pragma unroll
            for (int c = 0; c < 4; c++) acc[a][b][c] = 0.0f;

    int aBase[4][2];
    #pragma unroll
    for (int mi = 0; mi < 4; mi++) {
        int r = wr * 64 + mi * 16 + rq;
        aBase[mi][0] = r * 32 + cc;
        aBase[mi][1] = (r + 8) * 32 + cc;
    }
    int bBase[NF];
    #pragma unroll
    for (int ni = 0; ni < NF; ni++)
        bBase[ni] = (wc * WN + ni * 8 + rq) * 32 + cc;

    const int crow = tid >> 3;
    const int ckg  = tid & 7;

    auto issue = [&](int chunk) {
        const int s  = chunk % NS;
        const int k0 = chunk * 32;
        #pragma unroll
        for (int j = 0; j < 4; j++) {
            int row = j * 32 + crow;
            uint32_t dst = smemU + (uint32_t)(s * AELEM + row * 32 + ((ckg ^ (row & 7)) << 2)) * 4u;
            cp16(dst, A + (size_t)row * Ka + k0 + ckg * 4);
        }
        #pragma unroll
        for (int j = 0; j < BNW; j++) {
            int row = j * 32 + crow;
            uint32_t dst = smemU + (uint32_t)(NS * AELEM + s * BELEM + row * 32 + ((ckg ^ (row & 7)) << 2)) * 4u;
            cp16(dst, Bm + (size_t)row * Ka + k0 + ckg * 4);
        }
    };

    #pragma unroll
    for (int c = 0; c < NS - 1; c++) {
        if (c < CH) issue(c);
        CP_COMMIT();
    }

    #pragma unroll 1
    for (int i = 0; i < CH; i++) {
        CP_WAIT(NS - 2);
        __syncthreads();
        if (i + NS - 1 < CH) issue(i + NS - 1);
        CP_COMMIT();

        const uint32_t* as = smem_u + (i % NS) * AELEM;
        const uint32_t* bs = smem_u + NS * AELEM + (i % NS) * BELEM;
        #pragma unroll
        for (int ks = 0; ks < 4; ks++) {
            const int o0 = ((2 * ks) ^ rq) << 2;
            const int o1 = ((2 * ks + 1) ^ rq) << 2;
            uint32_t af[4][4];
            #pragma unroll
            for (int mi = 0; mi < 4; mi++) {
                af[mi][0] = as[aBase[mi][0] + o0];
                af[mi][1] = as[aBase[mi][1] + o0];
                af[mi][2] = as[aBase[mi][0] + o1];
                af[mi][3] = as[aBase[mi][1] + o1];
            }
            uint32_t bf[NF][2];
            #pragma unroll
            for (int ni = 0; ni < NF; ni++) {
                bf[ni][0] = bs[bBase[ni] + o0];
                bf[ni][1] = bs[bBase[ni] + o1];
            }
            #pragma unroll
            for (int mi = 0; mi < 4; mi++)
                #pragma unroll
                for (int ni = 0; ni < NF; ni++)
                    MMA_TF32(acc[mi][ni], af[mi], bf[ni]);
        }
    }
    CP_WAIT(0);
    __syncthreads();

    // ---------------- epilogue: frags -> smem stage -> global ----------------
    float* stage = (float*)smem_u;

    #pragma unroll 1
    for (int cb = 0; cb < BN / 32; cb++) {
        const int n0c = n0 + cb * 32;
        #pragma unroll
        for (int mi = 0; mi < 4; mi++)
            #pragma unroll
            for (int ni = 0; ni < NF; ni++) {
                int gc = wc * WN + ni * 8 + 2 * cc;
                if ((gc >> 5) == cb) {
                    int sc2 = gc & 31;
                    int r0 = wr * 64 + mi * 16 + rq;
                    stage[r0 * 33 + sc2]           = acc[mi][ni][0];
                    stage[r0 * 33 + sc2 + 1]       = acc[mi][ni][1];
                    stage[(r0 + 8) * 33 + sc2]     = acc[mi][ni][2];
                    stage[(r0 + 8) * 33 + sc2 + 1] = acc[mi][ni][3];
                }
            }
        __syncthreads();

        if (EPI == EPI_HEADS_T) {
            // V projection: write fp16 transposed [z][d][s]
            #pragma unroll 1
            for (int j = 0; j < 16; j++) {
                int e = j * 256 + tid;
                int row = e & 127, c = e >> 7;
                int m = m0 + row, n = n0c + c;
                float val = stage[row * 33 + c] + bias[n];
                int b = m >> 10, sq = m & 1023;
                int zz = b * NH + (n >> 6), dd = n & 63;
                Ch[((size_t)zz * DH + dd) * SEQ + sq] = __float2half(val);
            }
        } else {
            #pragma unroll 1
            for (int j = 0; j < 16; j++) {
                int e = j * 256 + tid;
                int row = e >> 5, c = e & 31;
                int m = m0 + row, n = n0c + c;
                float val = stage[row * 33 + c];
                if (EPI == EPI_HEADS) {
                    val += bias[n];
                    int b = m >> 10, sq = m & 1023, h = n >> 6, dd = n & 63;
                    size_t idx = (((size_t)(b * NH + h)) * SEQ + sq) * DH + dd;
                    C[idx] = val;
                    Ch[idx] = __float2half(val);
                } else if (EPI == EPI_POS) {
                    val += bias[n];
                    int h = n >> 6, dd = n & 63;
                    C[((size_t)h * TWOSPAN + m) * DH + dd] = val;
                } else if (EPI == EPI_SCALE) {
                    Ch[(size_t)z * sC + (size_t)m * ldC + n] = __float2half(val * alpha);
                } else { // EPI_OUT
                    val += bias[n] + ex1[(size_t)m * DMODEL + n];
                    C[(size_t)m * DMODEL + n] = val;
                }
            }
        }
        __syncthreads();
    }
}

// ================= flash attention (all-fp16 MMA): S=QK^T, softmax, PV ======
// grid (8 q-tiles, 64 z), 256 threads = 8 warps; warp w owns q rows 16w..16w+15.
// smem bytes: Q 16384 | K 2x8192 | V 2x8192 | lut 8188  => ~57KB, 2 CTA/SM
__global__ void __launch_bounds__(256, 2)
flash_k(const __half* __restrict__ Qg, const __half* __restrict__ Kg,
        const __half* __restrict__ Vg, const __half* __restrict__ c2p,
        const __half* __restrict__ p2cT, const int* __restrict__ mask,
        float* __restrict__ ctx, float alpha)
{
    constexpr int QSB = 0, KSB = 16384, VSB = 32768, LUTB = 49152;
    extern __shared__ float fsm[];
    char* smc = (char*)fsm;
    int* lut_s = (int*)(smc + LUTB);
    const uint32_t smemU = (uint32_t)__cvta_generic_to_shared(fsm);

    const int tid = threadIdx.x, lane = tid & 31, w = tid >> 5;
    const int rq = lane >> 2, cc = lane & 3;
    const int z = blockIdx.y, m0 = blockIdx.x * 128;
    const int b = z >> 4;

    const __half* Qz = Qg + (size_t)z * SEQ * DH;
    const __half* Kz = Kg + (size_t)z * SEQ * DH;
    const __half* Vz = Vg + (size_t)z * DH * SEQ;
    const __half* c2pz = c2p + (size_t)z * SEQ * TWOSPAN;
    const __half* p2cz = p2cT + (size_t)z * TWOSPAN * SEQ;   // [pos][k]
    const int* mz = mask + (size_t)b * SEQ * SEQ;

    for (int t = tid; t < 2047; t += 256) lut_s[t] = g_lut[t];

    // Q tile: 128 rows x 64 fp16 (128B/row), xor-swizzled in 16B units
    #pragma unroll
    for (int it = 0; it < 4; it++) {
        int idx = it * 256 + tid;
        int row = idx >> 3, g = idx & 7;
        uint32_t dst = smemU + (uint32_t)(QSB + row * 128 + ((g ^ (row & 7)) << 4));
        cp16(dst, Qz + (size_t)(m0 + row) * DH + g * 8);
    }
    auto issueKV = [&](int t) {
        int s = t & 1, n0 = t * 64;
        #pragma unroll
        for (int it = 0; it < 2; it++) {        // K: 64 rows x 64 fp16
            int idx = it * 256 + tid;
            int row = idx >> 3, g = idx & 7;
            uint32_t dst = smemU + (uint32_t)(KSB + s * 8192 + row * 128 + ((g ^ (row & 7)) << 4));
            cp16(dst, Kz + (size_t)(n0 + row) * DH + g * 8);
        }
        #pragma unroll
        for (int it = 0; it < 2; it++) {        // V: 64 d-rows x 64 fp16
            int idx = it * 256 + tid;
            int row = idx >> 3, g = idx & 7;
            uint32_t dst = smemU + (uint32_t)(VSB + s * 8192 + row * 128 + ((g ^ (row & 7)) << 4));
            cp16(dst, Vz + (size_t)row * SEQ + n0 + g * 8);
        }
    };
    issueKV(0);
    CP_COMMIT();

    float oacc[8][4];
    #pragma unroll
    for (int f = 0; f < 8; f++)
        #pragma unroll
        for (int e = 0; e < 4; e++) oacc[f][e] = 0.0f;
    float mrow[2] = {NEGF, NEGF};
    float lrow[2] = {0.0f, 0.0f};

    const int iA = m0 + 16 * w + rq, iB = iA + 8;
    const __half* c2pA = c2pz + (size_t)iA * TWOSPAN;
    const __half* c2pB = c2pz + (size_t)iB * TWOSPAN;
    const int* mA = mz + (size_t)iA * SEQ;
    const int* mB = mz + (size_t)iB * SEQ;
    const int rowA = 16 * w + rq, rowB = rowA + 8;

    #pragma unroll 1
    for (int t = 0; t < 16; t++) {
        const int s = t & 1, n0 = t * 64;
        CP_WAIT(0);
        __syncthreads();
        if (t + 1 < 16) issueKV(t + 1);
        CP_COMMIT();

        // ---- S = Q @ K^T (fp16 m16n8k16, 4 k-chunks) ----
        float sacc[8][4];
        #pragma unroll
        for (int f = 0; f < 8; f++)
            #pragma unroll
            for (int e = 0; e < 4; e++) sacc[f][e] = 0.0f;
        const char* kp = smc + KSB + s * 8192;
        #pragma unroll
        for (int kc = 0; kc < 4; kc++) {
            int g0 = 2 * kc, g1 = 2 * kc + 1;
            uint32_t a[4];
            a[0] = *(const uint32_t*)(smc + QSB + rowA * 128 + ((g0 ^ (rowA & 7)) << 4) + 4 * cc);
            a[1] = *(const uint32_t*)(smc + QSB + rowB * 128 + ((g0 ^ (rowB & 7)) << 4) + 4 * cc);
            a[2] = *(const uint32_t*)(smc + QSB + rowA * 128 + ((g1 ^ (rowA & 7)) << 4) + 4 * cc);
            a[3] = *(const uint32_t*)(smc + QSB + rowB * 128 + ((g1 ^ (rowB & 7)) << 4) + 4 * cc);
            #pragma unroll
            for (int f = 0; f < 8; f++) {
                int rk = 8 * f + rq;
                uint32_t bf[2];
                bf[0] = *(const uint32_t*)(kp + rk * 128 + ((g0 ^ (rk & 7)) << 4) + 4 * cc);
                bf[1] = *(const uint32_t*)(kp + rk * 128 + ((g1 ^ (rk & 7)) << 4) + 4 * cc);
                MMA_F16(sacc[f], a, bf);
            }
        }

        // ---- scale + c2p + p2c + mask, row max ----
        float mx0 = NEGF, mx1 = NEGF;
        #pragma unroll
        for (int f = 0; f < 8; f++) {
            int j0 = n0 + 8 * f + 2 * cc;
            int2 mm0 = *(const int2*)&mA[j0];
            int2 mm1 = *(const int2*)&mB[j0];
            float v0 = mm0.x ? sacc[f][0] * alpha + __half2float(c2pA[lut_s[iA - j0 + 1023]])
                               + __half2float(p2cz[(size_t)lut_s[j0 - iA + 1023] * SEQ + j0]) : NEGF;
            float v1 = mm0.y ? sacc[f][1] * alpha + __half2float(c2pA[lut_s[iA - j0 + 1022]])
                               + __half2float(p2cz[(size_t)lut_s[j0 + 1 - iA + 1023] * SEQ + j0 + 1]) : NEGF;
            float v2 = mm1.x ? sacc[f][2] * alpha + __half2float(c2pB[lut_s[iB - j0 + 1023]])
                               + __half2float(p2cz[(size_t)lut_s[j0 - iB + 1023] * SEQ + j0]) : NEGF;
            float v3 = mm1.y ? sacc[f][3] * alpha + __half2float(c2pB[lut_s[iB - j0 + 1022]])
                               + __half2float(p2cz[(size_t)lut_s[j0 + 1 - iB + 1023] * SEQ + j0 + 1]) : NEGF;
            sacc[f][0] = v0; sacc[f][1] = v1; sacc[f][2] = v2; sacc[f][3] = v3;
            mx0 = fmaxf(mx0, fmaxf(v0, v1));
            mx1 = fmaxf(mx1, fmaxf(v2, v3));
        }
        mx0 = fmaxf(mx0, __shfl_xor_sync(0xffffffffu, mx0, 1));
        mx0 = fmaxf(mx0, __shfl_xor_sync(0xffffffffu, mx0, 2));
        mx1 = fmaxf(mx1, __shfl_xor_sync(0xffffffffu, mx1, 1));
        mx1 = fmaxf(mx1, __shfl_xor_sync(0xffffffffu, mx1, 2));
        float mn0 = fmaxf(mrow[0], mx0), mn1 = fmaxf(mrow[1], mx1);
        float sc0 = __expf(mrow[0] - mn0), sc1 = __expf(mrow[1] - mn1);
        mrow[0] = mn0; mrow[1] = mn1;

        // ---- exp, pack P to fp16 A-fragments in-register ----
        float rs0 = 0.0f, rs1 = 0.0f;
        uint32_t ph[8][2];
        #pragma unroll
        for (int f = 0; f < 8; f++) {
            float e0 = __expf(sacc[f][0] - mn0);
            float e1 = __expf(sacc[f][1] - mn0);
            float e2 = __expf(sacc[f][2] - mn1);
            float e3 = __expf(sacc[f][3] - mn1);
            rs0 += e0 + e1; rs1 += e2 + e3;
            // masked entries contribute to denominator (reference) but 0 to PV
            float p0 = (sacc[f][0] == NEGF) ? 0.0f : e0;
            float p1 = (sacc[f][1] == NEGF) ? 0.0f : e1;
            float p2 = (sacc[f][2] == NEGF) ? 0.0f : e2;
            float p3 = (sacc[f][3] == NEGF) ? 0.0f : e3;
            ph[f][0] = pack_h2(p0, p1);   // row rq,   k = 2cc, 2cc+1
            ph[f][1] = pack_h2(p2, p3);   // row rq+8, k = 2cc, 2cc+1
        }
        rs0 += __shfl_xor_sync(0xffffffffu, rs0, 1);
        rs0 += __shfl_xor_sync(0xffffffffu, rs0, 2);
        rs1 += __shfl_xor_sync(0xffffffffu, rs1, 1);
        rs1 += __shfl_xor_sync(0xffffffffu, rs1, 2);
        lrow[0] = lrow[0] * sc0 + rs0;
        lrow[1] = lrow[1] * sc1 + rs1;
        #pragma unroll
        for (int f = 0; f < 8; f++) {
            oacc[f][0] *= sc0; oacc[f][1] *= sc0;
            oacc[f][2] *= sc1; oacc[f][3] *= sc1;
        }

        // ---- O += P @ V (fp16 m16n8k16, P in registers, V fp16 smem) ----
        const char* vp = smc + VSB + s * 8192;
        #pragma unroll
        for (int ks2 = 0; ks2 < 4; ks2++) {
            uint32_t a[4] = { ph[2*ks2][0], ph[2*ks2][1], ph[2*ks2+1][0], ph[2*ks2+1][1] };
            int g0 = (2 * ks2) ^ rq, g1 = (2 * ks2 + 1) ^ rq;
            #pragma unroll
            for (int n = 0; n < 8; n++) {
                int d = 8 * n + rq;
                uint32_t bf[2];
                bf[0] = *(const uint32_t*)(vp + d * 128 + (g0 << 4) + 4 * cc);
                bf[1] = *(const uint32_t*)(vp + d * 128 + (g1 << 4) + 4 * cc);
                MMA_F16(oacc[n], a, bf);
            }
        }
    }

    // ---- write ctx: [b][s][h*64+d] ----
    float inv0 = 1.0f / lrow[0], inv1 = 1.0f / lrow[1];
    int h = z & 15;
    float* crow0 = ctx + ((size_t)b * SEQ + (size_t)(m0 + 16 * w + rq)) * DMODEL + h * DH;
    float* crow1 = crow0 + (size_t)8 * DMODEL;
    #pragma unroll
    for (int f = 0; f < 8; f++) {
        int d0 = 8 * f + 2 * cc;
        float2 a = make_float2(oacc[f][0] * inv0, oacc[f][1] * inv0);
        float2 c = make_float2(oacc[f][2] * inv1, oacc[f][3] * inv1);
        *(float2*)&crow0[d0] = a;
        *(float2*)&crow1[d0] = c;
    }
}

// ================= layernorm ================================================
__device__ __forceinline__ float block_sum(float v, float* sh) {
    #pragma unroll
    for (int o = 16; o; o >>= 1) v += __shfl_xor_sync(0xffffffffu, v, o);
    int lane = threadIdx.x & 31, w = threadIdx.x >> 5;
    __syncthreads();
    if (lane == 0) sh[w] = v;
    __syncthreads();
    if (w == 0) {
        float x = (lane < (blockDim.x >> 5)) ? sh[lane] : 0.0f;
        #pragma unroll
        for (int o = 16; o; o >>= 1) x += __shfl_xor_sync(0xffffffffu, x, o);
        if (lane == 0) sh[0] = x;
    }
    __syncthreads();
    return sh[0];
}
__global__ void ln_k(float* __restrict__ out, const float* __restrict__ gamma,
                     const float* __restrict__ beta) {
    __shared__ float sh[32];
    int row = blockIdx.x, t = threadIdx.x;
    float* p = out + (size_t)row * DMODEL;
    float4 v = *(const float4*)(p + t * 4);
    float mean = block_sum(v.x + v.y + v.z + v.w, sh) * (1.0f / DMODEL);
    float dx = v.x - mean, dy = v.y - mean, dz = v.z - mean, dw = v.w - mean;
    float var = block_sum(dx*dx + dy*dy + dz*dz + dw*dw, sh) * (1.0f / DMODEL);
    float inv = rsqrtf(var + 1e-7f);
    float4 g = *(const float4*)(gamma + t * 4);
    float4 bb = *(const float4*)(beta + t * 4);
    float4 o;
    o.x = dx*inv*g.x + bb.x; o.y = dy*inv*g.y + bb.y;
    o.z = dz*inv*g.z + bb.z; o.w = dw*inv*g.w + bb.w;
    *(float4*)(p + t * 4) = o;
}

// ================= launch ====================================================
extern "C" void kernel_launch(void* const* d_in, const int* in_sizes, int n_in,
                              void* d_out, int out_size) {
    const float* hidden = (const float*)d_in[0];
    const int*   mask   = (const int*)  d_in[1];
    const float* rel    = (const float*)d_in[2];
    const float* Wq     = (const float*)d_in[3];
    const float* bq     = (const float*)d_in[4];
    const float* Wk     = (const float*)d_in[5];
    const float* bk     = (const float*)d_in[6];
    const float* Wv     = (const float*)d_in[7];
    const float* bv     = (const float*)d_in[8];
    const float* Wo     = (const float*)d_in[9];
    const float* bo     = (const float*)d_in[10];
    const float* gamma  = (const float*)d_in[11];
    const float* beta   = (const float*)d_in[12];
    float* out = (float*)d_out;

    float *q, *k, *pk, *pq, *ctx;
    __half *qh, *kh, *vt, *c2p, *p2cT;
    cudaGetSymbolAddress((void**)&q,    g_q);
    cudaGetSymbolAddress((void**)&k,    g_k);
    cudaGetSymbolAddress((void**)&qh,   g_qh);
    cudaGetSymbolAddress((void**)&kh,   g_kh);
    cudaGetSymbolAddress((void**)&vt,   g_vt);
    cudaGetSymbolAddress((void**)&pk,   g_posk);
    cudaGetSymbolAddress((void**)&pq,   g_posq);
    cudaGetSymbolAddress((void**)&c2p,  g_c2p);
    cudaGetSymbolAddress((void**)&p2cT, g_p2cT);
    cudaGetSymbolAddress((void**)&ctx,  g_ctx);

    const float alpha = 1.0f / sqrtf((float)(DH * 3));
    const size_t SM128 = (size_t)3 * (128 * 32 + 128 * 32) * 4;   // 98304
    const size_t SMF   = 57344;                                    // Q16K+K16K+V16K+lut8K

    cudaFuncSetAttribute((const void*)tc_gemm<EPI_HEADS,  128, 32>, cudaFuncAttributeMaxDynamicSharedMemorySize, (int)SM128);
    cudaFuncSetAttribute((const void*)tc_gemm<EPI_HEADS_T,128, 32>, cudaFuncAttributeMaxDynamicSharedMemorySize, (int)SM128);
    cudaFuncSetAttribute((const void*)tc_gemm<EPI_POS,    128, 32>, cudaFuncAttributeMaxDynamicSharedMemorySize, (int)SM128);
    cudaFuncSetAttribute((const void*)tc_gemm<EPI_SCALE,  128,  2>, cudaFuncAttributeMaxDynamicSharedMemorySize, (int)SM128);
    cudaFuncSetAttribute((const void*)tc_gemm<EPI_OUT,    128, 32>, cudaFuncAttributeMaxDynamicSharedMemorySize, (int)SM128);
    cudaFuncSetAttribute((const void*)flash_k, cudaFuncAttributeMaxDynamicSharedMemorySize, (int)SMF);

    lut_k<<<2, 1024>>>();

    // Q, K, V projections (M=4096, N=1024, K=1024); Q/K dual-store fp32+fp16
    tc_gemm<EPI_HEADS,  128, 32><<<dim3(8, 32, 1), 256, SM128>>>(hidden, Wq, bq, 0, q,  qh, 1024, 0, 0, 0, 0, 0, 0, 1.f);
    tc_gemm<EPI_HEADS,  128, 32><<<dim3(8, 32, 1), 256, SM128>>>(hidden, Wk, bk, 0, k,  kh, 1024, 0, 0, 0, 0, 0, 0, 1.f);
    tc_gemm<EPI_HEADS_T,128, 32><<<dim3(8, 32, 1), 256, SM128>>>(hidden, Wv, bv, 0, 0,  vt, 1024, 0, 0, 0, 0, 0, 0, 1.f);
    // position projections (M=512)
    tc_gemm<EPI_POS, 128, 32><<<dim3(8, 4, 1), 256, SM128>>>(rel, Wk, bk, 0, pk, 0, 1024, 0, 0, 0, 0, 0, 0, 1.f);
    tc_gemm<EPI_POS, 128, 32><<<dim3(8, 4, 1), 256, SM128>>>(rel, Wq, bq, 0, pq, 0, 1024, 0, 0, 0, 0, 0, 0, 1.f);
    // c2p: [z][q][p] = alpha * q[z] @ posk[h]^T    (M=1024, N=512, K=64), fp16 out
    tc_gemm<EPI_SCALE, 128, 2><<<dim3(4, 8, NBATCH), 256, SM128>>>(
        q, pk, 0, 0, 0, c2p, 64, (size_t)SEQ*DH, (size_t)TWOSPAN*DH, 0, NH,
        (size_t)SEQ*TWOSPAN, TWOSPAN, alpha);
    // p2cT: [z][p][k] = alpha * posq[h] @ k[z]^T   (M=512, N=1024, K=64), fp16 out
    tc_gemm<EPI_SCALE, 128, 2><<<dim3(8, 4, NBATCH), 256, SM128>>>(
        pq, k, 0, 0, 0, p2cT, 64, (size_t)TWOSPAN*DH, (size_t)SEQ*DH, NH, 0,
        (size_t)TWOSPAN*SEQ, SEQ, alpha);

    // fused attention: scores + masked softmax + P@V (all fp16 MMA)
    flash_k<<<dim3(8, NBATCH), 256, SMF>>>(qh, kh, vt, c2p, p2cT, mask, ctx, alpha);

    // output projection + residual
    tc_gemm<EPI_OUT, 128, 32><<<dim3(8, 32, 1), 256, SM128>>>(ctx, Wo, bo, hidden, out, 0, 1024, 0, 0, 0, 0, 0, 0, 1.f);

    ln_k<<<BDIM * SEQ, 256>>>(out, gamma, beta);
}

// round 11
// speedup vs baseline: 1.6042x; 1.2472x over previous
#include <cuda_runtime.h>
#include <cuda_fp16.h>
#include <math.h>
#include <stdint.h>

#define BDIM 4
#define SEQ 1024
#define DMODEL 1024
#define NH 16
#define DH 64
#define SPAN 256
#define TWOSPAN 512
#define NBATCH (BDIM*NH)   /* 64 */
#define NEGF (-3.402823466e38f)

// ---------------- scratch (device globals; no allocation allowed) ----------
__device__ __half g_hh  [(size_t)BDIM * SEQ * DMODEL];      // hidden fp16
__device__ __half g_wq  [(size_t)DMODEL * DMODEL];
__device__ __half g_wk  [(size_t)DMODEL * DMODEL];
__device__ __half g_wv  [(size_t)DMODEL * DMODEL];
__device__ __half g_wo  [(size_t)DMODEL * DMODEL];
__device__ __half g_relh[(size_t)TWOSPAN * DMODEL];
__device__ __half g_qh  [(size_t)NBATCH * SEQ * DH];        // [z][s][d]
__device__ __half g_kh  [(size_t)NBATCH * SEQ * DH];        // [z][s][d]
__device__ __half g_vt  [(size_t)NBATCH * DH * SEQ];        // [z][d][s]
__device__ __half g_pk  [(size_t)NH * TWOSPAN * DH];        // [h][p][d]
__device__ __half g_pq  [(size_t)NH * TWOSPAN * DH];
__device__ __half g_c2p [(size_t)NBATCH * SEQ * TWOSPAN];   // [z][q][p]  pre-scaled
__device__ __half g_p2cT[(size_t)NBATCH * TWOSPAN * SEQ];   // [z][p][k]  pre-scaled
__device__ __half g_ctx [(size_t)BDIM * SEQ * DMODEL];      // fp16 ctx
__device__ int    g_lut [2047];

// ================= small helpers ============================================
#define MMA_F16(d, a, b) \
    asm volatile("mma.sync.aligned.m16n8k16.row.col.f32.f16.f16.f32 " \
        "{%0,%1,%2,%3}, {%4,%5,%6,%7}, {%8,%9}, {%0,%1,%2,%3};" \
        : "+f"((d)[0]), "+f"((d)[1]), "+f"((d)[2]), "+f"((d)[3]) \
        : "r"((a)[0]), "r"((a)[1]), "r"((a)[2]), "r"((a)[3]), \
          "r"((b)[0]), "r"((b)[1]))

__device__ __forceinline__ uint32_t pack_h2(float lo, float hi) {
    uint32_t u;
    asm("cvt.rn.f16x2.f32 %0, %1, %2;" : "=r"(u) : "f"(hi), "f"(lo));
    return u;
}
__device__ __forceinline__ void cp16(uint32_t dst, const void* src) {
    asm volatile("cp.async.cg.shared.global [%0], [%1], 16;" :: "r"(dst), "l"(src));
}
#define CP_COMMIT() asm volatile("cp.async.commit_group;" ::: "memory")
#define CP_WAIT(n)  asm volatile("cp.async.wait_group %0;" :: "n"(n) : "memory")

// ================= fp32 -> fp16 convert ====================================
__global__ void cvt_k(const float* __restrict__ s, __half* __restrict__ d, int n) {
    int i = (blockIdx.x * blockDim.x + threadIdx.x) << 2;
    if (i >= n) return;
    float4 v = *(const float4*)(s + i);
    uint2 o = make_uint2(pack_h2(v.x, v.y), pack_h2(v.z, v.w));
    *(uint2*)((char*)d + (size_t)i * 2) = o;
}

// ================= rel-position bucket LUT ==================================
__device__ __forceinline__ int rel_bucket(int rel) {
    float abs_pos = (rel < 128 && rel > -128) ? 127.0f : fabsf((float)rel);
    if (abs_pos <= 128.0f) return rel;
    float sgn = (rel > 0) ? 1.0f : -1.0f;
    float log_pos = ceilf(logf(abs_pos * (1.0f/128.0f)) / logf(511.0f/128.0f) * 127.0f) + 128.0f;
    return (int)(log_pos * sgn);
}
__global__ void lut_k() {
    int t = blockIdx.x * blockDim.x + threadIdx.x;
    if (t >= 2047) return;
    int b = rel_bucket(t - 1023);
    g_lut[t] = min(max(b + SPAN, 0), TWOSPAN - 1);
}

// ================= unified fp16 mma.sync GEMM (C = A @ B^T + epilogues) =====
#define EPI_HEADS   0
#define EPI_HEADS_T 1
#define EPI_POS     2
#define EPI_SCALE   3
#define EPI_OUT     6

template<int EPI, int CH>
__global__ void __launch_bounds__(256, 2)
tc_gemm_h(const __half* __restrict__ A, const __half* __restrict__ Bm,
          const float* __restrict__ bias, const float* __restrict__ ex1,
          float* __restrict__ C, __half* __restrict__ Ch,
          int Ka, size_t sA, size_t sB, int nbModA, int nbModB,
          size_t sC, int ldC, float alpha)
{
    constexpr int NS = 3;
    constexpr int TB = 128 * 128;               // 16KB tile stage (128 rows x 128B)

    extern __shared__ char smc[];
    const uint32_t smemU = (uint32_t)__cvta_generic_to_shared(smc);

    const int tid  = threadIdx.x;
    const int lane = tid & 31, wid = tid >> 5;
    const int wr = wid & 1, wc = wid >> 1;       // 2 x 4 warp grid (64 x 32 warp tile)
    const int rq = lane >> 2, cc = lane & 3;
    const int z  = blockIdx.z;
    const int m0 = blockIdx.y * 128;
    const int n0 = blockIdx.x * 128;

    A  += (size_t)(nbModA ? (z % nbModA) : z) * sA + (size_t)m0 * Ka;
    Bm += (size_t)(nbModB ? (z % nbModB) : z) * sB + (size_t)n0 * Ka;

    float acc[4][4][4];
    #pragma unroll
    for (int a = 0; a < 4; a++)
        #pragma unroll
        for (int b = 0; b < 4; b++)
            #pragma unroll
            for (int c = 0; c < 4; c++) acc[a][b][c] = 0.0f;

    const int crow = tid >> 3;                   // 0..31
    const int cg   = tid & 7;                    // 16B group within 128B row

    auto issue = [&](int chunk) {
        const int s  = chunk % NS;
        const int k0 = chunk * 64;               // 64 fp16 per chunk
        #pragma unroll
        for (int j = 0; j < 4; j++) {
            int row = j * 32 + crow;
            cp16(smemU + (uint32_t)(s * TB + row * 128 + ((cg ^ (row & 7)) << 4)),
                 A + (size_t)row * Ka + k0 + cg * 8);
        }
        #pragma unroll
        for (int j = 0; j < 4; j++) {
            int row = j * 32 + crow;
            cp16(smemU + (uint32_t)(NS * TB + s * TB + row * 128 + ((cg ^ (row & 7)) << 4)),
                 Bm + (size_t)row * Ka + k0 + cg * 8);
        }
    };

    #pragma unroll
    for (int c = 0; c < NS - 1; c++) {
        if (c < CH) issue(c);
        CP_COMMIT();
    }

    #pragma unroll 1
    for (int i = 0; i < CH; i++) {
        CP_WAIT(NS - 2);
        __syncthreads();
        if (i + NS - 1 < CH) issue(i + NS - 1);
        CP_COMMIT();

        const char* as = smc + (i % NS) * TB;
        const char* bs = smc + NS * TB + (i % NS) * TB;
        #pragma unroll
        for (int kc = 0; kc < 4; kc++) {
            const int o0 = (((2 * kc)     ^ rq) << 4) + 4 * cc;
            const int o1 = (((2 * kc + 1) ^ rq) << 4) + 4 * cc;
            uint32_t af[4][4];
            #pragma unroll
            for (int mi = 0; mi < 4; mi++) {
                int rA = wr * 64 + mi * 16 + rq;
                af[mi][0] = *(const uint32_t*)(as + rA * 128 + o0);
                af[mi][1] = *(const uint32_t*)(as + (rA + 8) * 128 + o0);
                af[mi][2] = *(const uint32_t*)(as + rA * 128 + o1);
                af[mi][3] = *(const uint32_t*)(as + (rA + 8) * 128 + o1);
            }
            uint32_t bf[4][2];
            #pragma unroll
            for (int ni = 0; ni < 4; ni++) {
                int rn = wc * 32 + ni * 8 + rq;
                bf[ni][0] = *(const uint32_t*)(bs + rn * 128 + o0);
                bf[ni][1] = *(const uint32_t*)(bs + rn * 128 + o1);
            }
            #pragma unroll
            for (int mi = 0; mi < 4; mi++)
                #pragma unroll
                for (int ni = 0; ni < 4; ni++)
                    MMA_F16(acc[mi][ni], af[mi], bf[ni]);
        }
    }
    CP_WAIT(0);
    __syncthreads();

    // ---------------- epilogue: frags -> smem stage -> global ----------------
    float* stage = (float*)smc;                  // 128 x 33 fp32

    #pragma unroll 1
    for (int cb = 0; cb < 4; cb++) {
        const int n0c = n0 + cb * 32;
        #pragma unroll
        for (int mi = 0; mi < 4; mi++)
            #pragma unroll
            for (int ni = 0; ni < 4; ni++) {
                int gc = wc * 32 + ni * 8 + 2 * cc;
                if ((gc >> 5) == cb) {
                    int sc2 = gc & 31;
                    int r0 = wr * 64 + mi * 16 + rq;
                    stage[r0 * 33 + sc2]           = acc[mi][ni][0];
                    stage[r0 * 33 + sc2 + 1]       = acc[mi][ni][1];
                    stage[(r0 + 8) * 33 + sc2]     = acc[mi][ni][2];
                    stage[(r0 + 8) * 33 + sc2 + 1] = acc[mi][ni][3];
                }
            }
        __syncthreads();

        if (EPI == EPI_HEADS_T) {
            #pragma unroll 1
            for (int j = 0; j < 16; j++) {
                int e = j * 256 + tid;
                int row = e & 127, c = e >> 7;
                int m = m0 + row, n = n0c + c;
                float val = stage[row * 33 + c] + bias[n];
                int b = m >> 10, sq = m & 1023;
                int zz = b * NH + (n >> 6), dd = n & 63;
                Ch[((size_t)zz * DH + dd) * SEQ + sq] = __float2half(val);
            }
        } else {
            #pragma unroll 1
            for (int j = 0; j < 16; j++) {
                int e = j * 256 + tid;
                int row = e >> 5, c = e & 31;
                int m = m0 + row, n = n0c + c;
                float val = stage[row * 33 + c];
                if (EPI == EPI_HEADS) {
                    val += bias[n];
                    int b = m >> 10, sq = m & 1023, h = n >> 6, dd = n & 63;
                    Ch[(((size_t)(b * NH + h)) * SEQ + sq) * DH + dd] = __float2half(val);
                } else if (EPI == EPI_POS) {
                    val += bias[n];
                    int h = n >> 6, dd = n & 63;
                    Ch[((size_t)h * TWOSPAN + m) * DH + dd] = __float2half(val);
                } else if (EPI == EPI_SCALE) {
                    Ch[(size_t)z * sC + (size_t)m * ldC + n] = __float2half(val * alpha);
                } else { // EPI_OUT
                    val += bias[n] + ex1[(size_t)m * DMODEL + n];
                    C[(size_t)m * DMODEL + n] = val;
                }
            }
        }
        __syncthreads();
    }
}

// ================= flash attention (all-fp16 MMA): S=QK^T, softmax, PV ======
// grid (8 q-tiles, 64 z), 256 threads = 8 warps; warp w owns q rows 16w..16w+15.
// smem bytes: Q 16384 | K 2x8192 | V 2x8192 | lut 8188  => ~57KB, 2 CTA/SM
__global__ void __launch_bounds__(256, 2)
flash_k(const __half* __restrict__ Qg, const __half* __restrict__ Kg,
        const __half* __restrict__ Vg, const __half* __restrict__ c2p,
        const __half* __restrict__ p2cT, const int* __restrict__ mask,
        __half* __restrict__ ctx, float alpha)
{
    constexpr int QSB = 0, KSB = 16384, VSB = 32768, LUTB = 49152;
    extern __shared__ float fsm[];
    char* smc = (char*)fsm;
    int* lut_s = (int*)(smc + LUTB);
    const uint32_t smemU = (uint32_t)__cvta_generic_to_shared(fsm);

    const int tid = threadIdx.x, lane = tid & 31, w = tid >> 5;
    const int rq = lane >> 2, cc = lane & 3;
    const int z = blockIdx.y, m0 = blockIdx.x * 128;
    const int b = z >> 4;

    const __half* Qz = Qg + (size_t)z * SEQ * DH;
    const __half* Kz = Kg + (size_t)z * SEQ * DH;
    const __half* Vz = Vg + (size_t)z * DH * SEQ;
    const __half* c2pz = c2p + (size_t)z * SEQ * TWOSPAN;
    const __half* p2cz = p2cT + (size_t)z * TWOSPAN * SEQ;
    const int* mz = mask + (size_t)b * SEQ * SEQ;

    for (int t = tid; t < 2047; t += 256) lut_s[t] = g_lut[t];

    #pragma unroll
    for (int it = 0; it < 4; it++) {
        int idx = it * 256 + tid;
        int row = idx >> 3, g = idx & 7;
        cp16(smemU + (uint32_t)(QSB + row * 128 + ((g ^ (row & 7)) << 4)),
             Qz + (size_t)(m0 + row) * DH + g * 8);
    }
    auto issueKV = [&](int t) {
        int s = t & 1, n0 = t * 64;
        #pragma unroll
        for (int it = 0; it < 2; it++) {
            int idx = it * 256 + tid;
            int row = idx >> 3, g = idx & 7;
            cp16(smemU + (uint32_t)(KSB + s * 8192 + row * 128 + ((g ^ (row & 7)) << 4)),
                 Kz + (size_t)(n0 + row) * DH + g * 8);
        }
        #pragma unroll
        for (int it = 0; it < 2; it++) {
            int idx = it * 256 + tid;
            int row = idx >> 3, g = idx & 7;
            cp16(smemU + (uint32_t)(VSB + s * 8192 + row * 128 + ((g ^ (row & 7)) << 4)),
                 Vz + (size_t)row * SEQ + n0 + g * 8);
        }
    };
    issueKV(0);
    CP_COMMIT();

    float oacc[8][4];
    #pragma unroll
    for (int f = 0; f < 8; f++)
        #pragma unroll
        for (int e = 0; e < 4; e++) oacc[f][e] = 0.0f;
    float mrow[2] = {NEGF, NEGF};
    float lrow[2] = {0.0f, 0.0f};

    const int iA = m0 + 16 * w + rq, iB = iA + 8;
    const __half* c2pA = c2pz + (size_t)iA * TWOSPAN;
    const __half* c2pB = c2pz + (size_t)iB * TWOSPAN;
    const int* mA = mz + (size_t)iA * SEQ;
    const int* mB = mz + (size_t)iB * SEQ;
    const int rowA = 16 * w + rq, rowB = rowA + 8;

    #pragma unroll 1
    for (int t = 0; t < 16; t++) {
        const int s = t & 1, n0 = t * 64;
        CP_WAIT(0);
        __syncthreads();
        if (t + 1 < 16) issueKV(t + 1);
        CP_COMMIT();

        // ---- S = Q @ K^T (fp16 m16n8k16, 4 k-chunks) ----
        float sacc[8][4];
        #pragma unroll
        for (int f = 0; f < 8; f++)
            #pragma unroll
            for (int e = 0; e < 4; e++) sacc[f][e] = 0.0f;
        const char* kp = smc + KSB + s * 8192;
        #pragma unroll
        for (int kc = 0; kc < 4; kc++) {
            int g0 = 2 * kc, g1 = 2 * kc + 1;
            uint32_t a[4];
            a[0] = *(const uint32_t*)(smc + QSB + rowA * 128 + ((g0 ^ (rowA & 7)) << 4) + 4 * cc);
            a[1] = *(const uint32_t*)(smc + QSB + rowB * 128 + ((g0 ^ (rowB & 7)) << 4) + 4 * cc);
            a[2] = *(const uint32_t*)(smc + QSB + rowA * 128 + ((g1 ^ (rowA & 7)) << 4) + 4 * cc);
            a[3] = *(const uint32_t*)(smc + QSB + rowB * 128 + ((g1 ^ (rowB & 7)) << 4) + 4 * cc);
            #pragma unroll
            for (int f = 0; f < 8; f++) {
                int rk = 8 * f + rq;
                uint32_t bf[2];
                bf[0] = *(const uint32_t*)(kp + rk * 128 + ((g0 ^ (rk & 7)) << 4) + 4 * cc);
                bf[1] = *(const uint32_t*)(kp + rk * 128 + ((g1 ^ (rk & 7)) << 4) + 4 * cc);
                MMA_F16(sacc[f], a, bf);
            }
        }

        // ---- scale + c2p + p2c + mask, row max ----
        float mx0 = NEGF, mx1 = NEGF;
        #pragma unroll
        for (int f = 0; f < 8; f++) {
            int j0 = n0 + 8 * f + 2 * cc;
            int2 mm0 = *(const int2*)&mA[j0];
            int2 mm1 = *(const int2*)&mB[j0];
            float v0 = mm0.x ? sacc[f][0] * alpha + __half2float(c2pA[lut_s[iA - j0 + 1023]])
                               + __half2float(p2cz[(size_t)lut_s[j0 - iA + 1023] * SEQ + j0]) : NEGF;
            float v1 = mm0.y ? sacc[f][1] * alpha + __half2float(c2pA[lut_s[iA - j0 + 1022]])
                               + __half2float(p2cz[(size_t)lut_s[j0 + 1 - iA + 1023] * SEQ + j0 + 1]) : NEGF;
            float v2 = mm1.x ? sacc[f][2] * alpha + __half2float(c2pB[lut_s[iB - j0 + 1023]])
                               + __half2float(p2cz[(size_t)lut_s[j0 - iB + 1023] * SEQ + j0]) : NEGF;
            float v3 = mm1.y ? sacc[f][3] * alpha + __half2float(c2pB[lut_s[iB - j0 + 1022]])
                               + __half2float(p2cz[(size_t)lut_s[j0 + 1 - iB + 1023] * SEQ + j0 + 1]) : NEGF;
            sacc[f][0] = v0; sacc[f][1] = v1; sacc[f][2] = v2; sacc[f][3] = v3;
            mx0 = fmaxf(mx0, fmaxf(v0, v1));
            mx1 = fmaxf(mx1, fmaxf(v2, v3));
        }
        mx0 = fmaxf(mx0, __shfl_xor_sync(0xffffffffu, mx0, 1));
        mx0 = fmaxf(mx0, __shfl_xor_sync(0xffffffffu, mx0, 2));
        mx1 = fmaxf(mx1, __shfl_xor_sync(0xffffffffu, mx1, 1));
        mx1 = fmaxf(mx1, __shfl_xor_sync(0xffffffffu, mx1, 2));
        float mn0 = fmaxf(mrow[0], mx0), mn1 = fmaxf(mrow[1], mx1);
        float sc0 = __expf(mrow[0] - mn0), sc1 = __expf(mrow[1] - mn1);
        mrow[0] = mn0; mrow[1] = mn1;

        // ---- exp, pack P to fp16 A-fragments in-register ----
        float rs0 = 0.0f, rs1 = 0.0f;
        uint32_t ph[8][2];
        #pragma unroll
        for (int f = 0; f < 8; f++) {
            float e0 = __expf(sacc[f][0] - mn0);
            float e1 = __expf(sacc[f][1] - mn0);
            float e2 = __expf(sacc[f][2] - mn1);
            float e3 = __expf(sacc[f][3] - mn1);
            rs0 += e0 + e1; rs1 += e2 + e3;
            float p0 = (sacc[f][0] == NEGF) ? 0.0f : e0;
            float p1 = (sacc[f][1] == NEGF) ? 0.0f : e1;
            float p2 = (sacc[f][2] == NEGF) ? 0.0f : e2;
            float p3 = (sacc[f][3] == NEGF) ? 0.0f : e3;
            ph[f][0] = pack_h2(p0, p1);
            ph[f][1] = pack_h2(p2, p3);
        }
        rs0 += __shfl_xor_sync(0xffffffffu, rs0, 1);
        rs0 += __shfl_xor_sync(0xffffffffu, rs0, 2);
        rs1 += __shfl_xor_sync(0xffffffffu, rs1, 1);
        rs1 += __shfl_xor_sync(0xffffffffu, rs1, 2);
        lrow[0] = lrow[0] * sc0 + rs0;
        lrow[1] = lrow[1] * sc1 + rs1;
        #pragma unroll
        for (int f = 0; f < 8; f++) {
            oacc[f][0] *= sc0; oacc[f][1] *= sc0;
            oacc[f][2] *= sc1; oacc[f][3] *= sc1;
        }

        // ---- O += P @ V (fp16 m16n8k16, P in registers, V fp16 smem) ----
        const char* vp = smc + VSB + s * 8192;
        #pragma unroll
        for (int ks2 = 0; ks2 < 4; ks2++) {
            uint32_t a[4] = { ph[2*ks2][0], ph[2*ks2][1], ph[2*ks2+1][0], ph[2*ks2+1][1] };
            int g0 = (2 * ks2) ^ rq, g1 = (2 * ks2 + 1) ^ rq;
            #pragma unroll
            for (int n = 0; n < 8; n++) {
                int d = 8 * n + rq;
                uint32_t bf[2];
                bf[0] = *(const uint32_t*)(vp + d * 128 + (g0 << 4) + 4 * cc);
                bf[1] = *(const uint32_t*)(vp + d * 128 + (g1 << 4) + 4 * cc);
                MMA_F16(oacc[n], a, bf);
            }
        }
    }

    // ---- write ctx (fp16): [b][s][h*64+d] ----
    float inv0 = 1.0f / lrow[0], inv1 = 1.0f / lrow[1];
    int h = z & 15;
    __half* crow0 = ctx + ((size_t)b * SEQ + (size_t)(m0 + 16 * w + rq)) * DMODEL + h * DH;
    __half* crow1 = crow0 + (size_t)8 * DMODEL;
    #pragma unroll
    for (int f = 0; f < 8; f++) {
        int d0 = 8 * f + 2 * cc;
        *(uint32_t*)&crow0[d0] = pack_h2(oacc[f][0] * inv0, oacc[f][1] * inv0);
        *(uint32_t*)&crow1[d0] = pack_h2(oacc[f][2] * inv1, oacc[f][3] * inv1);
    }
}

// ================= layernorm ================================================
__device__ __forceinline__ float block_sum(float v, float* sh) {
    #pragma unroll
    for (int o = 16; o; o >>= 1) v += __shfl_xor_sync(0xffffffffu, v, o);
    int lane = threadIdx.x & 31, w = threadIdx.x >> 5;
    __syncthreads();
    if (lane == 0) sh[w] = v;
    __syncthreads();
    if (w == 0) {
        float x = (lane < (blockDim.x >> 5)) ? sh[lane] : 0.0f;
        #pragma unroll
        for (int o = 16; o; o >>= 1) x += __shfl_xor_sync(0xffffffffu, x, o);
        if (lane == 0) sh[0] = x;
    }
    __syncthreads();
    return sh[0];
}
__global__ void ln_k(float* __restrict__ out, const float* __restrict__ gamma,
                     const float* __restrict__ beta) {
    __shared__ float sh[32];
    int row = blockIdx.x, t = threadIdx.x;
    float* p = out + (size_t)row * DMODEL;
    float4 v = *(const float4*)(p + t * 4);
    float mean = block_sum(v.x + v.y + v.z + v.w, sh) * (1.0f / DMODEL);
    float dx = v.x - mean, dy = v.y - mean, dz = v.z - mean, dw = v.w - mean;
    float var = block_sum(dx*dx + dy*dy + dz*dz + dw*dw, sh) * (1.0f / DMODEL);
    float inv = rsqrtf(var + 1e-7f);
    float4 g = *(const float4*)(gamma + t * 4);
    float4 bb = *(const float4*)(beta + t * 4);
    float4 o;
    o.x = dx*inv*g.x + bb.x; o.y = dy*inv*g.y + bb.y;
    o.z = dz*inv*g.z + bb.z; o.w = dw*inv*g.w + bb.w;
    *(float4*)(p + t * 4) = o;
}

// ================= launch ====================================================
extern "C" void kernel_launch(void* const* d_in, const int* in_sizes, int n_in,
                              void* d_out, int out_size) {
    const float* hidden = (const float*)d_in[0];
    const int*   mask   = (const int*)  d_in[1];
    const float* rel    = (const float*)d_in[2];
    const float* Wq     = (const float*)d_in[3];
    const float* bq     = (const float*)d_in[4];
    const float* Wk     = (const float*)d_in[5];
    const float* bk     = (const float*)d_in[6];
    const float* Wv     = (const float*)d_in[7];
    const float* bv     = (const float*)d_in[8];
    const float* Wo     = (const float*)d_in[9];
    const float* bo     = (const float*)d_in[10];
    const float* gamma  = (const float*)d_in[11];
    const float* beta   = (const float*)d_in[12];
    float* out = (float*)d_out;

    __half *hh, *wq, *wk, *wv, *wo, *relh, *qh, *kh, *vt, *pk, *pq, *c2p, *p2cT, *ctx;
    cudaGetSymbolAddress((void**)&hh,   g_hh);
    cudaGetSymbolAddress((void**)&wq,   g_wq);
    cudaGetSymbolAddress((void**)&wk,   g_wk);
    cudaGetSymbolAddress((void**)&wv,   g_wv);
    cudaGetSymbolAddress((void**)&wo,   g_wo);
    cudaGetSymbolAddress((void**)&relh, g_relh);
    cudaGetSymbolAddress((void**)&qh,   g_qh);
    cudaGetSymbolAddress((void**)&kh,   g_kh);
    cudaGetSymbolAddress((void**)&vt,   g_vt);
    cudaGetSymbolAddress((void**)&pk,   g_pk);
    cudaGetSymbolAddress((void**)&pq,   g_pq);
    cudaGetSymbolAddress((void**)&c2p,  g_c2p);
    cudaGetSymbolAddress((void**)&p2cT, g_p2cT);
    cudaGetSymbolAddress((void**)&ctx,  g_ctx);

    const float alpha = 1.0f / sqrtf((float)(DH * 3));
    const size_t SMG = 98304;     // 6 x 16KB stages
    const size_t SMF = 57344;     // Q16K + K16K + V16K + lut8K

    cudaFuncSetAttribute((const void*)tc_gemm_h<EPI_HEADS,  16>, cudaFuncAttributeMaxDynamicSharedMemorySize, (int)SMG);
    cudaFuncSetAttribute((const void*)tc_gemm_h<EPI_HEADS_T,16>, cudaFuncAttributeMaxDynamicSharedMemorySize, (int)SMG);
    cudaFuncSetAttribute((const void*)tc_gemm_h<EPI_POS,    16>, cudaFuncAttributeMaxDynamicSharedMemorySize, (int)SMG);
    cudaFuncSetAttribute((const void*)tc_gemm_h<EPI_SCALE,   1>, cudaFuncAttributeMaxDynamicSharedMemorySize, (int)SMG);
    cudaFuncSetAttribute((const void*)tc_gemm_h<EPI_OUT,    16>, cudaFuncAttributeMaxDynamicSharedMemorySize, (int)SMG);
    cudaFuncSetAttribute((const void*)flash_k, cudaFuncAttributeMaxDynamicSharedMemorySize, (int)SMF);

    lut_k<<<2, 1024>>>();
    // fp32 -> fp16 conversions
    cvt_k<<<4096, 256>>>(hidden, hh,   BDIM * SEQ * DMODEL);
    cvt_k<<<1024, 256>>>(Wq,     wq,   DMODEL * DMODEL);
    cvt_k<<<1024, 256>>>(Wk,     wk,   DMODEL * DMODEL);
    cvt_k<<<1024, 256>>>(Wv,     wv,   DMODEL * DMODEL);
    cvt_k<<<1024, 256>>>(Wo,     wo,   DMODEL * DMODEL);
    cvt_k<<<512,  256>>>(rel,    relh, TWOSPAN * DMODEL);

    // Q, K, V projections (M=4096, N=1024, K=1024)
    tc_gemm_h<EPI_HEADS,  16><<<dim3(8, 32, 1), 256, SMG>>>(hh, wq, bq, 0, 0, qh, 1024, 0, 0, 0, 0, 0, 0, 1.f);
    tc_gemm_h<EPI_HEADS,  16><<<dim3(8, 32, 1), 256, SMG>>>(hh, wk, bk, 0, 0, kh, 1024, 0, 0, 0, 0, 0, 0, 1.f);
    tc_gemm_h<EPI_HEADS_T,16><<<dim3(8, 32, 1), 256, SMG>>>(hh, wv, bv, 0, 0, vt, 1024, 0, 0, 0, 0, 0, 0, 1.f);
    // position projections (M=512)
    tc_gemm_h<EPI_POS, 16><<<dim3(8, 4, 1), 256, SMG>>>(relh, wk, bk, 0, 0, pk, 1024, 0, 0, 0, 0, 0, 0, 1.f);
    tc_gemm_h<EPI_POS, 16><<<dim3(8, 4, 1), 256, SMG>>>(relh, wq, bq, 0, 0, pq, 1024, 0, 0, 0, 0, 0, 0, 1.f);
    // c2p: [z][q][p] = alpha * qh[z] @ pk[h]^T    (M=1024, N=512, K=64)
    tc_gemm_h<EPI_SCALE, 1><<<dim3(4, 8, NBATCH), 256, SMG>>>(
        qh, pk, 0, 0, 0, c2p, 64, (size_t)SEQ*DH, (size_t)TWOSPAN*DH, 0, NH,
        (size_t)SEQ*TWOSPAN, TWOSPAN, alpha);
    // p2cT: [z][p][k] = alpha * pq[h] @ kh[z]^T   (M=512, N=1024, K=64)
    tc_gemm_h<EPI_SCALE, 1><<<dim3(8, 4, NBATCH), 256, SMG>>>(
        pq, kh, 0, 0, 0, p2cT, 64, (size_t)TWOSPAN*DH, (size_t)SEQ*DH, NH, 0,
        (size_t)TWOSPAN*SEQ, SEQ, alpha);

    // fused attention: scores + masked softmax + P@V (all fp16 MMA)
    flash_k<<<dim3(8, NBATCH), 256, SMF>>>(qh, kh, vt, c2p, p2cT, mask, ctx, alpha);

    // output projection + residual (ctx fp16 @ Wo fp16 + hidden fp32)
    tc_gemm_h<EPI_OUT, 16><<<dim3(8, 32, 1), 256, SMG>>>(ctx, wo, bo, hidden, out, 0, 1024, 0, 0, 0, 0, 0, 0, 1.f);

    ln_k<<<BDIM * SEQ, 256>>>(out, gamma, beta);
}

// round 12
// speedup vs baseline: 1.6925x; 1.0551x over previous
#include <cuda_runtime.h>
#include <cuda_fp16.h>
#include <math.h>
#include <stdint.h>

#define BDIM 4
#define SEQ 1024
#define DMODEL 1024
#define NH 16
#define DH 64
#define SPAN 256
#define TWOSPAN 512
#define NBATCH (BDIM*NH)   /* 64 */
#define NEGF (-3.402823466e38f)
#define QKOFF ((size_t)NBATCH * SEQ * DH)

// ---------------- scratch (device globals; no allocation allowed) ----------
__device__ __half    g_hh   [(size_t)BDIM * SEQ * DMODEL];     // hidden fp16
__device__ __half    g_wqkv [(size_t)3 * DMODEL * DMODEL];     // packed Wq|Wk|Wv fp16
__device__ float     g_bqkv [3 * DMODEL];                       // packed bq|bk|bv
__device__ __half    g_wo   [(size_t)DMODEL * DMODEL];
__device__ __half    g_relh [(size_t)TWOSPAN * DMODEL];
__device__ __half    g_qkh  [(size_t)2 * NBATCH * SEQ * DH];   // qh | kh
__device__ __half    g_vt   [(size_t)NBATCH * DH * SEQ];       // [z][d][s]
__device__ __half    g_pk   [(size_t)NH * TWOSPAN * DH];
__device__ __half    g_pq   [(size_t)NH * TWOSPAN * DH];
__device__ __half    g_c2p  [(size_t)NBATCH * SEQ * TWOSPAN];  // pre-scaled
__device__ __half    g_p2cT [(size_t)NBATCH * TWOSPAN * SEQ];  // transposed, pre-scaled
__device__ __half    g_ctx  [(size_t)BDIM * SEQ * DMODEL];
__device__ uint32_t  g_mbits[(size_t)BDIM * SEQ * 32];          // packed mask bits
__device__ int       g_lut  [2047];

// ================= small helpers ============================================
#define MMA_F16(d, a, b) \
    asm volatile("mma.sync.aligned.m16n8k16.row.col.f32.f16.f16.f32 " \
        "{%0,%1,%2,%3}, {%4,%5,%6,%7}, {%8,%9}, {%0,%1,%2,%3};" \
        : "+f"((d)[0]), "+f"((d)[1]), "+f"((d)[2]), "+f"((d)[3]) \
        : "r"((a)[0]), "r"((a)[1]), "r"((a)[2]), "r"((a)[3]), \
          "r"((b)[0]), "r"((b)[1]))

__device__ __forceinline__ uint32_t pack_h2(float lo, float hi) {
    uint32_t u;
    asm("cvt.rn.f16x2.f32 %0, %1, %2;" : "=r"(u) : "f"(hi), "f"(lo));
    return u;
}
__device__ __forceinline__ void cp16(uint32_t dst, const void* src) {
    asm volatile("cp.async.cg.shared.global [%0], [%1], 16;" :: "r"(dst), "l"(src));
}
#define CP_COMMIT() asm volatile("cp.async.commit_group;" ::: "memory")
#define CP_WAIT(n)  asm volatile("cp.async.wait_group %0;" :: "n"(n) : "memory")

// ================= prep kernels =============================================
__global__ void cvt_k(const float* __restrict__ s, __half* __restrict__ d, int n) {
    int i = (blockIdx.x * blockDim.x + threadIdx.x) << 2;
    if (i >= n) return;
    float4 v = *(const float4*)(s + i);
    uint2 o = make_uint2(pack_h2(v.x, v.y), pack_h2(v.z, v.w));
    *(uint2*)((char*)d + (size_t)i * 2) = o;
}
__global__ void bias3_k(const float* __restrict__ a, const float* __restrict__ b,
                        const float* __restrict__ c, float* __restrict__ d) {
    int t = blockIdx.x * blockDim.x + threadIdx.x;
    if (t < DMODEL) { d[t] = a[t]; d[DMODEL + t] = b[t]; d[2 * DMODEL + t] = c[t]; }
}
__global__ void maskpack_k(const int* __restrict__ m, uint32_t* __restrict__ bm) {
    int idx = blockIdx.x * blockDim.x + threadIdx.x;   // 131072 words
    const int4* src = (const int4*)(m + (size_t)idx * 32);
    uint32_t v = 0;
    #pragma unroll
    for (int g = 0; g < 8; g++) {
        int4 x = src[g];
        v |= (x.x ? 1u : 0u) << (4 * g);
        v |= (x.y ? 1u : 0u) << (4 * g + 1);
        v |= (x.z ? 1u : 0u) << (4 * g + 2);
        v |= (x.w ? 1u : 0u) << (4 * g + 3);
    }
    bm[idx] = v;
}
__device__ __forceinline__ int rel_bucket(int rel) {
    float abs_pos = (rel < 128 && rel > -128) ? 127.0f : fabsf((float)rel);
    if (abs_pos <= 128.0f) return rel;
    float sgn = (rel > 0) ? 1.0f : -1.0f;
    float log_pos = ceilf(logf(abs_pos * (1.0f/128.0f)) / logf(511.0f/128.0f) * 127.0f) + 128.0f;
    return (int)(log_pos * sgn);
}
__global__ void lut_k() {
    int t = blockIdx.x * blockDim.x + threadIdx.x;
    if (t >= 2047) return;
    int b = rel_bucket(t - 1023);
    g_lut[t] = min(max(b + SPAN, 0), TWOSPAN - 1);
}

// ================= unified fp16 mma.sync GEMM (C = A @ B^T + epilogues) =====
#define EPI_HEADS   0
#define EPI_HEADS_T 1
#define EPI_POS     2
#define EPI_SCALE   3
#define EPI_OUT     6
#define EPI_QKV     7

template<int EPI, int CH>
__global__ void __launch_bounds__(256, 2)
tc_gemm_h(const __half* __restrict__ A, const __half* __restrict__ Bm,
          const float* __restrict__ bias, const float* __restrict__ ex1,
          float* __restrict__ C, __half* __restrict__ Ch,
          int Ka, size_t sA, size_t sB, int nbModA, int nbModB,
          size_t sC, int ldC, float alpha)
{
    constexpr int NS = 3;
    constexpr int TB = 128 * 128;

    extern __shared__ char smc[];
    const uint32_t smemU = (uint32_t)__cvta_generic_to_shared(smc);

    const int tid  = threadIdx.x;
    const int lane = tid & 31, wid = tid >> 5;
    const int wr = wid & 1, wc = wid >> 1;
    const int rq = lane >> 2, cc = lane & 3;
    const int z  = blockIdx.z;
    const int m0 = blockIdx.y * 128;
    const int n0 = blockIdx.x * 128;

    A  += (nbModA ? (size_t)(z % nbModA) : (size_t)z) * sA + (size_t)m0 * Ka;
    Bm += (nbModB ? (size_t)(z % nbModB) : (size_t)z) * sB + (size_t)n0 * Ka;

    float acc[4][4][4];
    #pragma unroll
    for (int a = 0; a < 4; a++)
        #pragma unroll
        for (int b = 0; b < 4; b++)
            #pragma unroll
            for (int c = 0; c < 4; c++) acc[a][b][c] = 0.0f;

    const int crow = tid >> 3;
    const int cg   = tid & 7;

    auto issue = [&](int chunk) {
        const int s  = chunk % NS;
        const int k0 = chunk * 64;
        #pragma unroll
        for (int j = 0; j < 4; j++) {
            int row = j * 32 + crow;
            cp16(smemU + (uint32_t)(s * TB + row * 128 + ((cg ^ (row & 7)) << 4)),
                 A + (size_t)row * Ka + k0 + cg * 8);
        }
        #pragma unroll
        for (int j = 0; j < 4; j++) {
            int row = j * 32 + crow;
            cp16(smemU + (uint32_t)(NS * TB + s * TB + row * 128 + ((cg ^ (row & 7)) << 4)),
                 Bm + (size_t)row * Ka + k0 + cg * 8);
        }
    };

    #pragma unroll
    for (int c = 0; c < NS - 1; c++) {
        if (c < CH) issue(c);
        CP_COMMIT();
    }

    #pragma unroll 1
    for (int i = 0; i < CH; i++) {
        CP_WAIT(NS - 2);
        __syncthreads();
        if (i + NS - 1 < CH) issue(i + NS - 1);
        CP_COMMIT();

        const char* as = smc + (i % NS) * TB;
        const char* bs = smc + NS * TB + (i % NS) * TB;
        #pragma unroll
        for (int kc = 0; kc < 4; kc++) {
            const int o0 = (((2 * kc)     ^ rq) << 4) + 4 * cc;
            const int o1 = (((2 * kc + 1) ^ rq) << 4) + 4 * cc;
            uint32_t af[4][4];
            #pragma unroll
            for (int mi = 0; mi < 4; mi++) {
                int rA = wr * 64 + mi * 16 + rq;
                af[mi][0] = *(const uint32_t*)(as + rA * 128 + o0);
                af[mi][1] = *(const uint32_t*)(as + (rA + 8) * 128 + o0);
                af[mi][2] = *(const uint32_t*)(as + rA * 128 + o1);
                af[mi][3] = *(const uint32_t*)(as + (rA + 8) * 128 + o1);
            }
            uint32_t bf[4][2];
            #pragma unroll
            for (int ni = 0; ni < 4; ni++) {
                int rn = wc * 32 + ni * 8 + rq;
                bf[ni][0] = *(const uint32_t*)(bs + rn * 128 + o0);
                bf[ni][1] = *(const uint32_t*)(bs + rn * 128 + o1);
            }
            #pragma unroll
            for (int mi = 0; mi < 4; mi++)
                #pragma unroll
                for (int ni = 0; ni < 4; ni++)
                    MMA_F16(acc[mi][ni], af[mi], bf[ni]);
        }
    }
    CP_WAIT(0);
    __syncthreads();

    // ---------------- epilogue: frags -> smem stage -> global ----------------
    float* stage = (float*)smc;
    const int boff = (EPI == EPI_QKV) ? z * DMODEL : 0;
    const bool transT = (EPI == EPI_HEADS_T) || (EPI == EPI_QKV && z == 2);

    #pragma unroll 1
    for (int cb = 0; cb < 4; cb++) {
        const int n0c = n0 + cb * 32;
        #pragma unroll
        for (int mi = 0; mi < 4; mi++)
            #pragma unroll
            for (int ni = 0; ni < 4; ni++) {
                int gc = wc * 32 + ni * 8 + 2 * cc;
                if ((gc >> 5) == cb) {
                    int sc2 = gc & 31;
                    int r0 = wr * 64 + mi * 16 + rq;
                    stage[r0 * 33 + sc2]           = acc[mi][ni][0];
                    stage[r0 * 33 + sc2 + 1]       = acc[mi][ni][1];
                    stage[(r0 + 8) * 33 + sc2]     = acc[mi][ni][2];
                    stage[(r0 + 8) * 33 + sc2 + 1] = acc[mi][ni][3];
                }
            }
        __syncthreads();

        if (transT) {
            __half* Vp = (EPI == EPI_QKV) ? (__half*)C : Ch;
            #pragma unroll 1
            for (int j = 0; j < 16; j++) {
                int e = j * 256 + tid;
                int row = e & 127, c = e >> 7;
                int m = m0 + row, n = n0c + c;
                float val = stage[row * 33 + c] + bias[boff + n];
                int b = m >> 10, sq = m & 1023;
                int zz = b * NH + (n >> 6), dd = n & 63;
                Vp[((size_t)zz * DH + dd) * SEQ + sq] = __float2half(val);
            }
        } else {
            #pragma unroll 1
            for (int j = 0; j < 16; j++) {
                int e = j * 256 + tid;
                int row = e >> 5, c = e & 31;
                int m = m0 + row, n = n0c + c;
                float val = stage[row * 33 + c];
                if (EPI == EPI_HEADS || EPI == EPI_QKV) {
                    val += bias[boff + n];
                    int b = m >> 10, sq = m & 1023, h = n >> 6, dd = n & 63;
                    size_t idx = (((size_t)(b * NH + h)) * SEQ + sq) * DH + dd;
                    Ch[(EPI == EPI_QKV ? (size_t)z * QKOFF : 0) + idx] = __float2half(val);
                } else if (EPI == EPI_POS) {
                    val += bias[n];
                    int h = n >> 6, dd = n & 63;
                    Ch[((size_t)h * TWOSPAN + m) * DH + dd] = __float2half(val);
                } else if (EPI == EPI_SCALE) {
                    Ch[(size_t)z * sC + (size_t)m * ldC + n] = __float2half(val * alpha);
                } else { // EPI_OUT
                    val += bias[n] + ex1[(size_t)m * DMODEL + n];
                    C[(size_t)m * DMODEL + n] = val;
                }
            }
        }
        __syncthreads();
    }
}

// ================= flash attention (all-fp16 MMA, 3-stage KV, bitmask) ======
// grid (8 q-tiles, 64 z), 256 threads = 8 warps; warp w owns q rows 16w..16w+15.
// smem bytes: Q 16K | K 3x8K | V 3x8K | lut 8K => 72KB, 2 CTA/SM
__global__ void __launch_bounds__(256, 2)
flash_k(const __half* __restrict__ Qg, const __half* __restrict__ Kg,
        const __half* __restrict__ Vg, const __half* __restrict__ c2p,
        const __half* __restrict__ p2cT, const uint32_t* __restrict__ mbits,
        __half* __restrict__ ctx, float alpha)
{
    constexpr int QSB = 0, KSB = 16384, VSB = 40960, LUTB = 65536;
    extern __shared__ float fsm[];
    char* smc = (char*)fsm;
    int* lut_s = (int*)(smc + LUTB);
    const uint32_t smemU = (uint32_t)__cvta_generic_to_shared(fsm);

    const int tid = threadIdx.x, lane = tid & 31, w = tid >> 5;
    const int rq = lane >> 2, cc = lane & 3;
    const int z = blockIdx.y, m0 = blockIdx.x * 128;
    const int b = z >> 4;

    const __half* Qz = Qg + (size_t)z * SEQ * DH;
    const __half* Kz = Kg + (size_t)z * SEQ * DH;
    const __half* Vz = Vg + (size_t)z * DH * SEQ;
    const __half* c2pz = c2p + (size_t)z * SEQ * TWOSPAN;
    const __half* p2cz = p2cT + (size_t)z * TWOSPAN * SEQ;

    for (int t = tid; t < 2047; t += 256) lut_s[t] = g_lut[t];

    #pragma unroll
    for (int it = 0; it < 4; it++) {
        int idx = it * 256 + tid;
        int row = idx >> 3, g = idx & 7;
        cp16(smemU + (uint32_t)(QSB + row * 128 + ((g ^ (row & 7)) << 4)),
             Qz + (size_t)(m0 + row) * DH + g * 8);
    }
    auto issueKV = [&](int t) {
        int s = t % 3, n0 = t * 64;
        #pragma unroll
        for (int it = 0; it < 2; it++) {
            int idx = it * 256 + tid;
            int row = idx >> 3, g = idx & 7;
            cp16(smemU + (uint32_t)(KSB + s * 8192 + row * 128 + ((g ^ (row & 7)) << 4)),
                 Kz + (size_t)(n0 + row) * DH + g * 8);
        }
        #pragma unroll
        for (int it = 0; it < 2; it++) {
            int idx = it * 256 + tid;
            int row = idx >> 3, g = idx & 7;
            cp16(smemU + (uint32_t)(VSB + s * 8192 + row * 128 + ((g ^ (row & 7)) << 4)),
                 Vz + (size_t)row * SEQ + n0 + g * 8);
        }
    };
    issueKV(0);
    CP_COMMIT();
    issueKV(1);
    CP_COMMIT();

    float oacc[8][4];
    #pragma unroll
    for (int f = 0; f < 8; f++)
        #pragma unroll
        for (int e = 0; e < 4; e++) oacc[f][e] = 0.0f;
    float mrow[2] = {NEGF, NEGF};
    float lrow[2] = {0.0f, 0.0f};

    const int iA = m0 + 16 * w + rq, iB = iA + 8;
    const __half* c2pA = c2pz + (size_t)iA * TWOSPAN;
    const __half* c2pB = c2pz + (size_t)iB * TWOSPAN;
    const uint32_t* bmA = mbits + ((size_t)b * SEQ + iA) * 32;
    const uint32_t* bmB = mbits + ((size_t)b * SEQ + iB) * 32;
    const int rowA = 16 * w + rq, rowB = rowA + 8;

    #pragma unroll 1
    for (int t = 0; t < 16; t++) {
        const int s = t % 3, n0 = t * 64;
        CP_WAIT(1);
        __syncthreads();
        if (t + 2 < 16) issueKV(t + 2);
        CP_COMMIT();

        // ---- S = Q @ K^T (fp16 m16n8k16, 4 k-chunks) ----
        float sacc[8][4];
        #pragma unroll
        for (int f = 0; f < 8; f++)
            #pragma unroll
            for (int e = 0; e < 4; e++) sacc[f][e] = 0.0f;
        const char* kp = smc + KSB + s * 8192;
        #pragma unroll
        for (int kc = 0; kc < 4; kc++) {
            int g0 = 2 * kc, g1 = 2 * kc + 1;
            uint32_t a[4];
            a[0] = *(const uint32_t*)(smc + QSB + rowA * 128 + ((g0 ^ (rowA & 7)) << 4) + 4 * cc);
            a[1] = *(const uint32_t*)(smc + QSB + rowB * 128 + ((g0 ^ (rowB & 7)) << 4) + 4 * cc);
            a[2] = *(const uint32_t*)(smc + QSB + rowA * 128 + ((g1 ^ (rowA & 7)) << 4) + 4 * cc);
            a[3] = *(const uint32_t*)(smc + QSB + rowB * 128 + ((g1 ^ (rowB & 7)) << 4) + 4 * cc);
            #pragma unroll
            for (int f = 0; f < 8; f++) {
                int rk = 8 * f + rq;
                uint32_t bf[2];
                bf[0] = *(const uint32_t*)(kp + rk * 128 + ((g0 ^ (rk & 7)) << 4) + 4 * cc);
                bf[1] = *(const uint32_t*)(kp + rk * 128 + ((g1 ^ (rk & 7)) << 4) + 4 * cc);
                MMA_F16(sacc[f], a, bf);
            }
        }

        // ---- mask bits for this 64-wide tile ----
        uint2 wA2 = *(const uint2*)&bmA[n0 >> 5];
        uint2 wB2 = *(const uint2*)&bmB[n0 >> 5];
        uint64_t mwA = (uint64_t)wA2.x | ((uint64_t)wA2.y << 32);
        uint64_t mwB = (uint64_t)wB2.x | ((uint64_t)wB2.y << 32);

        // ---- scale + c2p + p2c + mask, row max ----
        float mx0 = NEGF, mx1 = NEGF;
        #pragma unroll
        for (int f = 0; f < 8; f++) {
            int jl = 8 * f + 2 * cc;
            int j0 = n0 + jl;
            bool ma0 = (mwA >> jl) & 1, ma1 = (mwA >> (jl + 1)) & 1;
            bool mb0 = (mwB >> jl) & 1, mb1 = (mwB >> (jl + 1)) & 1;
            float v0 = ma0 ? sacc[f][0] * alpha + __half2float(c2pA[lut_s[iA - j0 + 1023]])
                             + __half2float(p2cz[(size_t)lut_s[j0 - iA + 1023] * SEQ + j0]) : NEGF;
            float v1 = ma1 ? sacc[f][1] * alpha + __half2float(c2pA[lut_s[iA - j0 + 1022]])
                             + __half2float(p2cz[(size_t)lut_s[j0 + 1 - iA + 1023] * SEQ + j0 + 1]) : NEGF;
            float v2 = mb0 ? sacc[f][2] * alpha + __half2float(c2pB[lut_s[iB - j0 + 1023]])
                             + __half2float(p2cz[(size_t)lut_s[j0 - iB + 1023] * SEQ + j0]) : NEGF;
            float v3 = mb1 ? sacc[f][3] * alpha + __half2float(c2pB[lut_s[iB - j0 + 1022]])
                             + __half2float(p2cz[(size_t)lut_s[j0 + 1 - iB + 1023] * SEQ + j0 + 1]) : NEGF;
            sacc[f][0] = v0; sacc[f][1] = v1; sacc[f][2] = v2; sacc[f][3] = v3;
            mx0 = fmaxf(mx0, fmaxf(v0, v1));
            mx1 = fmaxf(mx1, fmaxf(v2, v3));
        }
        mx0 = fmaxf(mx0, __shfl_xor_sync(0xffffffffu, mx0, 1));
        mx0 = fmaxf(mx0, __shfl_xor_sync(0xffffffffu, mx0, 2));
        mx1 = fmaxf(mx1, __shfl_xor_sync(0xffffffffu, mx1, 1));
        mx1 = fmaxf(mx1, __shfl_xor_sync(0xffffffffu, mx1, 2));
        float mn0 = fmaxf(mrow[0], mx0), mn1 = fmaxf(mrow[1], mx1);
        float sc0 = __expf(mrow[0] - mn0), sc1 = __expf(mrow[1] - mn1);
        mrow[0] = mn0; mrow[1] = mn1;

        // ---- exp, pack P to fp16 A-fragments in-register ----
        float rs0 = 0.0f, rs1 = 0.0f;
        uint32_t ph[8][2];
        #pragma unroll
        for (int f = 0; f < 8; f++) {
            float e0 = __expf(sacc[f][0] - mn0);
            float e1 = __expf(sacc[f][1] - mn0);
            float e2 = __expf(sacc[f][2] - mn1);
            float e3 = __expf(sacc[f][3] - mn1);
            rs0 += e0 + e1; rs1 += e2 + e3;
            float p0 = (sacc[f][0] == NEGF) ? 0.0f : e0;
            float p1 = (sacc[f][1] == NEGF) ? 0.0f : e1;
            float p2 = (sacc[f][2] == NEGF) ? 0.0f : e2;
            float p3 = (sacc[f][3] == NEGF) ? 0.0f : e3;
            ph[f][0] = pack_h2(p0, p1);
            ph[f][1] = pack_h2(p2, p3);
        }
        rs0 += __shfl_xor_sync(0xffffffffu, rs0, 1);
        rs0 += __shfl_xor_sync(0xffffffffu, rs0, 2);
        rs1 += __shfl_xor_sync(0xffffffffu, rs1, 1);
        rs1 += __shfl_xor_sync(0xffffffffu, rs1, 2);
        lrow[0] = lrow[0] * sc0 + rs0;
        lrow[1] = lrow[1] * sc1 + rs1;
        #pragma unroll
        for (int f = 0; f < 8; f++) {
            oacc[f][0] *= sc0; oacc[f][1] *= sc0;
            oacc[f][2] *= sc1; oacc[f][3] *= sc1;
        }

        // ---- O += P @ V (fp16, P in registers, V fp16 smem) ----
        const char* vp = smc + VSB + s * 8192;
        #pragma unroll
        for (int ks2 = 0; ks2 < 4; ks2++) {
            uint32_t a[4] = { ph[2*ks2][0], ph[2*ks2][1], ph[2*ks2+1][0], ph[2*ks2+1][1] };
            int g0 = (2 * ks2) ^ rq, g1 = (2 * ks2 + 1) ^ rq;
            #pragma unroll
            for (int n = 0; n < 8; n++) {
                int d = 8 * n + rq;
                uint32_t bf[2];
                bf[0] = *(const uint32_t*)(vp + d * 128 + (g0 << 4) + 4 * cc);
                bf[1] = *(const uint32_t*)(vp + d * 128 + (g1 << 4) + 4 * cc);
                MMA_F16(oacc[n], a, bf);
            }
        }
    }

    // ---- write ctx (fp16): [b][s][h*64+d] ----
    float inv0 = 1.0f / lrow[0], inv1 = 1.0f / lrow[1];
    int h = z & 15;
    __half* crow0 = ctx + ((size_t)b * SEQ + (size_t)(m0 + 16 * w + rq)) * DMODEL + h * DH;
    __half* crow1 = crow0 + (size_t)8 * DMODEL;
    #pragma unroll
    for (int f = 0; f < 8; f++) {
        int d0 = 8 * f + 2 * cc;
        *(uint32_t*)&crow0[d0] = pack_h2(oacc[f][0] * inv0, oacc[f][1] * inv0);
        *(uint32_t*)&crow1[d0] = pack_h2(oacc[f][2] * inv1, oacc[f][3] * inv1);
    }
}

// ================= layernorm ================================================
__device__ __forceinline__ float block_sum(float v, float* sh) {
    #pragma unroll
    for (int o = 16; o; o >>= 1) v += __shfl_xor_sync(0xffffffffu, v, o);
    int lane = threadIdx.x & 31, w = threadIdx.x >> 5;
    __syncthreads();
    if (lane == 0) sh[w] = v;
    __syncthreads();
    if (w == 0) {
        float x = (lane < (blockDim.x >> 5)) ? sh[lane] : 0.0f;
        #pragma unroll
        for (int o = 16; o; o >>= 1) x += __shfl_xor_sync(0xffffffffu, x, o);
        if (lane == 0) sh[0] = x;
    }
    __syncthreads();
    return sh[0];
}
__global__ void ln_k(float* __restrict__ out, const float* __restrict__ gamma,
                     const float* __restrict__ beta) {
    __shared__ float sh[32];
    int row = blockIdx.x, t = threadIdx.x;
    float* p = out + (size_t)row * DMODEL;
    float4 v = *(const float4*)(p + t * 4);
    float mean = block_sum(v.x + v.y + v.z + v.w, sh) * (1.0f / DMODEL);
    float dx = v.x - mean, dy = v.y - mean, dz = v.z - mean, dw = v.w - mean;
    float var = block_sum(dx*dx + dy*dy + dz*dz + dw*dw, sh) * (1.0f / DMODEL);
    float inv = rsqrtf(var + 1e-7f);
    float4 g = *(const float4*)(gamma + t * 4);
    float4 bb = *(const float4*)(beta + t * 4);
    float4 o;
    o.x = dx*inv*g.x + bb.x; o.y = dy*inv*g.y + bb.y;
    o.z = dz*inv*g.z + bb.z; o.w = dw*inv*g.w + bb.w;
    *(float4*)(p + t * 4) = o;
}

// ================= launch ====================================================
extern "C" void kernel_launch(void* const* d_in, const int* in_sizes, int n_in,
                              void* d_out, int out_size) {
    const float* hidden = (const float*)d_in[0];
    const int*   mask   = (const int*)  d_in[1];
    const float* rel    = (const float*)d_in[2];
    const float* Wq     = (const float*)d_in[3];
    const float* bq     = (const float*)d_in[4];
    const float* Wk     = (const float*)d_in[5];
    const float* bk     = (const float*)d_in[6];
    const float* Wv     = (const float*)d_in[7];
    const float* bv     = (const float*)d_in[8];
    const float* Wo     = (const float*)d_in[9];
    const float* bo     = (const float*)d_in[10];
    const float* gamma  = (const float*)d_in[11];
    const float* beta   = (const float*)d_in[12];
    float* out = (float*)d_out;

    __half *hh, *wqkv, *wo, *relh, *qkh, *vt, *pk, *pq, *c2p, *p2cT, *ctx;
    float* bqkv;
    uint32_t* mbits;
    cudaGetSymbolAddress((void**)&hh,    g_hh);
    cudaGetSymbolAddress((void**)&wqkv,  g_wqkv);
    cudaGetSymbolAddress((void**)&bqkv,  g_bqkv);
    cudaGetSymbolAddress((void**)&wo,    g_wo);
    cudaGetSymbolAddress((void**)&relh,  g_relh);
    cudaGetSymbolAddress((void**)&qkh,   g_qkh);
    cudaGetSymbolAddress((void**)&vt,    g_vt);
    cudaGetSymbolAddress((void**)&pk,    g_pk);
    cudaGetSymbolAddress((void**)&pq,    g_pq);
    cudaGetSymbolAddress((void**)&c2p,   g_c2p);
    cudaGetSymbolAddress((void**)&p2cT,  g_p2cT);
    cudaGetSymbolAddress((void**)&ctx,   g_ctx);
    cudaGetSymbolAddress((void**)&mbits, g_mbits);
    __half* qh = qkh;
    __half* kh = qkh + QKOFF;

    const float alpha = 1.0f / sqrtf((float)(DH * 3));
    const size_t SMG = 98304;     // 6 x 16KB stages
    const size_t SMF = 73728;     // Q16K + K24K + V24K + lut8K

    cudaFuncSetAttribute((const void*)tc_gemm_h<EPI_QKV,  16>, cudaFuncAttributeMaxDynamicSharedMemorySize, (int)SMG);
    cudaFuncSetAttribute((const void*)tc_gemm_h<EPI_POS,  16>, cudaFuncAttributeMaxDynamicSharedMemorySize, (int)SMG);
    cudaFuncSetAttribute((const void*)tc_gemm_h<EPI_SCALE, 1>, cudaFuncAttributeMaxDynamicSharedMemorySize, (int)SMG);
    cudaFuncSetAttribute((const void*)tc_gemm_h<EPI_OUT,  16>, cudaFuncAttributeMaxDynamicSharedMemorySize, (int)SMG);
    cudaFuncSetAttribute((const void*)flash_k, cudaFuncAttributeMaxDynamicSharedMemorySize, (int)SMF);

    lut_k<<<2, 1024>>>();
    maskpack_k<<<512, 256>>>(mask, mbits);
    bias3_k<<<4, 256>>>(bq, bk, bv, bqkv);
    cvt_k<<<4096, 256>>>(hidden, hh, BDIM * SEQ * DMODEL);
    cvt_k<<<1024, 256>>>(Wq, wqkv,                    DMODEL * DMODEL);
    cvt_k<<<1024, 256>>>(Wk, wqkv + DMODEL * DMODEL,  DMODEL * DMODEL);
    cvt_k<<<1024, 256>>>(Wv, wqkv + 2 * DMODEL * DMODEL, DMODEL * DMODEL);
    cvt_k<<<1024, 256>>>(Wo, wo, DMODEL * DMODEL);
    cvt_k<<<512,  256>>>(rel, relh, TWOSPAN * DMODEL);

    // fused Q/K/V projections: z in {0,1,2} selects weight/bias/output
    tc_gemm_h<EPI_QKV, 16><<<dim3(8, 32, 3), 256, SMG>>>(
        hh, wqkv, bqkv, 0, (float*)vt, qkh, 1024,
        0 /*sA*/, (size_t)DMODEL * DMODEL /*sB*/, 1 /*nbModA->0*/, 0 /*nbModB: z*sB*/,
        0, 0, 1.f);
    // position projections (M=512)
    tc_gemm_h<EPI_POS, 16><<<dim3(8, 4, 1), 256, SMG>>>(relh, wqkv + DMODEL * DMODEL, bk, 0, 0, pk, 1024, 0, 0, 0, 0, 0, 0, 1.f);
    tc_gemm_h<EPI_POS, 16><<<dim3(8, 4, 1), 256, SMG>>>(relh, wqkv,                   bq, 0, 0, pq, 1024, 0, 0, 0, 0, 0, 0, 1.f);
    // c2p: [z][q][p] = alpha * qh[z] @ pk[h]^T
    tc_gemm_h<EPI_SCALE, 1><<<dim3(4, 8, NBATCH), 256, SMG>>>(
        qh, pk, 0, 0, 0, c2p, 64, (size_t)SEQ*DH, (size_t)TWOSPAN*DH, 0, NH,
        (size_t)SEQ*TWOSPAN, TWOSPAN, alpha);
    // p2cT: [z][p][k] = alpha * pq[h] @ kh[z]^T
    tc_gemm_h<EPI_SCALE, 1><<<dim3(8, 4, NBATCH), 256, SMG>>>(
        pq, kh, 0, 0, 0, p2cT, 64, (size_t)TWOSPAN*DH, (size_t)SEQ*DH, NH, 0,
        (size_t)TWOSPAN*SEQ, SEQ, alpha);

    // fused attention: scores + masked softmax + P@V
    flash_k<<<dim3(8, NBATCH), 256, SMF>>>(qh, kh, vt, c2p, p2cT, mbits, ctx, alpha);

    // output projection + residual
    tc_gemm_h<EPI_OUT, 16><<<dim3(8, 32, 1), 256, SMG>>>(ctx, wo, bo, hidden, out, 0, 1024, 0, 0, 0, 0, 0, 0, 1.f);

    ln_k<<<BDIM * SEQ, 256>>>(out, gamma, beta);
}